// round 1
// baseline (speedup 1.0000x reference)
#include <cuda_runtime.h>
#include <cuda_bf16.h>
#include <math.h>

// Problem constants
#define BB 2
#define NN 4096
#define CC 512
#define HH 8
#define DD 64
#define MM (BB*NN)      // 8192
#define ADA6 (6*CC)     // 3072

// ---------------- scratch (__device__ globals; no allocs allowed) -------------
__device__ float g_ada[BB*ADA6];
__device__ float g_h [MM*CC];
__device__ float g_qkv[MM*3*CC];
__device__ float g_o [MM*CC];
__device__ float g_x1[MM*CC];
__device__ float g_h3[MM*CC];
__device__ int   g_kvidx[BB*NN];
__device__ int   g_kvcnt[BB];

// ---------------- ada = silu(cond) @ ada_w + ada_b ---------------------------
__global__ void ada_kernel(const float* __restrict__ cond,
                           const float* __restrict__ ada_w,
                           const float* __restrict__ ada_b) {
    int b = blockIdx.x / 12;
    int j = (blockIdx.x % 12) * 256 + threadIdx.x;   // 0..3071
    __shared__ float sc[CC];
    for (int t = threadIdx.x; t < CC; t += 256) {
        float x = cond[b*CC + t];
        sc[t] = x / (1.0f + expf(-x));
    }
    __syncthreads();
    float acc = ada_b[j];
    #pragma unroll 8
    for (int c = 0; c < CC; c++) acc += sc[c] * ada_w[c*ADA6 + j];
    g_ada[b*ADA6 + j] = acc;
}

// ---------------- deterministic mask compaction (block scan) ------------------
__global__ void compact_kernel(const int* __restrict__ mask) {
    int b = blockIdx.x;
    int tid = threadIdx.x;          // 1024 threads
    int base = b*NN;
    int loc[4]; int cnt = 0;
    #pragma unroll
    for (int q = 0; q < 4; q++) {
        int n = tid*4 + q;
        if (mask[base + n] == 1) loc[cnt++] = n;
    }
    __shared__ int ssum[1024];
    ssum[tid] = cnt;
    __syncthreads();
    for (int off = 1; off < 1024; off <<= 1) {
        int v = (tid >= off) ? ssum[tid - off] : 0;
        __syncthreads();
        ssum[tid] += v;
        __syncthreads();
    }
    int start = ssum[tid] - cnt;
    for (int i = 0; i < cnt; i++) g_kvidx[base + start + i] = loc[i];
    if (tid == 1023) g_kvcnt[b] = ssum[1023];
}

// ---------------- fused LayerNorm + adaLN modulate ----------------------------
__global__ void ln_mod_kernel(const float* __restrict__ X,
                              int shOff, int scOff,
                              float* __restrict__ Hout) {
    int row = blockIdx.x;           // 8192 rows
    int b = row >> 12;
    int tid = threadIdx.x;          // 128 threads, 4 floats each
    const float* xr = X + (size_t)row * CC;
    float4 v = *(const float4*)(xr + tid*4);
    float s  = v.x + v.y + v.z + v.w;
    float sq = v.x*v.x + v.y*v.y + v.z*v.z + v.w*v.w;
    #pragma unroll
    for (int off = 16; off > 0; off >>= 1) {
        s  += __shfl_down_sync(0xffffffffu, s,  off);
        sq += __shfl_down_sync(0xffffffffu, sq, off);
    }
    __shared__ float ws[4], wq[4];
    if ((tid & 31) == 0) { ws[tid>>5] = s; wq[tid>>5] = sq; }
    __syncthreads();
    s  = ws[0] + ws[1] + ws[2] + ws[3];
    sq = wq[0] + wq[1] + wq[2] + wq[3];
    float mean = s * (1.0f/CC);
    float var  = sq * (1.0f/CC) - mean*mean;
    float rstd = rsqrtf(var + 1e-6f);
    int c = tid*4;
    const float* adab = g_ada + b*ADA6;
    float4 sc = *(const float4*)(adab + scOff + c);
    float4 sh = *(const float4*)(adab + shOff + c);
    float4 o;
    o.x = (v.x - mean)*rstd*(1.0f + sc.x) + sh.x;
    o.y = (v.y - mean)*rstd*(1.0f + sc.y) + sh.y;
    o.z = (v.z - mean)*rstd*(1.0f + sc.z) + sh.z;
    o.w = (v.w - mean)*rstd*(1.0f + sc.w) + sh.w;
    *(float4*)(Hout + (size_t)row*CC + c) = o;
}

// ---------------- tiled SGEMM: C = A[M,512] @ W[512,N] (+epilogue) ------------
// EPI 0: +bias       EPI 1: gelu(+bias)      EPI 2: resid + gate*( +bias )
template<int EPI>
__global__ void gemm_kernel(const float* __restrict__ A,
                            const float* __restrict__ W,
                            const float* __restrict__ bias,
                            const float* __restrict__ resid,   // [M,512] for EPI2
                            const float* __restrict__ gate,    // g_ada+off, stride ADA6
                            float* __restrict__ Cout, int N) {
    __shared__ float As[16][132];
    __shared__ float Bs[16][128];
    int tid = threadIdx.x;                 // 256
    int tx = tid & 15, ty = tid >> 4;
    int m0 = blockIdx.y * 128;
    int n0 = blockIdx.x * 128;

    int arow = tid >> 1;                   // 0..127
    int acol = (tid & 1) * 8;              // 0 or 8
    int brow = tid >> 4;                   // 0..15
    int bcol = (tid & 15) * 8;

    const float* Aptr = A + (size_t)(m0 + arow)*CC + acol;
    const float* Wptr = W + (size_t)brow*N + n0 + bcol;

    float acc[8][8];
    #pragma unroll
    for (int i = 0; i < 8; i++)
        #pragma unroll
        for (int j = 0; j < 8; j++) acc[i][j] = 0.0f;

    for (int k0 = 0; k0 < CC; k0 += 16) {
        float4 a0 = *(const float4*)(Aptr + k0);
        float4 a1 = *(const float4*)(Aptr + k0 + 4);
        float4 b0 = *(const float4*)(Wptr + (size_t)k0*N);
        float4 b1 = *(const float4*)(Wptr + (size_t)k0*N + 4);
        As[acol+0][arow] = a0.x; As[acol+1][arow] = a0.y;
        As[acol+2][arow] = a0.z; As[acol+3][arow] = a0.w;
        As[acol+4][arow] = a1.x; As[acol+5][arow] = a1.y;
        As[acol+6][arow] = a1.z; As[acol+7][arow] = a1.w;
        *(float4*)&Bs[brow][bcol]   = b0;
        *(float4*)&Bs[brow][bcol+4] = b1;
        __syncthreads();
        #pragma unroll
        for (int k = 0; k < 16; k++) {
            float4 ar0 = *(const float4*)&As[k][ty*4];
            float4 ar1 = *(const float4*)&As[k][64 + ty*4];
            float4 br0 = *(const float4*)&Bs[k][tx*4];
            float4 br1 = *(const float4*)&Bs[k][64 + tx*4];
            float av[8] = {ar0.x,ar0.y,ar0.z,ar0.w, ar1.x,ar1.y,ar1.z,ar1.w};
            float bv[8] = {br0.x,br0.y,br0.z,br0.w, br1.x,br1.y,br1.z,br1.w};
            #pragma unroll
            for (int i = 0; i < 8; i++)
                #pragma unroll
                for (int j = 0; j < 8; j++)
                    acc[i][j] += av[i]*bv[j];
        }
        __syncthreads();
    }

    #pragma unroll
    for (int i = 0; i < 8; i++) {
        int r = m0 + ((i < 4) ? (ty*4 + i) : (64 + ty*4 + i - 4));
        int bb = r >> 12;
        #pragma unroll
        for (int j = 0; j < 8; j++) {
            int c = n0 + ((j < 4) ? (tx*4 + j) : (64 + tx*4 + j - 4));
            float v = acc[i][j] + bias[c];
            if (EPI == 1) {
                v = 0.5f * v * (1.0f + erff(v * 0.70710678118654752f));
            } else if (EPI == 2) {
                v = resid[(size_t)r*CC + c] + gate[(size_t)bb*ADA6 + c] * v;
            }
            Cout[(size_t)r*N + c] = v;
        }
    }
}

// ---------------- flash attention on compacted keys ---------------------------
// grid (64, H, B), 256 threads. BQ = BK = 64, per-thread 4x4 frags.
#define SPAD 68
__global__ void attn_kernel() {
    extern __shared__ float sm[];
    float* Qs = sm;                  // 64*68
    float* Ks = Qs + 64*SPAD;
    float* Vs = Ks + 64*SPAD;
    float* Ss = Vs + 64*SPAD;
    __shared__ float sm_m[64], sm_l[64], sm_corr[64];

    int qb = blockIdx.x, h = blockIdx.y, b = blockIdx.z;
    int tid = threadIdx.x;
    int tx = tid & 15, ty = tid >> 4;
    int r  = tid >> 2, f = tid & 3;  // loader mapping: row r, quarter f

    // load Q tile (pre-scaled by D^-0.5 = 0.125)
    {
        const float* qrow = g_qkv + ((size_t)(b*NN + qb*64 + r))*(3*CC) + h*DD;
        #pragma unroll
        for (int s4 = 0; s4 < 4; s4++) {
            int d = f*16 + s4*4;
            float4 v = *(const float4*)(qrow + d);
            v.x *= 0.125f; v.y *= 0.125f; v.z *= 0.125f; v.w *= 0.125f;
            *(float4*)&Qs[r*SPAD + d] = v;
        }
    }
    if (tid < 64) { sm_m[tid] = -INFINITY; sm_l[tid] = 0.0f; }

    float o[4][4];
    #pragma unroll
    for (int i = 0; i < 4; i++)
        #pragma unroll
        for (int j = 0; j < 4; j++) o[i][j] = 0.0f;

    int nk = g_kvcnt[b];
    int ntiles = (nk + 63) >> 6;

    for (int t = 0; t < ntiles; t++) {
        // load K,V tiles (gathered through compacted index list)
        int slot = t*64 + r;
        if (slot < nk) {
            int n = g_kvidx[b*NN + slot];
            const float* base = g_qkv + ((size_t)(b*NN + n))*(3*CC) + h*DD;
            #pragma unroll
            for (int s4 = 0; s4 < 4; s4++) {
                int d = f*16 + s4*4;
                *(float4*)&Ks[r*SPAD + d] = *(const float4*)(base + CC   + d);
                *(float4*)&Vs[r*SPAD + d] = *(const float4*)(base + 2*CC + d);
            }
        } else {
            float4 z = make_float4(0.f,0.f,0.f,0.f);
            #pragma unroll
            for (int s4 = 0; s4 < 4; s4++) {
                int d = f*16 + s4*4;
                *(float4*)&Ks[r*SPAD + d] = z;
                *(float4*)&Vs[r*SPAD + d] = z;
            }
        }
        __syncthreads();

        // S = Q K^T  (4x4 frag per thread)
        float s[4][4];
        #pragma unroll
        for (int i = 0; i < 4; i++)
            #pragma unroll
            for (int j = 0; j < 4; j++) s[i][j] = 0.0f;
        #pragma unroll
        for (int d4 = 0; d4 < 16; d4++) {
            float4 qf[4], kf[4];
            #pragma unroll
            for (int i = 0; i < 4; i++) qf[i] = *(const float4*)&Qs[(ty*4+i)*SPAD + d4*4];
            #pragma unroll
            for (int j = 0; j < 4; j++) kf[j] = *(const float4*)&Ks[(tx*4+j)*SPAD + d4*4];
            #pragma unroll
            for (int i = 0; i < 4; i++)
                #pragma unroll
                for (int j = 0; j < 4; j++)
                    s[i][j] += qf[i].x*kf[j].x + qf[i].y*kf[j].y
                             + qf[i].z*kf[j].z + qf[i].w*kf[j].w;
        }
        int valid = nk - t*64; if (valid > 64) valid = 64;
        #pragma unroll
        for (int i = 0; i < 4; i++)
            #pragma unroll
            for (int j = 0; j < 4; j++) {
                int c = tx*4 + j;
                Ss[(ty*4+i)*SPAD + c] = (c < valid) ? s[i][j] : -1e30f;
            }
        __syncthreads();

        // online softmax: 64 rows x 4 threads, 16 cols each
        {
            int rr = tid >> 2, sub = tid & 3;
            int base = rr*SPAD + sub*16;
            float mx = -1e30f;
            #pragma unroll
            for (int k = 0; k < 16; k++) mx = fmaxf(mx, Ss[base + k]);
            mx = fmaxf(mx, __shfl_xor_sync(0xffffffffu, mx, 1));
            mx = fmaxf(mx, __shfl_xor_sync(0xffffffffu, mx, 2));
            float mold = sm_m[rr];
            float mnew = fmaxf(mold, mx);
            float sum = 0.0f;
            #pragma unroll
            for (int k = 0; k < 16; k++) {
                float p = __expf(Ss[base + k] - mnew);
                Ss[base + k] = p;
                sum += p;
            }
            sum += __shfl_xor_sync(0xffffffffu, sum, 1);
            sum += __shfl_xor_sync(0xffffffffu, sum, 2);
            if (sub == 0) {
                float corr = __expf(mold - mnew);
                sm_corr[rr] = corr;
                sm_m[rr] = mnew;
                sm_l[rr] = sm_l[rr]*corr + sum;
            }
        }
        __syncthreads();

        // O = O*corr + P @ V
        #pragma unroll
        for (int i = 0; i < 4; i++) {
            float ci = sm_corr[ty*4 + i];
            #pragma unroll
            for (int j = 0; j < 4; j++) o[i][j] *= ci;
        }
        #pragma unroll
        for (int j4 = 0; j4 < 16; j4++) {
            float4 pf[4], vf[4];
            #pragma unroll
            for (int i = 0; i < 4; i++)  pf[i]  = *(const float4*)&Ss[(ty*4+i)*SPAD + j4*4];
            #pragma unroll
            for (int jj = 0; jj < 4; jj++) vf[jj] = *(const float4*)&Vs[(j4*4+jj)*SPAD + tx*4];
            #pragma unroll
            for (int i = 0; i < 4; i++) {
                o[i][0] += pf[i].x*vf[0].x + pf[i].y*vf[1].x + pf[i].z*vf[2].x + pf[i].w*vf[3].x;
                o[i][1] += pf[i].x*vf[0].y + pf[i].y*vf[1].y + pf[i].z*vf[2].y + pf[i].w*vf[3].y;
                o[i][2] += pf[i].x*vf[0].z + pf[i].y*vf[1].z + pf[i].z*vf[2].z + pf[i].w*vf[3].z;
                o[i][3] += pf[i].x*vf[0].w + pf[i].y*vf[1].w + pf[i].z*vf[2].w + pf[i].w*vf[3].w;
            }
        }
        __syncthreads();
    }

    // epilogue: O /= l, write [B,N,H*D]
    #pragma unroll
    for (int i = 0; i < 4; i++) {
        float invl = 1.0f / sm_l[ty*4 + i];
        int grow = b*NN + qb*64 + ty*4 + i;
        float4 v = make_float4(o[i][0]*invl, o[i][1]*invl, o[i][2]*invl, o[i][3]*invl);
        *(float4*)(g_o + (size_t)grow*CC + h*DD + tx*4) = v;
    }
}

// ---------------------------------------------------------------------------
extern "C" void kernel_launch(void* const* d_in, const int* in_sizes, int n_in,
                              void* d_out, int out_size) {
    const float* x      = (const float*)d_in[0];
    const float* cond   = (const float*)d_in[1];
    const int*   mask   = (const int*)  d_in[2];
    const float* qkv_w  = (const float*)d_in[3];
    const float* qkv_b  = (const float*)d_in[4];
    const float* proj_w = (const float*)d_in[5];
    const float* proj_b = (const float*)d_in[6];
    const float* ada_w  = (const float*)d_in[7];
    const float* ada_b  = (const float*)d_in[8];
    const float* mlp_w1 = (const float*)d_in[9];
    const float* mlp_b1 = (const float*)d_in[10];
    const float* mlp_w2 = (const float*)d_in[11];
    const float* mlp_b2 = (const float*)d_in[12];
    float* out = (float*)d_out;

    float *p_ada, *p_h, *p_qkv, *p_o, *p_x1, *p_h3;
    cudaGetSymbolAddress((void**)&p_ada, g_ada);
    cudaGetSymbolAddress((void**)&p_h,   g_h);
    cudaGetSymbolAddress((void**)&p_qkv, g_qkv);
    cudaGetSymbolAddress((void**)&p_o,   g_o);
    cudaGetSymbolAddress((void**)&p_x1,  g_x1);
    cudaGetSymbolAddress((void**)&p_h3,  g_h3);

    cudaFuncSetAttribute(attn_kernel, cudaFuncAttributeMaxDynamicSharedMemorySize,
                         4*64*SPAD*(int)sizeof(float));

    // 1. adaLN vector
    ada_kernel<<<BB*12, 256>>>(cond, ada_w, ada_b);
    // 2. compact unmasked keys (exact: -10000 bias underflows to 0 in softmax)
    compact_kernel<<<BB, 1024>>>(mask);
    // 3. LN + modulate (MSA branch): sh_msa @0, sc_msa @512
    ln_mod_kernel<<<MM, 128>>>(x, 0, CC, p_h);
    // 4. qkv GEMM [8192,1536]
    gemm_kernel<0><<<dim3(12, 64), 256>>>(p_h, qkv_w, qkv_b, nullptr, nullptr, p_qkv, 3*CC);
    // 5. attention
    attn_kernel<<<dim3(NN/64, HH, BB), 256, 4*64*SPAD*sizeof(float)>>>();
    // 6. proj GEMM + gated residual (g_msa @1024)
    gemm_kernel<2><<<dim3(4, 64), 256>>>(p_o, proj_w, proj_b, x, p_ada + 2*CC*1, p_x1, CC);
    // 7. LN + modulate (MLP branch): sh_mlp @1536, sc_mlp @2048
    ln_mod_kernel<<<MM, 128>>>(p_x1, 3*CC, 4*CC, p_h);
    // 8. mlp1 + exact GELU
    gemm_kernel<1><<<dim3(4, 64), 256>>>(p_h, mlp_w1, mlp_b1, nullptr, nullptr, p_h3, CC);
    // 9. mlp2 + gated residual (g_mlp @2560) -> d_out
    gemm_kernel<2><<<dim3(4, 64), 256>>>(p_h3, mlp_w2, mlp_b2, p_x1, p_ada + 5*CC, out, CC);
}

// round 3
// speedup vs baseline: 2.5824x; 2.5824x over previous
#include <cuda_runtime.h>
#include <cuda_bf16.h>
#include <math.h>
#include <stdint.h>

// Problem constants
#define BB 2
#define NN 4096
#define CC 512
#define HH 8
#define DD 64
#define MM (BB*NN)      // 8192
#define ADA6 (6*CC)     // 3072

// ---------------- scratch ----------------------------------------------------
__device__ float g_ada[BB*ADA6];
__device__ float g_h [MM*CC];
__device__ float g_qkv[MM*3*CC];
__device__ float g_o [MM*CC];
__device__ float g_x1[MM*CC];
__device__ float g_h3[MM*CC];
__device__ int   g_kvidx[BB*NN];
__device__ int   g_kvcnt[BB];

// ---------------- tf32 helpers ----------------------------------------------
__device__ __forceinline__ uint32_t f2tf(float f) {
    uint32_t u;
    asm("cvt.rna.tf32.f32 %0, %1;" : "=r"(u) : "f"(f));
    return u;
}
__device__ __forceinline__ float cvt1(float f) { return __uint_as_float(f2tf(f)); }
__device__ __forceinline__ float4 cvt4(float4 v) {
    v.x = cvt1(v.x); v.y = cvt1(v.y); v.z = cvt1(v.z); v.w = cvt1(v.w);
    return v;
}
__device__ __forceinline__ uint32_t fu(float f) { return __float_as_uint(f); }

__device__ __forceinline__ void mma_tf32(float4& d, const uint32_t a[4], const uint32_t b[2]) {
    asm volatile(
        "mma.sync.aligned.m16n8k8.row.col.f32.tf32.tf32.f32 "
        "{%0,%1,%2,%3}, {%4,%5,%6,%7}, {%8,%9}, {%0,%1,%2,%3};\n"
        : "+f"(d.x), "+f"(d.y), "+f"(d.z), "+f"(d.w)
        : "r"(a[0]), "r"(a[1]), "r"(a[2]), "r"(a[3]), "r"(b[0]), "r"(b[1]));
}

// ---------------- ada = silu(cond) @ ada_w + ada_b ---------------------------
__global__ void ada_kernel(const float* __restrict__ cond,
                           const float* __restrict__ ada_w,
                           const float* __restrict__ ada_b) {
    int b = blockIdx.x / 12;
    int j = (blockIdx.x % 12) * 256 + threadIdx.x;
    __shared__ float sc[CC];
    for (int t = threadIdx.x; t < CC; t += 256) {
        float x = cond[b*CC + t];
        sc[t] = x / (1.0f + expf(-x));
    }
    __syncthreads();
    float acc = ada_b[j];
    #pragma unroll 8
    for (int c = 0; c < CC; c++) acc += sc[c] * ada_w[c*ADA6 + j];
    g_ada[b*ADA6 + j] = acc;
}

// ---------------- deterministic mask compaction ------------------------------
__global__ void compact_kernel(const int* __restrict__ mask) {
    int b = blockIdx.x;
    int tid = threadIdx.x;
    int base = b*NN;
    int loc[4]; int cnt = 0;
    #pragma unroll
    for (int q = 0; q < 4; q++) {
        int n = tid*4 + q;
        if (mask[base + n] == 1) loc[cnt++] = n;
    }
    __shared__ int ssum[1024];
    ssum[tid] = cnt;
    __syncthreads();
    for (int off = 1; off < 1024; off <<= 1) {
        int v = (tid >= off) ? ssum[tid - off] : 0;
        __syncthreads();
        ssum[tid] += v;
        __syncthreads();
    }
    int start = ssum[tid] - cnt;
    for (int i = 0; i < cnt; i++) g_kvidx[base + start + i] = loc[i];
    if (tid == 1023) g_kvcnt[b] = ssum[1023];
}

// ---------------- fused LayerNorm + adaLN modulate ----------------------------
__global__ void ln_mod_kernel(const float* __restrict__ X,
                              int shOff, int scOff,
                              float* __restrict__ Hout) {
    int row = blockIdx.x;
    int b = row >> 12;
    int tid = threadIdx.x;
    const float* xr = X + (size_t)row * CC;
    float4 v = *(const float4*)(xr + tid*4);
    float s  = v.x + v.y + v.z + v.w;
    float sq = v.x*v.x + v.y*v.y + v.z*v.z + v.w*v.w;
    #pragma unroll
    for (int off = 16; off > 0; off >>= 1) {
        s  += __shfl_down_sync(0xffffffffu, s,  off);
        sq += __shfl_down_sync(0xffffffffu, sq, off);
    }
    __shared__ float ws[4], wq[4];
    if ((tid & 31) == 0) { ws[tid>>5] = s; wq[tid>>5] = sq; }
    __syncthreads();
    s  = ws[0] + ws[1] + ws[2] + ws[3];
    sq = wq[0] + wq[1] + wq[2] + wq[3];
    float mean = s * (1.0f/CC);
    float var  = sq * (1.0f/CC) - mean*mean;
    float rstd = rsqrtf(var + 1e-6f);
    int c = tid*4;
    const float* adab = g_ada + b*ADA6;
    float4 sc = *(const float4*)(adab + scOff + c);
    float4 sh = *(const float4*)(adab + shOff + c);
    float4 o;
    o.x = (v.x - mean)*rstd*(1.0f + sc.x) + sh.x;
    o.y = (v.y - mean)*rstd*(1.0f + sc.y) + sh.y;
    o.z = (v.z - mean)*rstd*(1.0f + sc.z) + sh.z;
    o.w = (v.w - mean)*rstd*(1.0f + sc.w) + sh.w;
    *(float4*)(Hout + (size_t)row*CC + c) = o;
}

// ---------------- TF32 tensor-core GEMM --------------------------------------
// C[M,N] = A[M,512] @ W[512,N] + epilogue.
// Block 128x128, 8 warps (2x4), warp tile 64x32, Kt=16 double-buffered.
// EPI 0: +bias    EPI 1: gelu(+bias)    EPI 2: resid + gate*(+bias)
template<int EPI>
__global__ __launch_bounds__(256, 2)
void gemm_tf32(const float* __restrict__ A, const float* __restrict__ W,
               const float* __restrict__ bias,
               const float* __restrict__ resid,
               const float* __restrict__ gate,
               float* __restrict__ Cout, int N) {
    __shared__ float As[2][128][20];
    __shared__ float Ws[2][16][136];
    int tid  = threadIdx.x;
    int warp = tid >> 5, lane = tid & 31;
    int wm = (warp >> 2) * 64, wn = (warp & 3) * 32;
    int m0 = blockIdx.y * 128, n0 = blockIdx.x * 128;

    int ar = tid >> 1, ac = (tid & 1) * 8;     // A loader: row, col-group
    int wr = tid >> 4, wc = (tid & 15) * 8;    // W loader

    const float* Ap = A + (size_t)(m0 + ar) * CC + ac;
    const float* Wp = W + (size_t)wr * N + n0 + wc;

    float4 acc[4][4];
    #pragma unroll
    for (int i = 0; i < 4; i++)
        #pragma unroll
        for (int j = 0; j < 4; j++) acc[i][j] = make_float4(0.f,0.f,0.f,0.f);

    // preload tile 0
    {
        float4 a0 = *(const float4*)(Ap);
        float4 a1 = *(const float4*)(Ap + 4);
        float4 b0 = *(const float4*)(Wp);
        float4 b1 = *(const float4*)(Wp + 4);
        *(float4*)&As[0][ar][ac]     = cvt4(a0);
        *(float4*)&As[0][ar][ac + 4] = cvt4(a1);
        *(float4*)&Ws[0][wr][wc]     = cvt4(b0);
        *(float4*)&Ws[0][wr][wc + 4] = cvt4(b1);
    }
    __syncthreads();

    #pragma unroll 2
    for (int kt = 0; kt < 32; kt++) {
        int cur = kt & 1;
        float4 na0, na1, nb0, nb1;
        if (kt < 31) {
            na0 = *(const float4*)(Ap + (kt+1)*16);
            na1 = *(const float4*)(Ap + (kt+1)*16 + 4);
            nb0 = *(const float4*)(Wp + (size_t)(kt+1)*16*N);
            nb1 = *(const float4*)(Wp + (size_t)(kt+1)*16*N + 4);
        }
        #pragma unroll
        for (int ks = 0; ks < 16; ks += 8) {
            uint32_t afr[4][4];
            #pragma unroll
            for (int mi = 0; mi < 4; mi++) {
                int r = wm + mi*16 + (lane >> 2);
                int c = ks + (lane & 3);
                afr[mi][0] = fu(As[cur][r][c]);
                afr[mi][1] = fu(As[cur][r+8][c]);
                afr[mi][2] = fu(As[cur][r][c+4]);
                afr[mi][3] = fu(As[cur][r+8][c+4]);
            }
            uint32_t bfr[4][2];
            #pragma unroll
            for (int nj = 0; nj < 4; nj++) {
                int n = wn + nj*8 + (lane >> 2);
                int k = ks + (lane & 3);
                bfr[nj][0] = fu(Ws[cur][k][n]);
                bfr[nj][1] = fu(Ws[cur][k+4][n]);
            }
            #pragma unroll
            for (int mi = 0; mi < 4; mi++)
                #pragma unroll
                for (int nj = 0; nj < 4; nj++)
                    mma_tf32(acc[mi][nj], afr[mi], bfr[nj]);
        }
        if (kt < 31) {
            int nxt = cur ^ 1;
            *(float4*)&As[nxt][ar][ac]     = cvt4(na0);
            *(float4*)&As[nxt][ar][ac + 4] = cvt4(na1);
            *(float4*)&Ws[nxt][wr][wc]     = cvt4(nb0);
            *(float4*)&Ws[nxt][wr][wc + 4] = cvt4(nb1);
        }
        __syncthreads();
    }

    // epilogue
    #pragma unroll
    for (int mi = 0; mi < 4; mi++) {
        int r0 = m0 + wm + mi*16 + (lane >> 2);
        int r1 = r0 + 8;
        int b0i = r0 >> 12, b1i = r1 >> 12;
        #pragma unroll
        for (int nj = 0; nj < 4; nj++) {
            int c = n0 + wn + nj*8 + 2*(lane & 3);
            float4 d = acc[mi][nj];
            float bx = bias[c], by = bias[c+1];
            float vx = d.x + bx, vy = d.y + by;
            float wx = d.z + bx, wy = d.w + by;
            if (EPI == 1) {
                vx = 0.5f*vx*(1.0f + erff(vx*0.70710678118654752f));
                vy = 0.5f*vy*(1.0f + erff(vy*0.70710678118654752f));
                wx = 0.5f*wx*(1.0f + erff(wx*0.70710678118654752f));
                wy = 0.5f*wy*(1.0f + erff(wy*0.70710678118654752f));
            } else if (EPI == 2) {
                float gx0 = gate[(size_t)b0i*ADA6 + c], gy0 = gate[(size_t)b0i*ADA6 + c + 1];
                float gx1 = gate[(size_t)b1i*ADA6 + c], gy1 = gate[(size_t)b1i*ADA6 + c + 1];
                vx = resid[(size_t)r0*CC + c]     + gx0*vx;
                vy = resid[(size_t)r0*CC + c + 1] + gy0*vy;
                wx = resid[(size_t)r1*CC + c]     + gx1*wx;
                wy = resid[(size_t)r1*CC + c + 1] + gy1*wy;
            }
            *(float2*)&Cout[(size_t)r0*N + c] = make_float2(vx, vy);
            *(float2*)&Cout[(size_t)r1*N + c] = make_float2(wx, wy);
        }
    }
}

// ---------------- TF32 flash attention on compacted keys ----------------------
// Block: 64 q-rows, 4 warps (16 rows each), KV tiles of 64. Q frags in regs.
#define KP 68
#define VP 72
#define PP 68
__global__ __launch_bounds__(128)
void attn_tf32() {
    extern __shared__ float smx[];
    float* Ks = smx;                 // [64][68]
    float* Vs = Ks + 64*KP;          // [64][72]
    float* Ps = Vs + 64*VP;          // [64][68]

    int qb = blockIdx.x, h = blockIdx.y, b = blockIdx.z;
    int tid = threadIdx.x;
    int warp = tid >> 5, lane = tid & 31;
    int lr = lane >> 2, lc = lane & 3;      // fragment row/col ids

    // ---- stage Q (scaled, tf32) into Ps, then load persistent A-frags ----
    {
        int row = tid >> 1, half = tid & 1;
        const float* qrow = g_qkv + (size_t)(b*NN + qb*64 + row)*(3*CC) + h*DD + half*32;
        #pragma unroll
        for (int s4 = 0; s4 < 8; s4++) {
            float4 v = *(const float4*)(qrow + s4*4);
            v.x *= 0.125f; v.y *= 0.125f; v.z *= 0.125f; v.w *= 0.125f;
            *(float4*)&Ps[row*PP + half*32 + s4*4] = cvt4(v);
        }
    }
    __syncthreads();
    uint32_t qf[8][4];
    {
        int r = warp*16 + lr;
        #pragma unroll
        for (int ks = 0; ks < 8; ks++) {
            int c = ks*8 + lc;
            qf[ks][0] = fu(Ps[r*PP + c]);
            qf[ks][1] = fu(Ps[(r+8)*PP + c]);
            qf[ks][2] = fu(Ps[r*PP + c + 4]);
            qf[ks][3] = fu(Ps[(r+8)*PP + c + 4]);
        }
    }

    float4 o[8];
    #pragma unroll
    for (int dn = 0; dn < 8; dn++) o[dn] = make_float4(0.f,0.f,0.f,0.f);
    float m0 = -INFINITY, m1 = -INFINITY, l0 = 0.f, l1 = 0.f;

    int nk = g_kvcnt[b];
    const int* kvbase = g_kvidx + b*NN;
    int ntiles = (nk + 63) >> 6;

    for (int t = 0; t < ntiles; t++) {
        __syncthreads();   // protect Ks/Vs reuse across tiles (and Ps from Q stage)
        // ---- gather K,V tile (zero-fill invalid) ----
        {
            int row = tid >> 1, half = tid & 1;
            int slot = t*64 + row;
            if (slot < nk) {
                int n = kvbase[slot];
                const float* base = g_qkv + (size_t)(b*NN + n)*(3*CC) + h*DD + half*32;
                #pragma unroll
                for (int s4 = 0; s4 < 8; s4++) {
                    float4 kk = *(const float4*)(base + CC   + s4*4);
                    float4 vv = *(const float4*)(base + 2*CC + s4*4);
                    *(float4*)&Ks[row*KP + half*32 + s4*4] = cvt4(kk);
                    *(float4*)&Vs[row*VP + half*32 + s4*4] = cvt4(vv);
                }
            } else {
                float4 z = make_float4(0.f,0.f,0.f,0.f);
                #pragma unroll
                for (int s4 = 0; s4 < 8; s4++) {
                    *(float4*)&Ks[row*KP + half*32 + s4*4] = z;
                    *(float4*)&Vs[row*VP + half*32 + s4*4] = z;
                }
            }
        }
        __syncthreads();

        // ---- S = Q K^T ----
        float4 s[8];
        #pragma unroll
        for (int nj = 0; nj < 8; nj++) s[nj] = make_float4(0.f,0.f,0.f,0.f);
        #pragma unroll
        for (int ks = 0; ks < 8; ks++) {
            #pragma unroll
            for (int nj = 0; nj < 8; nj++) {
                uint32_t bfr[2];
                int n = nj*8 + lr;
                int k = ks*8 + lc;
                bfr[0] = fu(Ks[n*KP + k]);
                bfr[1] = fu(Ks[n*KP + k + 4]);
                mma_tf32(s[nj], qf[ks], bfr);
            }
        }
        // mask invalid columns
        int valid = nk - t*64; if (valid > 64) valid = 64;
        #pragma unroll
        for (int nj = 0; nj < 8; nj++) {
            int c0 = nj*8 + 2*lc;
            if (c0     >= valid) { s[nj].x = -1e30f; s[nj].z = -1e30f; }
            if (c0 + 1 >= valid) { s[nj].y = -1e30f; s[nj].w = -1e30f; }
        }

        // ---- online softmax (in fragments; quad reductions) ----
        float mx0 = -1e30f, mx1 = -1e30f;
        #pragma unroll
        for (int nj = 0; nj < 8; nj++) {
            mx0 = fmaxf(mx0, fmaxf(s[nj].x, s[nj].y));
            mx1 = fmaxf(mx1, fmaxf(s[nj].z, s[nj].w));
        }
        mx0 = fmaxf(mx0, __shfl_xor_sync(0xffffffffu, mx0, 1));
        mx0 = fmaxf(mx0, __shfl_xor_sync(0xffffffffu, mx0, 2));
        mx1 = fmaxf(mx1, __shfl_xor_sync(0xffffffffu, mx1, 1));
        mx1 = fmaxf(mx1, __shfl_xor_sync(0xffffffffu, mx1, 2));
        float mn0 = fmaxf(m0, mx0), mn1 = fmaxf(m1, mx1);
        float cr0 = __expf(m0 - mn0), cr1 = __expf(m1 - mn1);
        m0 = mn0; m1 = mn1;
        float sum0 = 0.f, sum1 = 0.f;
        #pragma unroll
        for (int nj = 0; nj < 8; nj++) {
            s[nj].x = __expf(s[nj].x - mn0); sum0 += s[nj].x;
            s[nj].y = __expf(s[nj].y - mn0); sum0 += s[nj].y;
            s[nj].z = __expf(s[nj].z - mn1); sum1 += s[nj].z;
            s[nj].w = __expf(s[nj].w - mn1); sum1 += s[nj].w;
        }
        sum0 += __shfl_xor_sync(0xffffffffu, sum0, 1);
        sum0 += __shfl_xor_sync(0xffffffffu, sum0, 2);
        sum1 += __shfl_xor_sync(0xffffffffu, sum1, 1);
        sum1 += __shfl_xor_sync(0xffffffffu, sum1, 2);
        l0 = l0*cr0 + sum0;
        l1 = l1*cr1 + sum1;
        #pragma unroll
        for (int dn = 0; dn < 8; dn++) {
            o[dn].x *= cr0; o[dn].y *= cr0;
            o[dn].z *= cr1; o[dn].w *= cr1;
        }

        // ---- P -> smem (warp-local re-fragmentation) ----
        __syncwarp();
        {
            int r0 = warp*16 + lr;
            #pragma unroll
            for (int nj = 0; nj < 8; nj++) {
                int c0 = nj*8 + 2*lc;
                Ps[r0*PP + c0]     = cvt1(s[nj].x);
                Ps[r0*PP + c0 + 1] = cvt1(s[nj].y);
                Ps[(r0+8)*PP + c0]     = cvt1(s[nj].z);
                Ps[(r0+8)*PP + c0 + 1] = cvt1(s[nj].w);
            }
        }
        __syncwarp();

        // ---- O += P @ V ----
        {
            int r = warp*16 + lr;
            #pragma unroll
            for (int ks = 0; ks < 8; ks++) {
                uint32_t pf[4];
                int k = ks*8 + lc;
                pf[0] = fu(Ps[r*PP + k]);
                pf[1] = fu(Ps[(r+8)*PP + k]);
                pf[2] = fu(Ps[r*PP + k + 4]);
                pf[3] = fu(Ps[(r+8)*PP + k + 4]);
                #pragma unroll
                for (int dn = 0; dn < 8; dn++) {
                    uint32_t bfr[2];
                    int n = dn*8 + lr;
                    bfr[0] = fu(Vs[k*VP + n]);
                    bfr[1] = fu(Vs[(k+4)*VP + n]);
                    mma_tf32(o[dn], pf, bfr);
                }
            }
        }
    }

    // ---- epilogue: normalize and store ----
    float invl0 = 1.0f / l0, invl1 = 1.0f / l1;
    int r0 = qb*64 + warp*16 + lr;
    float* orow0 = g_o + (size_t)(b*NN + r0)*CC + h*DD;
    float* orow1 = orow0 + (size_t)8*CC;
    #pragma unroll
    for (int dn = 0; dn < 8; dn++) {
        int c = dn*8 + 2*lc;
        *(float2*)(orow0 + c) = make_float2(o[dn].x*invl0, o[dn].y*invl0);
        *(float2*)(orow1 + c) = make_float2(o[dn].z*invl1, o[dn].w*invl1);
    }
}

// ---------------------------------------------------------------------------
extern "C" void kernel_launch(void* const* d_in, const int* in_sizes, int n_in,
                              void* d_out, int out_size) {
    const float* x      = (const float*)d_in[0];
    const float* cond   = (const float*)d_in[1];
    const int*   mask   = (const int*)  d_in[2];
    const float* qkv_w  = (const float*)d_in[3];
    const float* qkv_b  = (const float*)d_in[4];
    const float* proj_w = (const float*)d_in[5];
    const float* proj_b = (const float*)d_in[6];
    const float* ada_w  = (const float*)d_in[7];
    const float* ada_b  = (const float*)d_in[8];
    const float* mlp_w1 = (const float*)d_in[9];
    const float* mlp_b1 = (const float*)d_in[10];
    const float* mlp_w2 = (const float*)d_in[11];
    const float* mlp_b2 = (const float*)d_in[12];
    float* out = (float*)d_out;

    float *p_ada, *p_h, *p_qkv, *p_o, *p_x1, *p_h3;
    cudaGetSymbolAddress((void**)&p_ada, g_ada);
    cudaGetSymbolAddress((void**)&p_h,   g_h);
    cudaGetSymbolAddress((void**)&p_qkv, g_qkv);
    cudaGetSymbolAddress((void**)&p_o,   g_o);
    cudaGetSymbolAddress((void**)&p_x1,  g_x1);
    cudaGetSymbolAddress((void**)&p_h3,  g_h3);

    int attn_smem = 64*(KP + VP + PP) * (int)sizeof(float);
    cudaFuncSetAttribute(attn_tf32, cudaFuncAttributeMaxDynamicSharedMemorySize, attn_smem);

    // 1. adaLN vector
    ada_kernel<<<BB*12, 256>>>(cond, ada_w, ada_b);
    // 2. compact unmasked keys (exact: -10000 underflows to 0 in softmax)
    compact_kernel<<<BB, 1024>>>(mask);
    // 3. LN + modulate (MSA): sh_msa @0, sc_msa @512
    ln_mod_kernel<<<MM, 128>>>(x, 0, CC, p_h);
    // 4. qkv GEMM [8192,1536]
    gemm_tf32<0><<<dim3(12, 64), 256>>>(p_h, qkv_w, qkv_b, nullptr, nullptr, p_qkv, 3*CC);
    // 5. attention
    attn_tf32<<<dim3(NN/64, HH, BB), 128, attn_smem>>>();
    // 6. proj GEMM + gated residual (g_msa @1024)
    gemm_tf32<2><<<dim3(4, 64), 256>>>(p_o, proj_w, proj_b, x, p_ada + 2*CC, p_x1, CC);
    // 7. LN + modulate (MLP): sh_mlp @1536, sc_mlp @2048
    ln_mod_kernel<<<MM, 128>>>(p_x1, 3*CC, 4*CC, p_h);
    // 8. mlp1 + exact GELU
    gemm_tf32<1><<<dim3(4, 64), 256>>>(p_h, mlp_w1, mlp_b1, nullptr, nullptr, p_h3, CC);
    // 9. mlp2 + gated residual (g_mlp @2560) -> d_out
    gemm_tf32<2><<<dim3(4, 64), 256>>>(p_h3, mlp_w2, mlp_b2, p_x1, p_ada + 5*CC, out, CC);
}

// round 4
// speedup vs baseline: 3.3014x; 1.2784x over previous
#include <cuda_runtime.h>
#include <cuda_bf16.h>
#include <math.h>
#include <stdint.h>

// Problem constants
#define BB 2
#define NN 4096
#define CC 512
#define HH 8
#define DD 64
#define MM (BB*NN)      // 8192
#define ADA6 (6*CC)     // 3072
#define NT64 (NN/64)    // 64 kv tiles max

// ---------------- scratch ----------------------------------------------------
__device__ float g_ada[BB*ADA6];
__device__ float g_h [MM*CC];
__device__ float g_qkv[MM*3*CC];
__device__ float g_o [MM*CC];
__device__ float g_x1[MM*CC];
__device__ float g_h3[MM*CC];
__device__ int   g_kvidx[BB*NN];
__device__ int   g_kvcnt[BB];
// packed, tf32-rounded, fragment-permuted K/V: [b][h][tile][ks(8)][nj(8)][lane(32)] float2
__device__ float2 g_kp[BB*HH*NT64*8*8*32];
__device__ float2 g_vp[BB*HH*NT64*8*8*32];

// ---------------- tf32 helpers ----------------------------------------------
__device__ __forceinline__ uint32_t f2tf(float f) {
    uint32_t u;
    asm("cvt.rna.tf32.f32 %0, %1;" : "=r"(u) : "f"(f));
    return u;
}
__device__ __forceinline__ float cvt1(float f) { return __uint_as_float(f2tf(f)); }
__device__ __forceinline__ float4 cvt4(float4 v) {
    v.x = cvt1(v.x); v.y = cvt1(v.y); v.z = cvt1(v.z); v.w = cvt1(v.w);
    return v;
}
__device__ __forceinline__ uint32_t fu(float f) { return __float_as_uint(f); }

__device__ __forceinline__ void mma_tf32(float4& d, const uint32_t a[4], const uint32_t b[2]) {
    asm volatile(
        "mma.sync.aligned.m16n8k8.row.col.f32.tf32.tf32.f32 "
        "{%0,%1,%2,%3}, {%4,%5,%6,%7}, {%8,%9}, {%0,%1,%2,%3};\n"
        : "+f"(d.x), "+f"(d.y), "+f"(d.z), "+f"(d.w)
        : "r"(a[0]), "r"(a[1]), "r"(a[2]), "r"(a[3]), "r"(b[0]), "r"(b[1]));
}

// ---------------- ada = silu(cond) @ ada_w + ada_b ---------------------------
__global__ void ada_kernel(const float* __restrict__ cond,
                           const float* __restrict__ ada_w,
                           const float* __restrict__ ada_b) {
    int b = blockIdx.x / 12;
    int j = (blockIdx.x % 12) * 256 + threadIdx.x;
    __shared__ float sc[CC];
    for (int t = threadIdx.x; t < CC; t += 256) {
        float x = cond[b*CC + t];
        sc[t] = x / (1.0f + expf(-x));
    }
    __syncthreads();
    float acc = ada_b[j];
    #pragma unroll 8
    for (int c = 0; c < CC; c++) acc += sc[c] * ada_w[c*ADA6 + j];
    g_ada[b*ADA6 + j] = acc;
}

// ---------------- deterministic mask compaction ------------------------------
__global__ void compact_kernel(const int* __restrict__ mask) {
    int b = blockIdx.x;
    int tid = threadIdx.x;
    int base = b*NN;
    int loc[4]; int cnt = 0;
    #pragma unroll
    for (int q = 0; q < 4; q++) {
        int n = tid*4 + q;
        if (mask[base + n] == 1) loc[cnt++] = n;
    }
    __shared__ int ssum[1024];
    ssum[tid] = cnt;
    __syncthreads();
    for (int off = 1; off < 1024; off <<= 1) {
        int v = (tid >= off) ? ssum[tid - off] : 0;
        __syncthreads();
        ssum[tid] += v;
        __syncthreads();
    }
    int start = ssum[tid] - cnt;
    for (int i = 0; i < cnt; i++) g_kvidx[base + start + i] = loc[i];
    if (tid == 1023) g_kvcnt[b] = ssum[1023];
}

// ---------------- fused LayerNorm + adaLN modulate ----------------------------
__global__ void ln_mod_kernel(const float* __restrict__ X,
                              int shOff, int scOff,
                              float* __restrict__ Hout) {
    int row = blockIdx.x;
    int b = row >> 12;
    int tid = threadIdx.x;
    const float* xr = X + (size_t)row * CC;
    float4 v = *(const float4*)(xr + tid*4);
    float s  = v.x + v.y + v.z + v.w;
    float sq = v.x*v.x + v.y*v.y + v.z*v.z + v.w*v.w;
    #pragma unroll
    for (int off = 16; off > 0; off >>= 1) {
        s  += __shfl_down_sync(0xffffffffu, s,  off);
        sq += __shfl_down_sync(0xffffffffu, sq, off);
    }
    __shared__ float ws[4], wq[4];
    if ((tid & 31) == 0) { ws[tid>>5] = s; wq[tid>>5] = sq; }
    __syncthreads();
    s  = ws[0] + ws[1] + ws[2] + ws[3];
    sq = wq[0] + wq[1] + wq[2] + wq[3];
    float mean = s * (1.0f/CC);
    float var  = sq * (1.0f/CC) - mean*mean;
    float rstd = rsqrtf(var + 1e-6f);
    int c = tid*4;
    const float* adab = g_ada + b*ADA6;
    float4 sc = *(const float4*)(adab + scOff + c);
    float4 sh = *(const float4*)(adab + shOff + c);
    float4 o;
    o.x = (v.x - mean)*rstd*(1.0f + sc.x) + sh.x;
    o.y = (v.y - mean)*rstd*(1.0f + sc.y) + sh.y;
    o.z = (v.z - mean)*rstd*(1.0f + sc.z) + sh.z;
    o.w = (v.w - mean)*rstd*(1.0f + sc.w) + sh.w;
    *(float4*)(Hout + (size_t)row*CC + c) = o;
}

// ---------------- TF32 tensor-core GEMM (unchanged from R3) -------------------
template<int EPI>
__global__ __launch_bounds__(256, 2)
void gemm_tf32(const float* __restrict__ A, const float* __restrict__ W,
               const float* __restrict__ bias,
               const float* __restrict__ resid,
               const float* __restrict__ gate,
               float* __restrict__ Cout, int N) {
    __shared__ float As[2][128][20];
    __shared__ float Ws[2][16][136];
    int tid  = threadIdx.x;
    int warp = tid >> 5, lane = tid & 31;
    int wm = (warp >> 2) * 64, wn = (warp & 3) * 32;
    int m0 = blockIdx.y * 128, n0 = blockIdx.x * 128;

    int ar = tid >> 1, ac = (tid & 1) * 8;
    int wr = tid >> 4, wc = (tid & 15) * 8;

    const float* Ap = A + (size_t)(m0 + ar) * CC + ac;
    const float* Wp = W + (size_t)wr * N + n0 + wc;

    float4 acc[4][4];
    #pragma unroll
    for (int i = 0; i < 4; i++)
        #pragma unroll
        for (int j = 0; j < 4; j++) acc[i][j] = make_float4(0.f,0.f,0.f,0.f);

    {
        float4 a0 = *(const float4*)(Ap);
        float4 a1 = *(const float4*)(Ap + 4);
        float4 b0 = *(const float4*)(Wp);
        float4 b1 = *(const float4*)(Wp + 4);
        *(float4*)&As[0][ar][ac]     = cvt4(a0);
        *(float4*)&As[0][ar][ac + 4] = cvt4(a1);
        *(float4*)&Ws[0][wr][wc]     = cvt4(b0);
        *(float4*)&Ws[0][wr][wc + 4] = cvt4(b1);
    }
    __syncthreads();

    #pragma unroll 2
    for (int kt = 0; kt < 32; kt++) {
        int cur = kt & 1;
        float4 na0, na1, nb0, nb1;
        if (kt < 31) {
            na0 = *(const float4*)(Ap + (kt+1)*16);
            na1 = *(const float4*)(Ap + (kt+1)*16 + 4);
            nb0 = *(const float4*)(Wp + (size_t)(kt+1)*16*N);
            nb1 = *(const float4*)(Wp + (size_t)(kt+1)*16*N + 4);
        }
        #pragma unroll
        for (int ks = 0; ks < 16; ks += 8) {
            uint32_t afr[4][4];
            #pragma unroll
            for (int mi = 0; mi < 4; mi++) {
                int r = wm + mi*16 + (lane >> 2);
                int c = ks + (lane & 3);
                afr[mi][0] = fu(As[cur][r][c]);
                afr[mi][1] = fu(As[cur][r+8][c]);
                afr[mi][2] = fu(As[cur][r][c+4]);
                afr[mi][3] = fu(As[cur][r+8][c+4]);
            }
            uint32_t bfr[4][2];
            #pragma unroll
            for (int nj = 0; nj < 4; nj++) {
                int n = wn + nj*8 + (lane >> 2);
                int k = ks + (lane & 3);
                bfr[nj][0] = fu(Ws[cur][k][n]);
                bfr[nj][1] = fu(Ws[cur][k+4][n]);
            }
            #pragma unroll
            for (int mi = 0; mi < 4; mi++)
                #pragma unroll
                for (int nj = 0; nj < 4; nj++)
                    mma_tf32(acc[mi][nj], afr[mi], bfr[nj]);
        }
        if (kt < 31) {
            int nxt = cur ^ 1;
            *(float4*)&As[nxt][ar][ac]     = cvt4(na0);
            *(float4*)&As[nxt][ar][ac + 4] = cvt4(na1);
            *(float4*)&Ws[nxt][wr][wc]     = cvt4(nb0);
            *(float4*)&Ws[nxt][wr][wc + 4] = cvt4(nb1);
        }
        __syncthreads();
    }

    #pragma unroll
    for (int mi = 0; mi < 4; mi++) {
        int r0 = m0 + wm + mi*16 + (lane >> 2);
        int r1 = r0 + 8;
        int b0i = r0 >> 12, b1i = r1 >> 12;
        #pragma unroll
        for (int nj = 0; nj < 4; nj++) {
            int c = n0 + wn + nj*8 + 2*(lane & 3);
            float4 d = acc[mi][nj];
            float bx = bias[c], by = bias[c+1];
            float vx = d.x + bx, vy = d.y + by;
            float wx = d.z + bx, wy = d.w + by;
            if (EPI == 1) {
                vx = 0.5f*vx*(1.0f + erff(vx*0.70710678118654752f));
                vy = 0.5f*vy*(1.0f + erff(vy*0.70710678118654752f));
                wx = 0.5f*wx*(1.0f + erff(wx*0.70710678118654752f));
                wy = 0.5f*wy*(1.0f + erff(wy*0.70710678118654752f));
            } else if (EPI == 2) {
                float gx0 = gate[(size_t)b0i*ADA6 + c], gy0 = gate[(size_t)b0i*ADA6 + c + 1];
                float gx1 = gate[(size_t)b1i*ADA6 + c], gy1 = gate[(size_t)b1i*ADA6 + c + 1];
                vx = resid[(size_t)r0*CC + c]     + gx0*vx;
                vy = resid[(size_t)r0*CC + c + 1] + gy0*vy;
                wx = resid[(size_t)r1*CC + c]     + gx1*wx;
                wy = resid[(size_t)r1*CC + c + 1] + gy1*wy;
            }
            *(float2*)&Cout[(size_t)r0*N + c] = make_float2(vx, vy);
            *(float2*)&Cout[(size_t)r1*N + c] = make_float2(wx, wy);
        }
    }
}

// ---------------- KV pack: gather + tf32 + fragment-permute -------------------
// grid (NT64, HH, BB), 256 thr. One 64-slot tile per block.
__global__ __launch_bounds__(256)
void kv_pack_kernel() {
    __shared__ float Ks[64][68];
    __shared__ float Vs[64][68];
    int t = blockIdx.x, h = blockIdx.y, b = blockIdx.z;
    int nk = g_kvcnt[b];
    int ntiles = (nk + 63) >> 6;
    if (t >= ntiles) return;
    int tid = threadIdx.x;

    // stage (coalesced-ish gather), zero-fill invalid slots
    {
        int row = tid >> 2, q = tid & 3;      // 4 threads/row, 16 floats each
        int slot = t*64 + row;
        if (slot < nk) {
            int n = g_kvidx[b*NN + slot];
            const float* base = g_qkv + (size_t)(b*NN + n)*(3*CC) + h*DD + q*16;
            #pragma unroll
            for (int i = 0; i < 4; i++) {
                *(float4*)&Ks[row][q*16 + i*4] = cvt4(*(const float4*)(base + CC   + i*4));
                *(float4*)&Vs[row][q*16 + i*4] = cvt4(*(const float4*)(base + 2*CC + i*4));
            }
        } else {
            float4 z = make_float4(0.f,0.f,0.f,0.f);
            #pragma unroll
            for (int i = 0; i < 4; i++) {
                *(float4*)&Ks[row][q*16 + i*4] = z;
                *(float4*)&Vs[row][q*16 + i*4] = z;
            }
        }
    }
    __syncthreads();

    // write permuted fragments (coalesced float2 stores)
    int lane = tid & 31, nj = tid >> 5;       // 8 nj groups x 32 lanes
    int lr = lane >> 2, lc = lane & 3;
    size_t tb = ((size_t)(b*HH + h)*NT64 + t) * 2048;   // 8*8*32 float2 per tile
    #pragma unroll
    for (int ks = 0; ks < 8; ks++) {
        // K frag for mma(nj,ks): n = nj*8+lr, k = ks*8+lc (+4)
        g_kp[tb + (ks*8 + nj)*32 + lane] =
            make_float2(Ks[nj*8 + lr][ks*8 + lc], Ks[nj*8 + lr][ks*8 + lc + 4]);
        // V frag for mma(dn=nj,ks): k = ks*8+lc (+4), n = nj*8+lr
        g_vp[tb + (ks*8 + nj)*32 + lane] =
            make_float2(Vs[ks*8 + lc][nj*8 + lr], Vs[ks*8 + lc + 4][nj*8 + lr]);
    }
}

// ---------------- TF32 flash attention v3 ------------------------------------
// 128 q-rows/block, 8 warps (16 rows each), KV frags straight from packed gmem.
__global__ __launch_bounds__(256, 1)
void attn_tf32() {
    __shared__ float Ps[8][16][68];   // per-warp P tile

    int qb = blockIdx.x, h = blockIdx.y, b = blockIdx.z;
    int tid = threadIdx.x;
    int warp = tid >> 5, lane = tid & 31;
    int lr = lane >> 2, lc = lane & 3;

    // ---- persistent Q fragments straight from gmem (scaled, tf32) ----
    uint32_t qf[8][4];
    {
        const float* q0 = g_qkv + (size_t)(b*NN + qb*128 + warp*16 + lr)*(3*CC) + h*DD;
        const float* q1 = q0 + (size_t)8*(3*CC);
        #pragma unroll
        for (int ks = 0; ks < 8; ks++) {
            qf[ks][0] = f2tf(q0[ks*8 + lc]     * 0.125f);
            qf[ks][1] = f2tf(q1[ks*8 + lc]     * 0.125f);
            qf[ks][2] = f2tf(q0[ks*8 + lc + 4] * 0.125f);
            qf[ks][3] = f2tf(q1[ks*8 + lc + 4] * 0.125f);
        }
    }

    float4 o[8];
    #pragma unroll
    for (int dn = 0; dn < 8; dn++) o[dn] = make_float4(0.f,0.f,0.f,0.f);
    float m0 = -INFINITY, m1 = -INFINITY, l0 = 0.f, l1 = 0.f;

    int nk = g_kvcnt[b];
    int ntiles = (nk + 63) >> 6;
    const float2* kpb = g_kp + ((size_t)(b*HH + h))*NT64*2048;
    const float2* vpb = g_vp + ((size_t)(b*HH + h))*NT64*2048;

    for (int t = 0; t < ntiles; t++) {
        const float2* kp = kpb + (size_t)t*2048;
        const float2* vp = vpb + (size_t)t*2048;

        // ---- S = Q K^T : one LDG.64 per mma ----
        float4 s[8];
        #pragma unroll
        for (int nj = 0; nj < 8; nj++) s[nj] = make_float4(0.f,0.f,0.f,0.f);
        #pragma unroll
        for (int ks = 0; ks < 8; ks++) {
            #pragma unroll
            for (int nj = 0; nj < 8; nj++) {
                float2 kv = __ldg(&kp[(ks*8 + nj)*32 + lane]);
                uint32_t bfr[2] = { fu(kv.x), fu(kv.y) };
                mma_tf32(s[nj], qf[ks], bfr);
            }
        }

        // mask invalid columns (last tile only has work here)
        int valid = nk - t*64; if (valid > 64) valid = 64;
        #pragma unroll
        for (int nj = 0; nj < 8; nj++) {
            int c0 = nj*8 + 2*lc;
            if (c0     >= valid) { s[nj].x = -1e30f; s[nj].z = -1e30f; }
            if (c0 + 1 >= valid) { s[nj].y = -1e30f; s[nj].w = -1e30f; }
        }

        // ---- online softmax (fragments + quad shuffles) ----
        float mx0 = -1e30f, mx1 = -1e30f;
        #pragma unroll
        for (int nj = 0; nj < 8; nj++) {
            mx0 = fmaxf(mx0, fmaxf(s[nj].x, s[nj].y));
            mx1 = fmaxf(mx1, fmaxf(s[nj].z, s[nj].w));
        }
        mx0 = fmaxf(mx0, __shfl_xor_sync(0xffffffffu, mx0, 1));
        mx0 = fmaxf(mx0, __shfl_xor_sync(0xffffffffu, mx0, 2));
        mx1 = fmaxf(mx1, __shfl_xor_sync(0xffffffffu, mx1, 1));
        mx1 = fmaxf(mx1, __shfl_xor_sync(0xffffffffu, mx1, 2));
        float mn0 = fmaxf(m0, mx0), mn1 = fmaxf(m1, mx1);
        float cr0 = __expf(m0 - mn0), cr1 = __expf(m1 - mn1);
        m0 = mn0; m1 = mn1;
        float sum0 = 0.f, sum1 = 0.f;
        #pragma unroll
        for (int nj = 0; nj < 8; nj++) {
            s[nj].x = __expf(s[nj].x - mn0); sum0 += s[nj].x;
            s[nj].y = __expf(s[nj].y - mn0); sum0 += s[nj].y;
            s[nj].z = __expf(s[nj].z - mn1); sum1 += s[nj].z;
            s[nj].w = __expf(s[nj].w - mn1); sum1 += s[nj].w;
        }
        sum0 += __shfl_xor_sync(0xffffffffu, sum0, 1);
        sum0 += __shfl_xor_sync(0xffffffffu, sum0, 2);
        sum1 += __shfl_xor_sync(0xffffffffu, sum1, 1);
        sum1 += __shfl_xor_sync(0xffffffffu, sum1, 2);
        l0 = l0*cr0 + sum0;
        l1 = l1*cr1 + sum1;
        #pragma unroll
        for (int dn = 0; dn < 8; dn++) {
            o[dn].x *= cr0; o[dn].y *= cr0;
            o[dn].z *= cr1; o[dn].w *= cr1;
        }

        // ---- P -> warp-private smem (float2 stores) ----
        #pragma unroll
        for (int nj = 0; nj < 8; nj++) {
            int c0 = nj*8 + 2*lc;
            *(float2*)&Ps[warp][lr][c0]     = make_float2(cvt1(s[nj].x), cvt1(s[nj].y));
            *(float2*)&Ps[warp][lr + 8][c0] = make_float2(cvt1(s[nj].z), cvt1(s[nj].w));
        }
        __syncwarp();

        // ---- O += P @ V ----
        #pragma unroll
        for (int ks = 0; ks < 8; ks++) {
            uint32_t pf[4];
            int k = ks*8 + lc;
            pf[0] = fu(Ps[warp][lr][k]);
            pf[1] = fu(Ps[warp][lr + 8][k]);
            pf[2] = fu(Ps[warp][lr][k + 4]);
            pf[3] = fu(Ps[warp][lr + 8][k + 4]);
            #pragma unroll
            for (int dn = 0; dn < 8; dn++) {
                float2 vv = __ldg(&vp[(ks*8 + dn)*32 + lane]);
                uint32_t bfr[2] = { fu(vv.x), fu(vv.y) };
                mma_tf32(o[dn], pf, bfr);
            }
        }
        __syncwarp();   // P reads done before next tile's stores
    }

    // ---- epilogue: normalize, store ----
    float invl0 = 1.0f / l0, invl1 = 1.0f / l1;
    int r0 = qb*128 + warp*16 + lr;
    float* orow0 = g_o + (size_t)(b*NN + r0)*CC + h*DD;
    float* orow1 = orow0 + (size_t)8*CC;
    #pragma unroll
    for (int dn = 0; dn < 8; dn++) {
        int c = dn*8 + 2*lc;
        *(float2*)(orow0 + c) = make_float2(o[dn].x*invl0, o[dn].y*invl0);
        *(float2*)(orow1 + c) = make_float2(o[dn].z*invl1, o[dn].w*invl1);
    }
}

// ---------------------------------------------------------------------------
extern "C" void kernel_launch(void* const* d_in, const int* in_sizes, int n_in,
                              void* d_out, int out_size) {
    const float* x      = (const float*)d_in[0];
    const float* cond   = (const float*)d_in[1];
    const int*   mask   = (const int*)  d_in[2];
    const float* qkv_w  = (const float*)d_in[3];
    const float* qkv_b  = (const float*)d_in[4];
    const float* proj_w = (const float*)d_in[5];
    const float* proj_b = (const float*)d_in[6];
    const float* ada_w  = (const float*)d_in[7];
    const float* ada_b  = (const float*)d_in[8];
    const float* mlp_w1 = (const float*)d_in[9];
    const float* mlp_b1 = (const float*)d_in[10];
    const float* mlp_w2 = (const float*)d_in[11];
    const float* mlp_b2 = (const float*)d_in[12];
    float* out = (float*)d_out;

    float *p_ada, *p_h, *p_qkv, *p_o, *p_x1, *p_h3;
    cudaGetSymbolAddress((void**)&p_ada, g_ada);
    cudaGetSymbolAddress((void**)&p_h,   g_h);
    cudaGetSymbolAddress((void**)&p_qkv, g_qkv);
    cudaGetSymbolAddress((void**)&p_o,   g_o);
    cudaGetSymbolAddress((void**)&p_x1,  g_x1);
    cudaGetSymbolAddress((void**)&p_h3,  g_h3);

    // 1. adaLN vector
    ada_kernel<<<BB*12, 256>>>(cond, ada_w, ada_b);
    // 2. compact unmasked keys (exact: -10000 underflows to 0 in softmax)
    compact_kernel<<<BB, 1024>>>(mask);
    // 3. LN + modulate (MSA): sh_msa @0, sc_msa @512
    ln_mod_kernel<<<MM, 128>>>(x, 0, CC, p_h);
    // 4. qkv GEMM [8192,1536]
    gemm_tf32<0><<<dim3(12, 64), 256>>>(p_h, qkv_w, qkv_b, nullptr, nullptr, p_qkv, 3*CC);
    // 5. pack compacted K/V into fragment-permuted tf32 buffers
    kv_pack_kernel<<<dim3(NT64, HH, BB), 256>>>();
    // 6. attention (128 q-rows/block)
    attn_tf32<<<dim3(NN/128, HH, BB), 256>>>();
    // 7. proj GEMM + gated residual (g_msa @1024)
    gemm_tf32<2><<<dim3(4, 64), 256>>>(p_o, proj_w, proj_b, x, p_ada + 2*CC, p_x1, CC);
    // 8. LN + modulate (MLP): sh_mlp @1536, sc_mlp @2048
    ln_mod_kernel<<<MM, 128>>>(p_x1, 3*CC, 4*CC, p_h);
    // 9. mlp1 + exact GELU
    gemm_tf32<1><<<dim3(4, 64), 256>>>(p_h, mlp_w1, mlp_b1, nullptr, nullptr, p_h3, CC);
    // 10. mlp2 + gated residual (g_mlp @2560) -> d_out
    gemm_tf32<2><<<dim3(4, 64), 256>>>(p_h3, mlp_w2, mlp_b2, p_x1, p_ada + 5*CC, out, CC);
}

// round 5
// speedup vs baseline: 3.6672x; 1.1108x over previous
#include <cuda_runtime.h>
#include <cuda_bf16.h>
#include <math.h>
#include <stdint.h>

// Problem constants
#define BB 2
#define NN 4096
#define CC 512
#define HH 8
#define DD 64
#define MM (BB*NN)      // 8192
#define ADA6 (6*CC)     // 3072
#define NT64 (NN/64)    // 64 kv tiles max

// ---------------- scratch ----------------------------------------------------
__device__ float g_ada[BB*ADA6];
__device__ float g_h [MM*CC];
__device__ float g_qkv[MM*3*CC];
__device__ float g_o [MM*CC];
__device__ float g_x1[MM*CC];
__device__ float g_h3[MM*CC];
__device__ int   g_kvidx[BB*NN];
__device__ int   g_kvcnt[BB];
// packed K/V fragments: [b][h][tile][ks(8)][nj(8)][lane(32)] float2
__device__ float2 g_kp[BB*HH*NT64*8*8*32];
__device__ float2 g_vp[BB*HH*NT64*8*8*32];
// packed weights (fragment-permuted tf32): qkv | proj | mlp1 | mlp2
#define WP_QKV  0
#define WP_PROJ (CC*3*CC)
#define WP_MLP1 (WP_PROJ + CC*CC)
#define WP_MLP2 (WP_MLP1 + CC*CC)
__device__ float g_wp[CC*3*CC + 3*CC*CC];

// ---------------- tf32 helpers ----------------------------------------------
__device__ __forceinline__ uint32_t f2tf(float f) {
    uint32_t u;
    asm("cvt.rna.tf32.f32 %0, %1;" : "=r"(u) : "f"(f));
    return u;
}
__device__ __forceinline__ float cvt1(float f) { return __uint_as_float(f2tf(f)); }
__device__ __forceinline__ float4 cvt4(float4 v) {
    v.x = cvt1(v.x); v.y = cvt1(v.y); v.z = cvt1(v.z); v.w = cvt1(v.w);
    return v;
}
__device__ __forceinline__ uint32_t fu(float f) { return __float_as_uint(f); }

__device__ __forceinline__ void mma_tf32(float4& d, const uint32_t a[4], const uint32_t b[2]) {
    asm volatile(
        "mma.sync.aligned.m16n8k8.row.col.f32.tf32.tf32.f32 "
        "{%0,%1,%2,%3}, {%4,%5,%6,%7}, {%8,%9}, {%0,%1,%2,%3};\n"
        : "+f"(d.x), "+f"(d.y), "+f"(d.z), "+f"(d.w)
        : "r"(a[0]), "r"(a[1]), "r"(a[2]), "r"(a[3]), "r"(b[0]), "r"(b[1]));
}

// ---------------- ada = silu(cond) @ ada_w + ada_b ---------------------------
__global__ void ada_kernel(const float* __restrict__ cond,
                           const float* __restrict__ ada_w,
                           const float* __restrict__ ada_b) {
    int b = blockIdx.x / 12;
    int j = (blockIdx.x % 12) * 256 + threadIdx.x;
    __shared__ float sc[CC];
    for (int t = threadIdx.x; t < CC; t += 256) {
        float x = cond[b*CC + t];
        sc[t] = x / (1.0f + expf(-x));
    }
    __syncthreads();
    float acc = ada_b[j];
    #pragma unroll 8
    for (int c = 0; c < CC; c++) acc += sc[c] * ada_w[c*ADA6 + j];
    g_ada[b*ADA6 + j] = acc;
}

// ---------------- deterministic mask compaction ------------------------------
__global__ void compact_kernel(const int* __restrict__ mask) {
    int b = blockIdx.x;
    int tid = threadIdx.x;
    int base = b*NN;
    int loc[4]; int cnt = 0;
    #pragma unroll
    for (int q = 0; q < 4; q++) {
        int n = tid*4 + q;
        if (mask[base + n] == 1) loc[cnt++] = n;
    }
    __shared__ int ssum[1024];
    ssum[tid] = cnt;
    __syncthreads();
    for (int off = 1; off < 1024; off <<= 1) {
        int v = (tid >= off) ? ssum[tid - off] : 0;
        __syncthreads();
        ssum[tid] += v;
        __syncthreads();
    }
    int start = ssum[tid] - cnt;
    for (int i = 0; i < cnt; i++) g_kvidx[base + start + i] = loc[i];
    if (tid == 1023) g_kvcnt[b] = ssum[1023];
}

// ---------------- fused LayerNorm + adaLN modulate ----------------------------
__global__ void ln_mod_kernel(const float* __restrict__ X,
                              int shOff, int scOff,
                              float* __restrict__ Hout) {
    int row = blockIdx.x;
    int b = row >> 12;
    int tid = threadIdx.x;
    const float* xr = X + (size_t)row * CC;
    float4 v = *(const float4*)(xr + tid*4);
    float s  = v.x + v.y + v.z + v.w;
    float sq = v.x*v.x + v.y*v.y + v.z*v.z + v.w*v.w;
    #pragma unroll
    for (int off = 16; off > 0; off >>= 1) {
        s  += __shfl_down_sync(0xffffffffu, s,  off);
        sq += __shfl_down_sync(0xffffffffu, sq, off);
    }
    __shared__ float ws[4], wq[4];
    if ((tid & 31) == 0) { ws[tid>>5] = s; wq[tid>>5] = sq; }
    __syncthreads();
    s  = ws[0] + ws[1] + ws[2] + ws[3];
    sq = wq[0] + wq[1] + wq[2] + wq[3];
    float mean = s * (1.0f/CC);
    float var  = sq * (1.0f/CC) - mean*mean;
    float rstd = rsqrtf(var + 1e-6f);
    int c = tid*4;
    const float* adab = g_ada + b*ADA6;
    float4 sc = *(const float4*)(adab + scOff + c);
    float4 sh = *(const float4*)(adab + shOff + c);
    float4 o;
    o.x = (v.x - mean)*rstd*(1.0f + sc.x) + sh.x;
    o.y = (v.y - mean)*rstd*(1.0f + sc.y) + sh.y;
    o.z = (v.z - mean)*rstd*(1.0f + sc.z) + sh.z;
    o.w = (v.w - mean)*rstd*(1.0f + sc.w) + sh.w;
    *(float4*)(Hout + (size_t)row*CC + c) = o;
}

// ---------------- weight pack: W[512,N] -> fragment-permuted tf32 -------------
// Wp[((k8*(N/8) + nf)*32 + lane)*2 + e] = tf32(W[k8*8 + (lane&3) + e*4][nf*8 + (lane>>2)])
// grid (64, N/64), 256 threads.
__global__ void wpack_kernel(const float* __restrict__ W, float* __restrict__ Wp, int N) {
    __shared__ float ws[8][65];
    int k8 = blockIdx.x, nt = blockIdx.y;
    int tid = threadIdx.x;
    for (int i = tid; i < 512; i += 256) {
        int r = i >> 6, c = i & 63;
        ws[r][c] = cvt1(W[(size_t)(k8*8 + r)*N + nt*64 + c]);
    }
    __syncthreads();
    for (int i = tid; i < 512; i += 256) {
        int nfl = i >> 6, rest = i & 63;
        int lane = rest >> 1, e = rest & 1;
        int lr = lane >> 2, lc = lane & 3;
        Wp[((size_t)(k8*(N/8) + nt*8 + nfl)*32 + lane)*2 + e] = ws[lc + e*4][nfl*8 + lr];
    }
}

// ---------------- TF32 tensor-core GEMM v2 ------------------------------------
// A from smem (fragment-permuted, swizzled), B fragments straight from packed gmem.
// Block 128x128, 8 warps (2x4), Kt=16 double-buffered.
#define ASWZ(lane) ((lane) ^ (((lane) >> 3) & 3))
template<int EPI>
__global__ __launch_bounds__(256, 2)
void gemm_tf32(const float* __restrict__ A, const float* __restrict__ Wp,
               const float* __restrict__ bias,
               const float* __restrict__ resid,
               const float* __restrict__ gate,
               float* __restrict__ Cout, int N) {
    __shared__ float Asp[2][2048];   // 16 regions x 128 floats
    int tid  = threadIdx.x;
    int warp = tid >> 5, lane = tid & 31;
    int wg = warp >> 2, wn4 = warp & 3;
    int m0 = blockIdx.y * 128, n0 = blockIdx.x * 128;

    // ---- A loader mapping: row-pair x col-quad ----
    int rp = tid >> 2, cq = tid & 3;
    int lg = rp >> 5, lmi = (rp >> 3) & 3, llr = rp & 7;
    int lks = cq >> 1, lch = cq & 1;
    int lrow = lg*64 + lmi*16 + llr;
    const float* Ap = A + (size_t)(m0 + lrow)*CC + lks*8 + lch*4;
    // permuted store base: region(lg,lmi,lks)*128 + ASWZ(llr*4+lc)*4 + 2*lch (+e)
    int sregion = ((lg*4 + lmi)*2 + lks)*128;

    // ---- B fragment base: nf = n0/8 + wn4*4 + nj ----
    const float* wp0 = Wp + ((size_t)(n0/8 + wn4*4)*32 + lane)*2;
    size_t wp_k8 = (size_t)(N/8)*64;     // stride per k8 in floats

    float4 acc[4][4];
    #pragma unroll
    for (int i = 0; i < 4; i++)
        #pragma unroll
        for (int j = 0; j < 4; j++) acc[i][j] = make_float4(0.f,0.f,0.f,0.f);

    // ---- preload kt=0 ----
    float4 va = cvt4(*(const float4*)(Ap));
    float4 vb = cvt4(*(const float4*)(Ap + 8*CC));
    {
        float* dst = &Asp[0][sregion];
        float vva[4] = {va.x, va.y, va.z, va.w};
        float vvb[4] = {vb.x, vb.y, vb.z, vb.w};
        #pragma unroll
        for (int lc = 0; lc < 4; lc++)
            *(float2*)&dst[ASWZ(llr*4 + lc)*4 + 2*lch] = make_float2(vva[lc], vvb[lc]);
    }
    float2 bf[2][2][4];   // [buf][ks][nj]
    #pragma unroll
    for (int ks = 0; ks < 2; ks++)
        #pragma unroll
        for (int nj = 0; nj < 4; nj++)
            bf[0][ks][nj] = *(const float2*)(wp0 + (size_t)ks*wp_k8 + (size_t)nj*64);
    __syncthreads();

    #pragma unroll 2
    for (int kt = 0; kt < 32; kt++) {
        int cur = kt & 1;
        // prefetch next tile
        if (kt < 31) {
            va = cvt4(*(const float4*)(Ap + (kt+1)*16));
            vb = cvt4(*(const float4*)(Ap + (kt+1)*16 + 8*CC));
            #pragma unroll
            for (int ks = 0; ks < 2; ks++)
                #pragma unroll
                for (int nj = 0; nj < 4; nj++)
                    bf[cur^1][ks][nj] =
                        *(const float2*)(wp0 + ((size_t)(kt+1)*2 + ks)*wp_k8 + (size_t)nj*64);
        }
        // compute
        #pragma unroll
        for (int ks = 0; ks < 2; ks++) {
            #pragma unroll
            for (int mi = 0; mi < 4; mi++) {
                float4 af = *(const float4*)&Asp[cur][((wg*4 + mi)*2 + ks)*128 + ASWZ(lane)*4];
                uint32_t afr[4] = { fu(af.x), fu(af.y), fu(af.z), fu(af.w) };
                #pragma unroll
                for (int nj = 0; nj < 4; nj++) {
                    uint32_t bfr[2] = { fu(bf[cur][ks][nj].x), fu(bf[cur][ks][nj].y) };
                    mma_tf32(acc[mi][nj], afr, bfr);
                }
            }
        }
        // store next A tile
        if (kt < 31) {
            float* dst = &Asp[cur^1][sregion];
            float vva[4] = {va.x, va.y, va.z, va.w};
            float vvb[4] = {vb.x, vb.y, vb.z, vb.w};
            #pragma unroll
            for (int lc = 0; lc < 4; lc++)
                *(float2*)&dst[ASWZ(llr*4 + lc)*4 + 2*lch] = make_float2(vva[lc], vvb[lc]);
        }
        __syncthreads();
    }

    // ---- epilogue (unchanged layout) ----
    int wm = wg * 64, wn = wn4 * 32;
    #pragma unroll
    for (int mi = 0; mi < 4; mi++) {
        int r0 = m0 + wm + mi*16 + (lane >> 2);
        int r1 = r0 + 8;
        int b0i = r0 >> 12, b1i = r1 >> 12;
        #pragma unroll
        for (int nj = 0; nj < 4; nj++) {
            int c = n0 + wn + nj*8 + 2*(lane & 3);
            float4 d = acc[mi][nj];
            float bx = bias[c], by = bias[c+1];
            float vx = d.x + bx, vy = d.y + by;
            float wx = d.z + bx, wy = d.w + by;
            if (EPI == 1) {
                vx = 0.5f*vx*(1.0f + erff(vx*0.70710678118654752f));
                vy = 0.5f*vy*(1.0f + erff(vy*0.70710678118654752f));
                wx = 0.5f*wx*(1.0f + erff(wx*0.70710678118654752f));
                wy = 0.5f*wy*(1.0f + erff(wy*0.70710678118654752f));
            } else if (EPI == 2) {
                float gx0 = gate[(size_t)b0i*ADA6 + c], gy0 = gate[(size_t)b0i*ADA6 + c + 1];
                float gx1 = gate[(size_t)b1i*ADA6 + c], gy1 = gate[(size_t)b1i*ADA6 + c + 1];
                vx = resid[(size_t)r0*CC + c]     + gx0*vx;
                vy = resid[(size_t)r0*CC + c + 1] + gy0*vy;
                wx = resid[(size_t)r1*CC + c]     + gx1*wx;
                wy = resid[(size_t)r1*CC + c + 1] + gy1*wy;
            }
            *(float2*)&Cout[(size_t)r0*N + c] = make_float2(vx, vy);
            *(float2*)&Cout[(size_t)r1*N + c] = make_float2(wx, wy);
        }
    }
}

// ---------------- KV pack: gather + tf32 + fragment-permute -------------------
__global__ __launch_bounds__(256)
void kv_pack_kernel() {
    __shared__ float Ks[64][68];
    __shared__ float Vs[64][68];
    int t = blockIdx.x, h = blockIdx.y, b = blockIdx.z;
    int nk = g_kvcnt[b];
    int ntiles = (nk + 63) >> 6;
    if (t >= ntiles) return;
    int tid = threadIdx.x;

    {
        int row = tid >> 2, q = tid & 3;
        int slot = t*64 + row;
        if (slot < nk) {
            int n = g_kvidx[b*NN + slot];
            const float* base = g_qkv + (size_t)(b*NN + n)*(3*CC) + h*DD + q*16;
            #pragma unroll
            for (int i = 0; i < 4; i++) {
                *(float4*)&Ks[row][q*16 + i*4] = cvt4(*(const float4*)(base + CC   + i*4));
                *(float4*)&Vs[row][q*16 + i*4] = cvt4(*(const float4*)(base + 2*CC + i*4));
            }
        } else {
            float4 z = make_float4(0.f,0.f,0.f,0.f);
            #pragma unroll
            for (int i = 0; i < 4; i++) {
                *(float4*)&Ks[row][q*16 + i*4] = z;
                *(float4*)&Vs[row][q*16 + i*4] = z;
            }
        }
    }
    __syncthreads();

    int lane = tid & 31, nj = tid >> 5;
    int lr = lane >> 2, lc = lane & 3;
    size_t tb = ((size_t)(b*HH + h)*NT64 + t) * 2048;
    #pragma unroll
    for (int ks = 0; ks < 8; ks++) {
        g_kp[tb + (ks*8 + nj)*32 + lane] =
            make_float2(Ks[nj*8 + lr][ks*8 + lc], Ks[nj*8 + lr][ks*8 + lc + 4]);
        g_vp[tb + (ks*8 + nj)*32 + lane] =
            make_float2(Vs[ks*8 + lc][nj*8 + lr], Vs[ks*8 + lc + 4][nj*8 + lr]);
    }
}

// ---------------- TF32 flash attention (unchanged from R4) --------------------
__global__ __launch_bounds__(256, 1)
void attn_tf32() {
    __shared__ float Ps[8][16][68];

    int qb = blockIdx.x, h = blockIdx.y, b = blockIdx.z;
    int tid = threadIdx.x;
    int warp = tid >> 5, lane = tid & 31;
    int lr = lane >> 2, lc = lane & 3;

    uint32_t qf[8][4];
    {
        const float* q0 = g_qkv + (size_t)(b*NN + qb*128 + warp*16 + lr)*(3*CC) + h*DD;
        const float* q1 = q0 + (size_t)8*(3*CC);
        #pragma unroll
        for (int ks = 0; ks < 8; ks++) {
            qf[ks][0] = f2tf(q0[ks*8 + lc]     * 0.125f);
            qf[ks][1] = f2tf(q1[ks*8 + lc]     * 0.125f);
            qf[ks][2] = f2tf(q0[ks*8 + lc + 4] * 0.125f);
            qf[ks][3] = f2tf(q1[ks*8 + lc + 4] * 0.125f);
        }
    }

    float4 o[8];
    #pragma unroll
    for (int dn = 0; dn < 8; dn++) o[dn] = make_float4(0.f,0.f,0.f,0.f);
    float m0 = -INFINITY, m1 = -INFINITY, l0 = 0.f, l1 = 0.f;

    int nk = g_kvcnt[b];
    int ntiles = (nk + 63) >> 6;
    const float2* kpb = g_kp + ((size_t)(b*HH + h))*NT64*2048;
    const float2* vpb = g_vp + ((size_t)(b*HH + h))*NT64*2048;

    for (int t = 0; t < ntiles; t++) {
        const float2* kp = kpb + (size_t)t*2048;
        const float2* vp = vpb + (size_t)t*2048;

        float4 s[8];
        #pragma unroll
        for (int nj = 0; nj < 8; nj++) s[nj] = make_float4(0.f,0.f,0.f,0.f);
        #pragma unroll
        for (int ks = 0; ks < 8; ks++) {
            #pragma unroll
            for (int nj = 0; nj < 8; nj++) {
                float2 kv = __ldg(&kp[(ks*8 + nj)*32 + lane]);
                uint32_t bfr[2] = { fu(kv.x), fu(kv.y) };
                mma_tf32(s[nj], qf[ks], bfr);
            }
        }

        int valid = nk - t*64; if (valid > 64) valid = 64;
        #pragma unroll
        for (int nj = 0; nj < 8; nj++) {
            int c0 = nj*8 + 2*lc;
            if (c0     >= valid) { s[nj].x = -1e30f; s[nj].z = -1e30f; }
            if (c0 + 1 >= valid) { s[nj].y = -1e30f; s[nj].w = -1e30f; }
        }

        float mx0 = -1e30f, mx1 = -1e30f;
        #pragma unroll
        for (int nj = 0; nj < 8; nj++) {
            mx0 = fmaxf(mx0, fmaxf(s[nj].x, s[nj].y));
            mx1 = fmaxf(mx1, fmaxf(s[nj].z, s[nj].w));
        }
        mx0 = fmaxf(mx0, __shfl_xor_sync(0xffffffffu, mx0, 1));
        mx0 = fmaxf(mx0, __shfl_xor_sync(0xffffffffu, mx0, 2));
        mx1 = fmaxf(mx1, __shfl_xor_sync(0xffffffffu, mx1, 1));
        mx1 = fmaxf(mx1, __shfl_xor_sync(0xffffffffu, mx1, 2));
        float mn0 = fmaxf(m0, mx0), mn1 = fmaxf(m1, mx1);
        float cr0 = __expf(m0 - mn0), cr1 = __expf(m1 - mn1);
        m0 = mn0; m1 = mn1;
        float sum0 = 0.f, sum1 = 0.f;
        #pragma unroll
        for (int nj = 0; nj < 8; nj++) {
            s[nj].x = __expf(s[nj].x - mn0); sum0 += s[nj].x;
            s[nj].y = __expf(s[nj].y - mn0); sum0 += s[nj].y;
            s[nj].z = __expf(s[nj].z - mn1); sum1 += s[nj].z;
            s[nj].w = __expf(s[nj].w - mn1); sum1 += s[nj].w;
        }
        sum0 += __shfl_xor_sync(0xffffffffu, sum0, 1);
        sum0 += __shfl_xor_sync(0xffffffffu, sum0, 2);
        sum1 += __shfl_xor_sync(0xffffffffu, sum1, 1);
        sum1 += __shfl_xor_sync(0xffffffffu, sum1, 2);
        l0 = l0*cr0 + sum0;
        l1 = l1*cr1 + sum1;
        #pragma unroll
        for (int dn = 0; dn < 8; dn++) {
            o[dn].x *= cr0; o[dn].y *= cr0;
            o[dn].z *= cr1; o[dn].w *= cr1;
        }

        #pragma unroll
        for (int nj = 0; nj < 8; nj++) {
            int c0 = nj*8 + 2*lc;
            *(float2*)&Ps[warp][lr][c0]     = make_float2(cvt1(s[nj].x), cvt1(s[nj].y));
            *(float2*)&Ps[warp][lr + 8][c0] = make_float2(cvt1(s[nj].z), cvt1(s[nj].w));
        }
        __syncwarp();

        #pragma unroll
        for (int ks = 0; ks < 8; ks++) {
            uint32_t pf[4];
            int k = ks*8 + lc;
            pf[0] = fu(Ps[warp][lr][k]);
            pf[1] = fu(Ps[warp][lr + 8][k]);
            pf[2] = fu(Ps[warp][lr][k + 4]);
            pf[3] = fu(Ps[warp][lr + 8][k + 4]);
            #pragma unroll
            for (int dn = 0; dn < 8; dn++) {
                float2 vv = __ldg(&vp[(ks*8 + dn)*32 + lane]);
                uint32_t bfr[2] = { fu(vv.x), fu(vv.y) };
                mma_tf32(o[dn], pf, bfr);
            }
        }
        __syncwarp();
    }

    float invl0 = 1.0f / l0, invl1 = 1.0f / l1;
    int r0 = qb*128 + warp*16 + lr;
    float* orow0 = g_o + (size_t)(b*NN + r0)*CC + h*DD;
    float* orow1 = orow0 + (size_t)8*CC;
    #pragma unroll
    for (int dn = 0; dn < 8; dn++) {
        int c = dn*8 + 2*lc;
        *(float2*)(orow0 + c) = make_float2(o[dn].x*invl0, o[dn].y*invl0);
        *(float2*)(orow1 + c) = make_float2(o[dn].z*invl1, o[dn].w*invl1);
    }
}

// ---------------------------------------------------------------------------
extern "C" void kernel_launch(void* const* d_in, const int* in_sizes, int n_in,
                              void* d_out, int out_size) {
    const float* x      = (const float*)d_in[0];
    const float* cond   = (const float*)d_in[1];
    const int*   mask   = (const int*)  d_in[2];
    const float* qkv_w  = (const float*)d_in[3];
    const float* qkv_b  = (const float*)d_in[4];
    const float* proj_w = (const float*)d_in[5];
    const float* proj_b = (const float*)d_in[6];
    const float* ada_w  = (const float*)d_in[7];
    const float* ada_b  = (const float*)d_in[8];
    const float* mlp_w1 = (const float*)d_in[9];
    const float* mlp_b1 = (const float*)d_in[10];
    const float* mlp_w2 = (const float*)d_in[11];
    const float* mlp_b2 = (const float*)d_in[12];
    float* out = (float*)d_out;

    float *p_ada, *p_h, *p_qkv, *p_o, *p_x1, *p_h3, *p_wp;
    cudaGetSymbolAddress((void**)&p_ada, g_ada);
    cudaGetSymbolAddress((void**)&p_h,   g_h);
    cudaGetSymbolAddress((void**)&p_qkv, g_qkv);
    cudaGetSymbolAddress((void**)&p_o,   g_o);
    cudaGetSymbolAddress((void**)&p_x1,  g_x1);
    cudaGetSymbolAddress((void**)&p_h3,  g_h3);
    cudaGetSymbolAddress((void**)&p_wp,  g_wp);

    // 0. weight packs (independent of data kernels; scheduler overlaps)
    wpack_kernel<<<dim3(64, 24), 256>>>(qkv_w,  p_wp + WP_QKV,  3*CC);
    wpack_kernel<<<dim3(64, 8),  256>>>(proj_w, p_wp + WP_PROJ, CC);
    wpack_kernel<<<dim3(64, 8),  256>>>(mlp_w1, p_wp + WP_MLP1, CC);
    wpack_kernel<<<dim3(64, 8),  256>>>(mlp_w2, p_wp + WP_MLP2, CC);
    // 1. adaLN vector
    ada_kernel<<<BB*12, 256>>>(cond, ada_w, ada_b);
    // 2. compact unmasked keys (exact: -10000 underflows to 0 in softmax)
    compact_kernel<<<BB, 1024>>>(mask);
    // 3. LN + modulate (MSA): sh_msa @0, sc_msa @512
    ln_mod_kernel<<<MM, 128>>>(x, 0, CC, p_h);
    // 4. qkv GEMM [8192,1536]
    gemm_tf32<0><<<dim3(12, 64), 256>>>(p_h, p_wp + WP_QKV, qkv_b, nullptr, nullptr, p_qkv, 3*CC);
    // 5. pack compacted K/V into fragment-permuted tf32 buffers
    kv_pack_kernel<<<dim3(NT64, HH, BB), 256>>>();
    // 6. attention (128 q-rows/block)
    attn_tf32<<<dim3(NN/128, HH, BB), 256>>>();
    // 7. proj GEMM + gated residual (g_msa @1024)
    gemm_tf32<2><<<dim3(4, 64), 256>>>(p_o, p_wp + WP_PROJ, proj_b, x, p_ada + 2*CC, p_x1, CC);
    // 8. LN + modulate (MLP): sh_mlp @1536, sc_mlp @2048
    ln_mod_kernel<<<MM, 128>>>(p_x1, 3*CC, 4*CC, p_h);
    // 9. mlp1 + exact GELU
    gemm_tf32<1><<<dim3(4, 64), 256>>>(p_h, p_wp + WP_MLP1, mlp_b1, nullptr, nullptr, p_h3, CC);
    // 10. mlp2 + gated residual (g_mlp @2560) -> d_out
    gemm_tf32<2><<<dim3(4, 64), 256>>>(p_h3, p_wp + WP_MLP2, mlp_b2, p_x1, p_ada + 5*CC, out, CC);
}

// round 9
// speedup vs baseline: 5.0266x; 1.3707x over previous
#include <cuda_runtime.h>
#include <cuda_bf16.h>
#include <cuda_fp16.h>
#include <math.h>
#include <stdint.h>

// Problem constants
#define BB 2
#define NN 4096
#define CC 512
#define HH 8
#define DD 64
#define MM (BB*NN)      // 8192
#define ADA6 (6*CC)     // 3072
#define NT64 (NN/64)    // 64 kv tiles max

// ---------------- scratch ----------------------------------------------------
__device__ float  g_ada[BB*ADA6];
__device__ __half g_h [MM*CC];          // LN+mod outputs (fp16)
__device__ __half g_qkv[MM*3*CC];       // qkv (fp16, q pre-scaled)
__device__ __half g_o [MM*CC];          // attention out (fp16)
__device__ float  g_x1[MM*CC];          // residual stream (fp32)
__device__ __half g_h3[MM*CC];          // gelu out (fp16)
__device__ int    g_kvidx[BB*NN];
__device__ int    g_kvcnt[BB];
// packed K/V fragments: [b][h][tile][ks(4)][nj(8)][lane(32)] uint2 (4 halves)
__device__ uint2  g_kp[BB*HH*NT64*4*8*32];
__device__ uint2  g_vp[BB*HH*NT64*4*8*32];
// packed weights (fp16 fragment-permuted): [(k16*(N/8)+nf)*32+lane] uint2
#define WPE_QKV  0
#define WPE_PROJ (32*(3*CC/8)*32)              // 196608
#define WPE_MLP1 (WPE_PROJ + 32*(CC/8)*32)     // 262144
#define WPE_MLP2 (WPE_MLP1 + 32*(CC/8)*32)     // 327680
__device__ uint2  g_wp[WPE_MLP2 + 32*(CC/8)*32];

// ---------------- helpers ----------------------------------------------------
__device__ __forceinline__ uint32_t h2u(float a, float b) {
    __half2 h = __floats2half2_rn(a, b);
    return *(uint32_t*)&h;
}
__device__ __forceinline__ void mma_f16(float4& d, const uint32_t a[4],
                                        uint32_t b0, uint32_t b1) {
    asm volatile(
        "mma.sync.aligned.m16n8k16.row.col.f32.f16.f16.f32 "
        "{%0,%1,%2,%3}, {%4,%5,%6,%7}, {%8,%9}, {%0,%1,%2,%3};\n"
        : "+f"(d.x), "+f"(d.y), "+f"(d.z), "+f"(d.w)
        : "r"(a[0]), "r"(a[1]), "r"(a[2]), "r"(a[3]), "r"(b0), "r"(b1));
}

// ---------------- ada = silu(cond) @ ada_w + ada_b ---------------------------
__global__ void ada_kernel(const float* __restrict__ cond,
                           const float* __restrict__ ada_w,
                           const float* __restrict__ ada_b) {
    int b = blockIdx.x / 12;
    int j = (blockIdx.x % 12) * 256 + threadIdx.x;
    __shared__ float sc[CC];
    for (int t = threadIdx.x; t < CC; t += 256) {
        float x = cond[b*CC + t];
        sc[t] = x / (1.0f + expf(-x));
    }
    __syncthreads();
    float acc = ada_b[j];
    #pragma unroll 8
    for (int c = 0; c < CC; c++) acc += sc[c] * ada_w[c*ADA6 + j];
    g_ada[b*ADA6 + j] = acc;
}

// ---------------- deterministic mask compaction ------------------------------
__global__ void compact_kernel(const int* __restrict__ mask) {
    int b = blockIdx.x;
    int tid = threadIdx.x;
    int base = b*NN;
    int loc[4]; int cnt = 0;
    #pragma unroll
    for (int q = 0; q < 4; q++) {
        int n = tid*4 + q;
        if (mask[base + n] == 1) loc[cnt++] = n;
    }
    __shared__ int ssum[1024];
    ssum[tid] = cnt;
    __syncthreads();
    for (int off = 1; off < 1024; off <<= 1) {
        int v = (tid >= off) ? ssum[tid - off] : 0;
        __syncthreads();
        ssum[tid] += v;
        __syncthreads();
    }
    int start = ssum[tid] - cnt;
    for (int i = 0; i < cnt; i++) g_kvidx[base + start + i] = loc[i];
    if (tid == 1023) g_kvcnt[b] = ssum[1023];
}

// ---------------- fused LayerNorm + adaLN modulate -> fp16 --------------------
__global__ void ln_mod_kernel(const float* __restrict__ X,
                              int shOff, int scOff,
                              __half* __restrict__ Hout) {
    int row = blockIdx.x;
    int b = row >> 12;
    int tid = threadIdx.x;
    const float* xr = X + (size_t)row * CC;
    float4 v = *(const float4*)(xr + tid*4);
    float s  = v.x + v.y + v.z + v.w;
    float sq = v.x*v.x + v.y*v.y + v.z*v.z + v.w*v.w;
    #pragma unroll
    for (int off = 16; off > 0; off >>= 1) {
        s  += __shfl_down_sync(0xffffffffu, s,  off);
        sq += __shfl_down_sync(0xffffffffu, sq, off);
    }
    __shared__ float ws[4], wq[4];
    if ((tid & 31) == 0) { ws[tid>>5] = s; wq[tid>>5] = sq; }
    __syncthreads();
    s  = ws[0] + ws[1] + ws[2] + ws[3];
    sq = wq[0] + wq[1] + wq[2] + wq[3];
    float mean = s * (1.0f/CC);
    float var  = sq * (1.0f/CC) - mean*mean;
    float rstd = rsqrtf(var + 1e-6f);
    int c = tid*4;
    const float* adab = g_ada + b*ADA6;
    float4 sc = *(const float4*)(adab + scOff + c);
    float4 sh = *(const float4*)(adab + shOff + c);
    float ox = (v.x - mean)*rstd*(1.0f + sc.x) + sh.x;
    float oy = (v.y - mean)*rstd*(1.0f + sc.y) + sh.y;
    float oz = (v.z - mean)*rstd*(1.0f + sc.z) + sh.z;
    float ow = (v.w - mean)*rstd*(1.0f + sc.w) + sh.w;
    uint2 u = make_uint2(h2u(ox, oy), h2u(oz, ow));
    *(uint2*)&Hout[(size_t)row*CC + c] = u;
}

// ---------------- weight pack: W[512,N] -> fp16 fragment-permuted -------------
// out[((k16*(N/8) + nf)*32 + lane)] = { half2(W[k0][n],W[k0+1][n]),
//                                       half2(W[k0+8][n],W[k0+9][n]) }
// with k0 = k16*16 + 2*(lane&3), n = nf*8 + (lane>>2).
// grid (32, N/64), 256 threads.
__global__ void wpack_f16(const float* __restrict__ W, uint2* __restrict__ Wp, int N) {
    __shared__ float ws[16][65];
    int k16 = blockIdx.x, nb = blockIdx.y;
    int tid = threadIdx.x;
    for (int i = tid; i < 16*64; i += 256) {
        int k = i >> 6, n = i & 63;
        ws[k][n] = W[(size_t)(k16*16 + k)*N + nb*64 + n];
    }
    __syncthreads();
    int nf = tid >> 5, lane = tid & 31;
    int lr = lane >> 2, lc = lane & 3;
    int n = nf*8 + lr, k0 = 2*lc;
    uint2 u;
    u.x = h2u(ws[k0][n],     ws[k0+1][n]);
    u.y = h2u(ws[k0+8][n],   ws[k0+9][n]);
    Wp[((size_t)k16*(N/8) + nb*8 + nf)*32 + lane] = u;
}

// ---------------- FP16 tensor-core GEMM ---------------------------------------
// C[M,N] = A[M,512]@W + epi. Block 128x128, 8 warps (2x4), Kt=32 double-buffered.
// EPI 0: +bias, scale q cols, ->half   EPI 1: gelu(+bias) ->half
// EPI 2: resid + gate*(+bias) ->float
template<int EPI>
__global__ __launch_bounds__(256, 2)
void gemm_f16(const __half* __restrict__ A, const uint2* __restrict__ Wp,
              const float* __restrict__ bias,
              const float* __restrict__ resid,
              const float* __restrict__ gate,
              void* __restrict__ CoutV, int N) {
    __shared__ uint4 Asp[2][512];     // 16 regions x 32 lanes x 16B
    int tid  = threadIdx.x;
    int warp = tid >> 5, lane = tid & 31;
    int wg = warp >> 2, wn4 = warp & 3;
    int m0 = blockIdx.y*128, n0 = blockIdx.x*128;

    // loader slot mapping (2 slots/thread)
    int s0 = tid, s1 = tid + 256;
    auto loadA = [&](int kt, uint4& o0, uint4& o1) {
        #pragma unroll
        for (int j = 0; j < 2; j++) {
            int s = j ? s1 : s0;
            int rg = s >> 5, ln = s & 31;
            int mg = rg >> 1, ksl = rg & 1;
            int llr = ln >> 2, llc = ln & 3;
            int r0 = m0 + mg*16 + llr, r1 = r0 + 8;
            int ck = kt*32 + ksl*16 + 2*llc;
            uint4 v;
            v.x = *(const uint32_t*)&A[(size_t)r0*CC + ck];
            v.y = *(const uint32_t*)&A[(size_t)r1*CC + ck];
            v.z = *(const uint32_t*)&A[(size_t)r0*CC + ck + 8];
            v.w = *(const uint32_t*)&A[(size_t)r1*CC + ck + 8];
            if (j) o1 = v; else o0 = v;
        }
    };

    const uint2* wp0 = Wp + ((size_t)(n0>>3) + wn4*4)*32 + lane;
    size_t wstride = (size_t)(N >> 3) * 32;   // per k16 step

    float4 acc[4][4];
    #pragma unroll
    for (int i = 0; i < 4; i++)
        #pragma unroll
        for (int j = 0; j < 4; j++) acc[i][j] = make_float4(0.f,0.f,0.f,0.f);

    uint4 pa0, pa1;
    loadA(0, pa0, pa1);
    Asp[0][s0] = pa0; Asp[0][s1] = pa1;
    uint2 bf[2][2][4];
    #pragma unroll
    for (int ks = 0; ks < 2; ks++)
        #pragma unroll
        for (int nj = 0; nj < 4; nj++)
            bf[0][ks][nj] = __ldg(wp0 + (size_t)ks*wstride + (size_t)nj*32);
    __syncthreads();

    for (int kt = 0; kt < 16; kt++) {
        int cur = kt & 1;
        if (kt < 15) {
            loadA(kt + 1, pa0, pa1);
            #pragma unroll
            for (int ks = 0; ks < 2; ks++)
                #pragma unroll
                for (int nj = 0; nj < 4; nj++)
                    bf[cur^1][ks][nj] =
                        __ldg(wp0 + ((size_t)(kt+1)*2 + ks)*wstride + (size_t)nj*32);
        }
        #pragma unroll
        for (int ks = 0; ks < 2; ks++) {
            #pragma unroll
            for (int mi = 0; mi < 4; mi++) {
                uint4 af4 = Asp[cur][(((wg*4 + mi)*2 + ks) << 5) + lane];
                uint32_t afr[4] = { af4.x, af4.y, af4.z, af4.w };
                #pragma unroll
                for (int nj = 0; nj < 4; nj++)
                    mma_f16(acc[mi][nj], afr, bf[cur][ks][nj].x, bf[cur][ks][nj].y);
            }
        }
        if (kt < 15) {
            Asp[cur^1][s0] = pa0;
            Asp[cur^1][s1] = pa1;
        }
        __syncthreads();
    }

    // ---- epilogue ----
    int wm = wg*64, wn = wn4*32;
    int lr = lane >> 2, lc = lane & 3;
    #pragma unroll
    for (int mi = 0; mi < 4; mi++) {
        int r0 = m0 + wm + mi*16 + lr;
        int r1 = r0 + 8;
        int b0i = r0 >> 12, b1i = r1 >> 12;
        #pragma unroll
        for (int nj = 0; nj < 4; nj++) {
            int c = n0 + wn + nj*8 + 2*lc;
            float4 d = acc[mi][nj];
            float bx = bias[c], by = bias[c+1];
            float vx = d.x + bx, vy = d.y + by;
            float wx = d.z + bx, wy = d.w + by;
            if (EPI == 0) {
                float qs = (c < CC) ? 0.125f : 1.0f;   // fold D^-0.5 into q
                vx *= qs; vy *= qs; wx *= qs; wy *= qs;
                __half* Ch = (__half*)CoutV;
                *(uint32_t*)&Ch[(size_t)r0*N + c] = h2u(vx, vy);
                *(uint32_t*)&Ch[(size_t)r1*N + c] = h2u(wx, wy);
            } else if (EPI == 1) {
                vx = 0.5f*vx*(1.0f + erff(vx*0.70710678118654752f));
                vy = 0.5f*vy*(1.0f + erff(vy*0.70710678118654752f));
                wx = 0.5f*wx*(1.0f + erff(wx*0.70710678118654752f));
                wy = 0.5f*wy*(1.0f + erff(wy*0.70710678118654752f));
                __half* Ch = (__half*)CoutV;
                *(uint32_t*)&Ch[(size_t)r0*N + c] = h2u(vx, vy);
                *(uint32_t*)&Ch[(size_t)r1*N + c] = h2u(wx, wy);
            } else {
                float gx0 = gate[(size_t)b0i*ADA6 + c], gy0 = gate[(size_t)b0i*ADA6 + c + 1];
                float gx1 = gate[(size_t)b1i*ADA6 + c], gy1 = gate[(size_t)b1i*ADA6 + c + 1];
                float* Cf = (float*)CoutV;
                *(float2*)&Cf[(size_t)r0*N + c] =
                    make_float2(resid[(size_t)r0*CC + c]     + gx0*vx,
                                resid[(size_t)r0*CC + c + 1] + gy0*vy);
                *(float2*)&Cf[(size_t)r1*N + c] =
                    make_float2(resid[(size_t)r1*CC + c]     + gx1*wx,
                                resid[(size_t)r1*CC + c + 1] + gy1*wy);
            }
        }
    }
}

// ---------------- KV pack: gather fp16 + fragment-permute ---------------------
__global__ __launch_bounds__(256)
void kv_pack_kernel() {
    __shared__ __half Ks[64][72];
    __shared__ __half Vs[64][72];
    int t = blockIdx.x, h = blockIdx.y, b = blockIdx.z;
    int nk = g_kvcnt[b];
    int ntiles = (nk + 63) >> 6;
    if (t >= ntiles) return;
    int tid = threadIdx.x;

    {
        int row = tid >> 2, q4 = tid & 3;   // 16 halves (32B) per thread
        int slot = t*64 + row;
        if (slot < nk) {
            int n = g_kvidx[b*NN + slot];
            const __half* base = g_qkv + (size_t)(b*NN + n)*(3*CC) + h*DD + q4*16;
            *(uint4*)&Ks[row][q4*16]     = *(const uint4*)(base + CC);
            *(uint4*)&Ks[row][q4*16 + 8] = *(const uint4*)(base + CC + 8);
            *(uint4*)&Vs[row][q4*16]     = *(const uint4*)(base + 2*CC);
            *(uint4*)&Vs[row][q4*16 + 8] = *(const uint4*)(base + 2*CC + 8);
        } else {
            uint4 z = make_uint4(0,0,0,0);
            *(uint4*)&Ks[row][q4*16] = z; *(uint4*)&Ks[row][q4*16 + 8] = z;
            *(uint4*)&Vs[row][q4*16] = z; *(uint4*)&Vs[row][q4*16 + 8] = z;
        }
    }
    __syncthreads();

    int g = tid >> 5, lane = tid & 31;
    int lr = lane >> 2, lc = lane & 3;
    size_t tb = ((size_t)(b*HH + h)*NT64 + t) * 1024;
    #pragma unroll
    for (int ks = 0; ks < 4; ks++) {
        int k0 = ks*16 + 2*lc;
        // K frag (n = key, k = d): contiguous within a K row
        int n = g*8 + lr;
        uint2 ku;
        ku.x = *(const uint32_t*)&Ks[n][k0];
        ku.y = *(const uint32_t*)&Ks[n][k0 + 8];
        g_kp[tb + (ks*8 + g)*32 + lane] = ku;
        // V frag (k = key, n = d): cross-row
        int nd = g*8 + lr;
        uint2 vu;
        vu.x = h2u(__half2float(Vs[k0][nd]),     __half2float(Vs[k0+1][nd]));
        vu.y = h2u(__half2float(Vs[k0+8][nd]),   __half2float(Vs[k0+9][nd]));
        g_vp[tb + (ks*8 + g)*32 + lane] = vu;
    }
}

// ---------------- FP16 flash attention ----------------------------------------
__global__ __launch_bounds__(256, 1)
void attn_f16() {
    __shared__ uint32_t Ps[8][16][36];   // per-warp P (half2 units), padded

    int qb = blockIdx.x, h = blockIdx.y, b = blockIdx.z;
    int tid = threadIdx.x;
    int warp = tid >> 5, lane = tid & 31;
    int lr = lane >> 2, lc = lane & 3;

    // ---- persistent Q fragments (q pre-scaled in qkv epilogue) ----
    uint32_t qf[4][4];
    {
        const __half* q0 = g_qkv + (size_t)(b*NN + qb*128 + warp*16 + lr)*(3*CC) + h*DD;
        const __half* q1 = q0 + (size_t)8*(3*CC);
        #pragma unroll
        for (int ks = 0; ks < 4; ks++) {
            int k0 = ks*16 + 2*lc;
            qf[ks][0] = *(const uint32_t*)&q0[k0];
            qf[ks][1] = *(const uint32_t*)&q1[k0];
            qf[ks][2] = *(const uint32_t*)&q0[k0 + 8];
            qf[ks][3] = *(const uint32_t*)&q1[k0 + 8];
        }
    }

    float4 o[8];
    #pragma unroll
    for (int dn = 0; dn < 8; dn++) o[dn] = make_float4(0.f,0.f,0.f,0.f);
    float m0 = -INFINITY, m1 = -INFINITY, l0 = 0.f, l1 = 0.f;

    int nk = g_kvcnt[b];
    int ntiles = (nk + 63) >> 6;
    const uint2* kpb = g_kp + ((size_t)(b*HH + h))*NT64*1024;
    const uint2* vpb = g_vp + ((size_t)(b*HH + h))*NT64*1024;

    for (int t = 0; t < ntiles; t++) {
        const uint2* kp = kpb + (size_t)t*1024;
        const uint2* vp = vpb + (size_t)t*1024;

        // ---- S = Q K^T : one LDG.64 + one mma per (ks,nj) ----
        float4 s[8];
        #pragma unroll
        for (int nj = 0; nj < 8; nj++) s[nj] = make_float4(0.f,0.f,0.f,0.f);
        #pragma unroll
        for (int ks = 0; ks < 4; ks++) {
            #pragma unroll
            for (int nj = 0; nj < 8; nj++) {
                uint2 kv = __ldg(&kp[(ks*8 + nj)*32 + lane]);
                mma_f16(s[nj], qf[ks], kv.x, kv.y);
            }
        }

        int valid = nk - t*64; if (valid > 64) valid = 64;
        #pragma unroll
        for (int nj = 0; nj < 8; nj++) {
            int c0 = nj*8 + 2*lc;
            if (c0     >= valid) { s[nj].x = -1e30f; s[nj].z = -1e30f; }
            if (c0 + 1 >= valid) { s[nj].y = -1e30f; s[nj].w = -1e30f; }
        }

        // ---- online softmax ----
        float mx0 = -1e30f, mx1 = -1e30f;
        #pragma unroll
        for (int nj = 0; nj < 8; nj++) {
            mx0 = fmaxf(mx0, fmaxf(s[nj].x, s[nj].y));
            mx1 = fmaxf(mx1, fmaxf(s[nj].z, s[nj].w));
        }
        mx0 = fmaxf(mx0, __shfl_xor_sync(0xffffffffu, mx0, 1));
        mx0 = fmaxf(mx0, __shfl_xor_sync(0xffffffffu, mx0, 2));
        mx1 = fmaxf(mx1, __shfl_xor_sync(0xffffffffu, mx1, 1));
        mx1 = fmaxf(mx1, __shfl_xor_sync(0xffffffffu, mx1, 2));
        float mn0 = fmaxf(m0, mx0), mn1 = fmaxf(m1, mx1);
        float cr0 = __expf(m0 - mn0), cr1 = __expf(m1 - mn1);
        m0 = mn0; m1 = mn1;
        float sum0 = 0.f, sum1 = 0.f;
        #pragma unroll
        for (int nj = 0; nj < 8; nj++) {
            s[nj].x = __expf(s[nj].x - mn0); sum0 += s[nj].x;
            s[nj].y = __expf(s[nj].y - mn0); sum0 += s[nj].y;
            s[nj].z = __expf(s[nj].z - mn1); sum1 += s[nj].z;
            s[nj].w = __expf(s[nj].w - mn1); sum1 += s[nj].w;
        }
        sum0 += __shfl_xor_sync(0xffffffffu, sum0, 1);
        sum0 += __shfl_xor_sync(0xffffffffu, sum0, 2);
        sum1 += __shfl_xor_sync(0xffffffffu, sum1, 1);
        sum1 += __shfl_xor_sync(0xffffffffu, sum1, 2);
        l0 = l0*cr0 + sum0;
        l1 = l1*cr1 + sum1;
        #pragma unroll
        for (int dn = 0; dn < 8; dn++) {
            o[dn].x *= cr0; o[dn].y *= cr0;
            o[dn].z *= cr1; o[dn].w *= cr1;
        }

        // ---- P -> warp-private smem (half2) ----
        #pragma unroll
        for (int nj = 0; nj < 8; nj++) {
            Ps[warp][lr][nj*4 + lc]     = h2u(s[nj].x, s[nj].y);
            Ps[warp][lr + 8][nj*4 + lc] = h2u(s[nj].z, s[nj].w);
        }
        __syncwarp();

        // ---- O += P @ V ----
        #pragma unroll
        for (int ks = 0; ks < 4; ks++) {
            uint32_t pf[4];
            pf[0] = Ps[warp][lr][ks*8 + lc];
            pf[1] = Ps[warp][lr + 8][ks*8 + lc];
            pf[2] = Ps[warp][lr][ks*8 + lc + 4];
            pf[3] = Ps[warp][lr + 8][ks*8 + lc + 4];
            #pragma unroll
            for (int dn = 0; dn < 8; dn++) {
                uint2 vv = __ldg(&vp[(ks*8 + dn)*32 + lane]);
                mma_f16(o[dn], pf, vv.x, vv.y);
            }
        }
        __syncwarp();
    }

    // ---- epilogue: normalize, store fp16 ----
    float invl0 = 1.0f / l0, invl1 = 1.0f / l1;
    int r0 = qb*128 + warp*16 + lr;
    __half* orow0 = g_o + (size_t)(b*NN + r0)*CC + h*DD;
    __half* orow1 = orow0 + (size_t)8*CC;
    #pragma unroll
    for (int dn = 0; dn < 8; dn++) {
        int c = dn*8 + 2*lc;
        *(uint32_t*)&orow0[c] = h2u(o[dn].x*invl0, o[dn].y*invl0);
        *(uint32_t*)&orow1[c] = h2u(o[dn].z*invl1, o[dn].w*invl1);
    }
}

// ---------------------------------------------------------------------------
extern "C" void kernel_launch(void* const* d_in, const int* in_sizes, int n_in,
                              void* d_out, int out_size) {
    const float* x      = (const float*)d_in[0];
    const float* cond   = (const float*)d_in[1];
    const int*   mask   = (const int*)  d_in[2];
    const float* qkv_w  = (const float*)d_in[3];
    const float* qkv_b  = (const float*)d_in[4];
    const float* proj_w = (const float*)d_in[5];
    const float* proj_b = (const float*)d_in[6];
    const float* ada_w  = (const float*)d_in[7];
    const float* ada_b  = (const float*)d_in[8];
    const float* mlp_w1 = (const float*)d_in[9];
    const float* mlp_b1 = (const float*)d_in[10];
    const float* mlp_w2 = (const float*)d_in[11];
    const float* mlp_b2 = (const float*)d_in[12];
    float* out = (float*)d_out;

    float *p_ada, *p_x1;
    __half *p_h, *p_qkv, *p_o, *p_h3;
    uint2 *p_wp;
    cudaGetSymbolAddress((void**)&p_ada, g_ada);
    cudaGetSymbolAddress((void**)&p_h,   g_h);
    cudaGetSymbolAddress((void**)&p_qkv, g_qkv);
    cudaGetSymbolAddress((void**)&p_o,   g_o);
    cudaGetSymbolAddress((void**)&p_x1,  g_x1);
    cudaGetSymbolAddress((void**)&p_h3,  g_h3);
    cudaGetSymbolAddress((void**)&p_wp,  g_wp);

    // 0. weight packs (fp16 fragment-permuted)
    wpack_f16<<<dim3(32, 24), 256>>>(qkv_w,  p_wp + WPE_QKV,  3*CC);
    wpack_f16<<<dim3(32, 8),  256>>>(proj_w, p_wp + WPE_PROJ, CC);
    wpack_f16<<<dim3(32, 8),  256>>>(mlp_w1, p_wp + WPE_MLP1, CC);
    wpack_f16<<<dim3(32, 8),  256>>>(mlp_w2, p_wp + WPE_MLP2, CC);
    // 1. adaLN vector
    ada_kernel<<<BB*12, 256>>>(cond, ada_w, ada_b);
    // 2. compact unmasked keys (exact: -10000 underflows to 0 in softmax)
    compact_kernel<<<BB, 1024>>>(mask);
    // 3. LN + modulate (MSA): sh_msa @0, sc_msa @512
    ln_mod_kernel<<<MM, 128>>>(x, 0, CC, p_h);
    // 4. qkv GEMM [8192,1536] -> fp16, q pre-scaled
    gemm_f16<0><<<dim3(12, 64), 256>>>(p_h, p_wp + WPE_QKV, qkv_b, nullptr, nullptr, p_qkv, 3*CC);
    // 5. pack compacted K/V
    kv_pack_kernel<<<dim3(NT64, HH, BB), 256>>>();
    // 6. attention
    attn_f16<<<dim3(NN/128, HH, BB), 256>>>();
    // 7. proj GEMM + gated residual (g_msa @1024) -> fp32 x1
    gemm_f16<2><<<dim3(4, 64), 256>>>(p_o, p_wp + WPE_PROJ, proj_b, x, p_ada + 2*CC, p_x1, CC);
    // 8. LN + modulate (MLP): sh_mlp @1536, sc_mlp @2048
    ln_mod_kernel<<<MM, 128>>>(p_x1, 3*CC, 4*CC, p_h);
    // 9. mlp1 + exact GELU -> fp16
    gemm_f16<1><<<dim3(4, 64), 256>>>(p_h, p_wp + WPE_MLP1, mlp_b1, nullptr, nullptr, p_h3, CC);
    // 10. mlp2 + gated residual (g_mlp @2560) -> d_out (fp32)
    gemm_f16<2><<<dim3(4, 64), 256>>>(p_h3, p_wp + WPE_MLP2, mlp_b2, p_x1, p_ada + 5*CC, out, CC);
}

// round 11
// speedup vs baseline: 5.3990x; 1.0741x over previous
#include <cuda_runtime.h>
#include <cuda_bf16.h>
#include <cuda_fp16.h>
#include <math.h>
#include <stdint.h>

// Problem constants
#define BB 2
#define NN 4096
#define CC 512
#define HH 8
#define DD 64
#define MM (BB*NN)      // 8192
#define ADA6 (6*CC)     // 3072
#define NT64 (NN/64)    // 64 kv tiles max

// ---------------- scratch ----------------------------------------------------
__device__ float  g_ada[BB*ADA6];
__device__ __half g_h [MM*CC];          // LN+mod outputs (fp16)
__device__ __half g_qkv[MM*3*CC];       // qkv (fp16, q pre-scaled)
__device__ __half g_o [MM*CC];          // attention out (fp16)
__device__ float  g_x1[MM*CC];          // residual stream (fp32)
__device__ __half g_h3[MM*CC];          // gelu out (fp16)
__device__ int    g_kvidx[BB*NN];
__device__ int    g_kvcnt[BB];
// packed K/V fragment PAIRS: [b][h][tile][ks(4)][njp(4)][lane(32)] uint4
__device__ uint4  g_kp[BB*HH*NT64*4*4*32];
__device__ uint4  g_vp[BB*HH*NT64*4*4*32];
// packed weights (fp16 fragment pairs): [(k16*(N/16)+nfp)*32+lane] uint4
#define WP4_QKV  0
#define WP4_PROJ 98304
#define WP4_MLP1 131072
#define WP4_MLP2 163840
__device__ uint4  g_wp[196608];

// ---------------- helpers ----------------------------------------------------
__device__ __forceinline__ uint32_t h2u(float a, float b) {
    __half2 h = __floats2half2_rn(a, b);
    return *(uint32_t*)&h;
}
__device__ __forceinline__ void mma_f16(float4& d, const uint32_t a[4],
                                        uint32_t b0, uint32_t b1) {
    asm volatile(
        "mma.sync.aligned.m16n8k16.row.col.f32.f16.f16.f32 "
        "{%0,%1,%2,%3}, {%4,%5,%6,%7}, {%8,%9}, {%0,%1,%2,%3};\n"
        : "+f"(d.x), "+f"(d.y), "+f"(d.z), "+f"(d.w)
        : "r"(a[0]), "r"(a[1]), "r"(a[2]), "r"(a[3]), "r"(b0), "r"(b1));
}

// ---------------- ada = silu(cond) @ ada_w + ada_b ---------------------------
__global__ void ada_kernel(const float* __restrict__ cond,
                           const float* __restrict__ ada_w,
                           const float* __restrict__ ada_b) {
    int b = blockIdx.x / 12;
    int j = (blockIdx.x % 12) * 256 + threadIdx.x;
    __shared__ float sc[CC];
    for (int t = threadIdx.x; t < CC; t += 256) {
        float x = cond[b*CC + t];
        sc[t] = x / (1.0f + expf(-x));
    }
    __syncthreads();
    float acc = ada_b[j];
    #pragma unroll 8
    for (int c = 0; c < CC; c++) acc += sc[c] * ada_w[c*ADA6 + j];
    g_ada[b*ADA6 + j] = acc;
}

// ---------------- deterministic mask compaction ------------------------------
__global__ void compact_kernel(const int* __restrict__ mask) {
    int b = blockIdx.x;
    int tid = threadIdx.x;
    int base = b*NN;
    int loc[4]; int cnt = 0;
    #pragma unroll
    for (int q = 0; q < 4; q++) {
        int n = tid*4 + q;
        if (mask[base + n] == 1) loc[cnt++] = n;
    }
    __shared__ int ssum[1024];
    ssum[tid] = cnt;
    __syncthreads();
    for (int off = 1; off < 1024; off <<= 1) {
        int v = (tid >= off) ? ssum[tid - off] : 0;
        __syncthreads();
        ssum[tid] += v;
        __syncthreads();
    }
    int start = ssum[tid] - cnt;
    for (int i = 0; i < cnt; i++) g_kvidx[base + start + i] = loc[i];
    if (tid == 1023) g_kvcnt[b] = ssum[1023];
}

// ---------------- fused LayerNorm + adaLN modulate -> fp16 --------------------
__global__ void ln_mod_kernel(const float* __restrict__ X,
                              int shOff, int scOff,
                              __half* __restrict__ Hout) {
    int row = blockIdx.x;
    int b = row >> 12;
    int tid = threadIdx.x;
    const float* xr = X + (size_t)row * CC;
    float4 v = *(const float4*)(xr + tid*4);
    float s  = v.x + v.y + v.z + v.w;
    float sq = v.x*v.x + v.y*v.y + v.z*v.z + v.w*v.w;
    #pragma unroll
    for (int off = 16; off > 0; off >>= 1) {
        s  += __shfl_down_sync(0xffffffffu, s,  off);
        sq += __shfl_down_sync(0xffffffffu, sq, off);
    }
    __shared__ float ws[4], wq[4];
    if ((tid & 31) == 0) { ws[tid>>5] = s; wq[tid>>5] = sq; }
    __syncthreads();
    s  = ws[0] + ws[1] + ws[2] + ws[3];
    sq = wq[0] + wq[1] + wq[2] + wq[3];
    float mean = s * (1.0f/CC);
    float var  = sq * (1.0f/CC) - mean*mean;
    float rstd = rsqrtf(var + 1e-6f);
    int c = tid*4;
    const float* adab = g_ada + b*ADA6;
    float4 sc = *(const float4*)(adab + scOff + c);
    float4 sh = *(const float4*)(adab + shOff + c);
    float ox = (v.x - mean)*rstd*(1.0f + sc.x) + sh.x;
    float oy = (v.y - mean)*rstd*(1.0f + sc.y) + sh.y;
    float oz = (v.z - mean)*rstd*(1.0f + sc.z) + sh.z;
    float ow = (v.w - mean)*rstd*(1.0f + sc.w) + sh.w;
    uint2 u = make_uint2(h2u(ox, oy), h2u(oz, ow));
    *(uint2*)&Hout[(size_t)row*CC + c] = u;
}

// ---------------- weight pack (all 4 weights, one launch) ---------------------
// out[((k16*(N/16) + nfp)*32 + lane)] = uint4{ frag(nf=2nfp), frag(nf=2nfp+1) }
// frag(nf) = { half2(W[k0][n],W[k0+1][n]), half2(W[k0+8][n],W[k0+9][n]) },
// k0 = k16*16 + 2*(lane&3), n = nf*8 + (lane>>2).  grid (32, 48).
__global__ void wpack_f16(const float* __restrict__ W0, const float* __restrict__ W1,
                          const float* __restrict__ W2, const float* __restrict__ W3) {
    __shared__ float ws[16][65];
    int k16 = blockIdx.x, nb = blockIdx.y;
    const float* W; int N; size_t off; int nbl;
    if (nb < 24)      { W = W0; N = 3*CC; off = WP4_QKV;  nbl = nb; }
    else if (nb < 32) { W = W1; N = CC;   off = WP4_PROJ; nbl = nb - 24; }
    else if (nb < 40) { W = W2; N = CC;   off = WP4_MLP1; nbl = nb - 32; }
    else              { W = W3; N = CC;   off = WP4_MLP2; nbl = nb - 40; }
    int tid = threadIdx.x;
    for (int i = tid; i < 16*64; i += 256) {
        int k = i >> 6, n = i & 63;
        ws[k][n] = W[(size_t)(k16*16 + k)*N + nbl*64 + n];
    }
    __syncthreads();
    if (tid < 128) {
        int nfp = tid >> 5, lane = tid & 31;
        int lr = lane >> 2, k0 = 2*(lane & 3);
        int n0 = nfp*16 + lr, n1 = n0 + 8;
        uint4 u;
        u.x = h2u(ws[k0][n0],   ws[k0+1][n0]);
        u.y = h2u(ws[k0+8][n0], ws[k0+9][n0]);
        u.z = h2u(ws[k0][n1],   ws[k0+1][n1]);
        u.w = h2u(ws[k0+8][n1], ws[k0+9][n1]);
        g_wp[off + ((size_t)k16*(N>>4) + nbl*4 + nfp)*32 + lane] = u;
    }
}

// ---------------- FP16 tensor-core GEMM ---------------------------------------
// C[M,N] = A[M,512]@W + epi. Block 128x128, 8 warps (2x4), Kt=32 double-buffered.
// B fragment pairs straight from packed gmem (one LDG.128 -> two mmas).
template<int EPI>
__global__ __launch_bounds__(256, 2)
void gemm_f16(const __half* __restrict__ A, const uint4* __restrict__ Wp,
              const float* __restrict__ bias,
              const float* __restrict__ resid,
              const float* __restrict__ gate,
              void* __restrict__ CoutV, int N) {
    __shared__ uint4 Asp[2][512];     // 16 regions x 32 lanes x 16B
    int tid  = threadIdx.x;
    int warp = tid >> 5, lane = tid & 31;
    int wg = warp >> 2, wn4 = warp & 3;
    int m0 = blockIdx.y*128, n0 = blockIdx.x*128;

    int s0 = tid, s1 = tid + 256;
    auto loadA = [&](int kt, uint4& o0, uint4& o1) {
        #pragma unroll
        for (int j = 0; j < 2; j++) {
            int s = j ? s1 : s0;
            int rg = s >> 5, ln = s & 31;
            int mg = rg >> 1, ksl = rg & 1;
            int llr = ln >> 2, llc = ln & 3;
            int r0 = m0 + mg*16 + llr, r1 = r0 + 8;
            int ck = kt*32 + ksl*16 + 2*llc;
            uint4 v;
            v.x = *(const uint32_t*)&A[(size_t)r0*CC + ck];
            v.y = *(const uint32_t*)&A[(size_t)r1*CC + ck];
            v.z = *(const uint32_t*)&A[(size_t)r0*CC + ck + 8];
            v.w = *(const uint32_t*)&A[(size_t)r1*CC + ck + 8];
            if (j) o1 = v; else o0 = v;
        }
    };

    const uint4* wp0 = Wp + ((size_t)(n0 >> 4) + wn4*2)*32 + lane;
    size_t wstride = (size_t)(N >> 4) * 32;   // per k16 step (uint4)

    float4 acc[4][4];
    #pragma unroll
    for (int i = 0; i < 4; i++)
        #pragma unroll
        for (int j = 0; j < 4; j++) acc[i][j] = make_float4(0.f,0.f,0.f,0.f);

    uint4 pa0, pa1;
    loadA(0, pa0, pa1);
    Asp[0][s0] = pa0; Asp[0][s1] = pa1;
    uint4 bf[2][2][2];   // [buf][ks][njp]
    #pragma unroll
    for (int ks = 0; ks < 2; ks++)
        #pragma unroll
        for (int p = 0; p < 2; p++)
            bf[0][ks][p] = __ldg(wp0 + (size_t)ks*wstride + (size_t)p*32);
    __syncthreads();

    for (int kt = 0; kt < 16; kt++) {
        int cur = kt & 1;
        if (kt < 15) {
            loadA(kt + 1, pa0, pa1);
            #pragma unroll
            for (int ks = 0; ks < 2; ks++)
                #pragma unroll
                for (int p = 0; p < 2; p++)
                    bf[cur^1][ks][p] =
                        __ldg(wp0 + ((size_t)(kt+1)*2 + ks)*wstride + (size_t)p*32);
        }
        #pragma unroll
        for (int ks = 0; ks < 2; ks++) {
            #pragma unroll
            for (int mi = 0; mi < 4; mi++) {
                uint4 af4 = Asp[cur][(((wg*4 + mi)*2 + ks) << 5) + lane];
                uint32_t afr[4] = { af4.x, af4.y, af4.z, af4.w };
                #pragma unroll
                for (int p = 0; p < 2; p++) {
                    mma_f16(acc[mi][2*p],   afr, bf[cur][ks][p].x, bf[cur][ks][p].y);
                    mma_f16(acc[mi][2*p+1], afr, bf[cur][ks][p].z, bf[cur][ks][p].w);
                }
            }
        }
        if (kt < 15) {
            Asp[cur^1][s0] = pa0;
            Asp[cur^1][s1] = pa1;
        }
        __syncthreads();
    }

    // ---- epilogue ----
    int wm = wg*64, wn = wn4*32;
    int lr = lane >> 2, lc = lane & 3;
    #pragma unroll
    for (int mi = 0; mi < 4; mi++) {
        int r0 = m0 + wm + mi*16 + lr;
        int r1 = r0 + 8;
        int b0i = r0 >> 12, b1i = r1 >> 12;
        #pragma unroll
        for (int nj = 0; nj < 4; nj++) {
            int c = n0 + wn + nj*8 + 2*lc;
            float4 d = acc[mi][nj];
            float bx = bias[c], by = bias[c+1];
            float vx = d.x + bx, vy = d.y + by;
            float wx = d.z + bx, wy = d.w + by;
            if (EPI == 0) {
                float qs = (c < CC) ? 0.125f : 1.0f;   // fold D^-0.5 into q
                vx *= qs; vy *= qs; wx *= qs; wy *= qs;
                __half* Ch = (__half*)CoutV;
                *(uint32_t*)&Ch[(size_t)r0*N + c] = h2u(vx, vy);
                *(uint32_t*)&Ch[(size_t)r1*N + c] = h2u(wx, wy);
            } else if (EPI == 1) {
                vx = 0.5f*vx*(1.0f + erff(vx*0.70710678118654752f));
                vy = 0.5f*vy*(1.0f + erff(vy*0.70710678118654752f));
                wx = 0.5f*wx*(1.0f + erff(wx*0.70710678118654752f));
                wy = 0.5f*wy*(1.0f + erff(wy*0.70710678118654752f));
                __half* Ch = (__half*)CoutV;
                *(uint32_t*)&Ch[(size_t)r0*N + c] = h2u(vx, vy);
                *(uint32_t*)&Ch[(size_t)r1*N + c] = h2u(wx, wy);
            } else {
                float gx0 = gate[(size_t)b0i*ADA6 + c], gy0 = gate[(size_t)b0i*ADA6 + c + 1];
                float gx1 = gate[(size_t)b1i*ADA6 + c], gy1 = gate[(size_t)b1i*ADA6 + c + 1];
                float* Cf = (float*)CoutV;
                *(float2*)&Cf[(size_t)r0*N + c] =
                    make_float2(resid[(size_t)r0*CC + c]     + gx0*vx,
                                resid[(size_t)r0*CC + c + 1] + gy0*vy);
                *(float2*)&Cf[(size_t)r1*N + c] =
                    make_float2(resid[(size_t)r1*CC + c]     + gx1*wx,
                                resid[(size_t)r1*CC + c + 1] + gy1*wy);
            }
        }
    }
}

// ---------------- KV pack: gather fp16 + fragment-pair permute ----------------
__global__ __launch_bounds__(256)
void kv_pack_kernel() {
    __shared__ __half Ks[64][72];
    __shared__ __half Vs[64][72];
    int t = blockIdx.x, h = blockIdx.y, b = blockIdx.z;
    int nk = g_kvcnt[b];
    int ntiles = (nk + 63) >> 6;
    if (t >= ntiles) return;
    int tid = threadIdx.x;

    {
        int row = tid >> 2, q4 = tid & 3;
        int slot = t*64 + row;
        if (slot < nk) {
            int n = g_kvidx[b*NN + slot];
            const __half* base = g_qkv + (size_t)(b*NN + n)*(3*CC) + h*DD + q4*16;
            *(uint4*)&Ks[row][q4*16]     = *(const uint4*)(base + CC);
            *(uint4*)&Ks[row][q4*16 + 8] = *(const uint4*)(base + CC + 8);
            *(uint4*)&Vs[row][q4*16]     = *(const uint4*)(base + 2*CC);
            *(uint4*)&Vs[row][q4*16 + 8] = *(const uint4*)(base + 2*CC + 8);
        } else {
            uint4 z = make_uint4(0,0,0,0);
            *(uint4*)&Ks[row][q4*16] = z; *(uint4*)&Ks[row][q4*16 + 8] = z;
            *(uint4*)&Vs[row][q4*16] = z; *(uint4*)&Vs[row][q4*16 + 8] = z;
        }
    }
    __syncthreads();

    int g = tid >> 5, lane = tid & 31;
    int lr = lane >> 2, lc = lane & 3;
    size_t tb = ((size_t)(b*HH + h)*NT64 + t) * 512;
    if (g < 4) {
        // K pairs: njp = g -> key rows g*16+lr and +8
        int n0 = g*16 + lr, n1 = n0 + 8;
        #pragma unroll
        for (int ks = 0; ks < 4; ks++) {
            int k0 = ks*16 + 2*lc;
            uint4 u;
            u.x = *(const uint32_t*)&Ks[n0][k0];
            u.y = *(const uint32_t*)&Ks[n0][k0 + 8];
            u.z = *(const uint32_t*)&Ks[n1][k0];
            u.w = *(const uint32_t*)&Ks[n1][k0 + 8];
            g_kp[tb + (ks*4 + g)*32 + lane] = u;
        }
    } else {
        // V pairs: njp = g-4 -> d cols (g-4)*16+lr and +8
        int gg = g - 4;
        int nd0 = gg*16 + lr, nd1 = nd0 + 8;
        #pragma unroll
        for (int ks = 0; ks < 4; ks++) {
            int k0 = ks*16 + 2*lc;
            uint4 u;
            u.x = h2u(__half2float(Vs[k0][nd0]),   __half2float(Vs[k0+1][nd0]));
            u.y = h2u(__half2float(Vs[k0+8][nd0]), __half2float(Vs[k0+9][nd0]));
            u.z = h2u(__half2float(Vs[k0][nd1]),   __half2float(Vs[k0+1][nd1]));
            u.w = h2u(__half2float(Vs[k0+8][nd1]), __half2float(Vs[k0+9][nd1]));
            g_vp[tb + (ks*4 + gg)*32 + lane] = u;
        }
    }
}

// ---------------- FP16 flash attention ----------------------------------------
__global__ __launch_bounds__(256, 2)
void attn_f16() {
    __shared__ uint32_t Ps[8][16][36];   // per-warp P (half2 units), padded

    int qb = blockIdx.x, h = blockIdx.y, b = blockIdx.z;
    int tid = threadIdx.x;
    int warp = tid >> 5, lane = tid & 31;
    int lr = lane >> 2, lc = lane & 3;

    // ---- persistent Q fragments (q pre-scaled in qkv epilogue) ----
    uint32_t qf[4][4];
    {
        const __half* q0 = g_qkv + (size_t)(b*NN + qb*128 + warp*16 + lr)*(3*CC) + h*DD;
        const __half* q1 = q0 + (size_t)8*(3*CC);
        #pragma unroll
        for (int ks = 0; ks < 4; ks++) {
            int k0 = ks*16 + 2*lc;
            qf[ks][0] = *(const uint32_t*)&q0[k0];
            qf[ks][1] = *(const uint32_t*)&q1[k0];
            qf[ks][2] = *(const uint32_t*)&q0[k0 + 8];
            qf[ks][3] = *(const uint32_t*)&q1[k0 + 8];
        }
    }

    float4 o[8];
    #pragma unroll
    for (int dn = 0; dn < 8; dn++) o[dn] = make_float4(0.f,0.f,0.f,0.f);
    float m0 = -INFINITY, m1 = -INFINITY, l0 = 0.f, l1 = 0.f;

    int nk = g_kvcnt[b];
    int ntiles = (nk + 63) >> 6;
    const uint4* kpb = g_kp + ((size_t)(b*HH + h))*NT64*512;
    const uint4* vpb = g_vp + ((size_t)(b*HH + h))*NT64*512;

    for (int t = 0; t < ntiles; t++) {
        const uint4* kp = kpb + (size_t)t*512;
        const uint4* vp = vpb + (size_t)t*512;

        // ---- S = Q K^T : one LDG.128 -> two mmas ----
        float4 s[8];
        #pragma unroll
        for (int nj = 0; nj < 8; nj++) s[nj] = make_float4(0.f,0.f,0.f,0.f);
        #pragma unroll
        for (int ks = 0; ks < 4; ks++) {
            #pragma unroll
            for (int p = 0; p < 4; p++) {
                uint4 kk = __ldg(&kp[(ks*4 + p)*32 + lane]);
                mma_f16(s[2*p],   qf[ks], kk.x, kk.y);
                mma_f16(s[2*p+1], qf[ks], kk.z, kk.w);
            }
        }

        // mask only the ragged final tile (uniform branch)
        int valid = nk - t*64;
        if (valid < 64) {
            #pragma unroll
            for (int nj = 0; nj < 8; nj++) {
                int c0 = nj*8 + 2*lc;
                if (c0     >= valid) { s[nj].x = -1e30f; s[nj].z = -1e30f; }
                if (c0 + 1 >= valid) { s[nj].y = -1e30f; s[nj].w = -1e30f; }
            }
        }

        // ---- online softmax ----
        float mx0 = -1e30f, mx1 = -1e30f;
        #pragma unroll
        for (int nj = 0; nj < 8; nj++) {
            mx0 = fmaxf(mx0, fmaxf(s[nj].x, s[nj].y));
            mx1 = fmaxf(mx1, fmaxf(s[nj].z, s[nj].w));
        }
        mx0 = fmaxf(mx0, __shfl_xor_sync(0xffffffffu, mx0, 1));
        mx0 = fmaxf(mx0, __shfl_xor_sync(0xffffffffu, mx0, 2));
        mx1 = fmaxf(mx1, __shfl_xor_sync(0xffffffffu, mx1, 1));
        mx1 = fmaxf(mx1, __shfl_xor_sync(0xffffffffu, mx1, 2));
        float mn0 = fmaxf(m0, mx0), mn1 = fmaxf(m1, mx1);
        float cr0 = __expf(m0 - mn0), cr1 = __expf(m1 - mn1);
        m0 = mn0; m1 = mn1;
        float sum0 = 0.f, sum1 = 0.f;
        #pragma unroll
        for (int nj = 0; nj < 8; nj++) {
            s[nj].x = __expf(s[nj].x - mn0); sum0 += s[nj].x;
            s[nj].y = __expf(s[nj].y - mn0); sum0 += s[nj].y;
            s[nj].z = __expf(s[nj].z - mn1); sum1 += s[nj].z;
            s[nj].w = __expf(s[nj].w - mn1); sum1 += s[nj].w;
        }
        sum0 += __shfl_xor_sync(0xffffffffu, sum0, 1);
        sum0 += __shfl_xor_sync(0xffffffffu, sum0, 2);
        sum1 += __shfl_xor_sync(0xffffffffu, sum1, 1);
        sum1 += __shfl_xor_sync(0xffffffffu, sum1, 2);
        l0 = l0*cr0 + sum0;
        l1 = l1*cr1 + sum1;
        #pragma unroll
        for (int dn = 0; dn < 8; dn++) {
            o[dn].x *= cr0; o[dn].y *= cr0;
            o[dn].z *= cr1; o[dn].w *= cr1;
        }

        // ---- P -> warp-private smem (half2) ----
        #pragma unroll
        for (int nj = 0; nj < 8; nj++) {
            Ps[warp][lr][nj*4 + lc]     = h2u(s[nj].x, s[nj].y);
            Ps[warp][lr + 8][nj*4 + lc] = h2u(s[nj].z, s[nj].w);
        }
        __syncwarp();

        // ---- O += P @ V : one LDG.128 -> two mmas ----
        #pragma unroll
        for (int ks = 0; ks < 4; ks++) {
            uint32_t pf[4];
            pf[0] = Ps[warp][lr][ks*8 + lc];
            pf[1] = Ps[warp][lr + 8][ks*8 + lc];
            pf[2] = Ps[warp][lr][ks*8 + lc + 4];
            pf[3] = Ps[warp][lr + 8][ks*8 + lc + 4];
            #pragma unroll
            for (int p = 0; p < 4; p++) {
                uint4 vv = __ldg(&vp[(ks*4 + p)*32 + lane]);
                mma_f16(o[2*p],   pf, vv.x, vv.y);
                mma_f16(o[2*p+1], pf, vv.z, vv.w);
            }
        }
        __syncwarp();
    }

    // ---- epilogue: normalize, store fp16 ----
    float invl0 = 1.0f / l0, invl1 = 1.0f / l1;
    int r0 = qb*128 + warp*16 + lr;
    __half* orow0 = g_o + (size_t)(b*NN + r0)*CC + h*DD;
    __half* orow1 = orow0 + (size_t)8*CC;
    #pragma unroll
    for (int dn = 0; dn < 8; dn++) {
        int c = dn*8 + 2*lc;
        *(uint32_t*)&orow0[c] = h2u(o[dn].x*invl0, o[dn].y*invl0);
        *(uint32_t*)&orow1[c] = h2u(o[dn].z*invl1, o[dn].w*invl1);
    }
}

// ---------------------------------------------------------------------------
extern "C" void kernel_launch(void* const* d_in, const int* in_sizes, int n_in,
                              void* d_out, int out_size) {
    const float* x      = (const float*)d_in[0];
    const float* cond   = (const float*)d_in[1];
    const int*   mask   = (const int*)  d_in[2];
    const float* qkv_w  = (const float*)d_in[3];
    const float* qkv_b  = (const float*)d_in[4];
    const float* proj_w = (const float*)d_in[5];
    const float* proj_b = (const float*)d_in[6];
    const float* ada_w  = (const float*)d_in[7];
    const float* ada_b  = (const float*)d_in[8];
    const float* mlp_w1 = (const float*)d_in[9];
    const float* mlp_b1 = (const float*)d_in[10];
    const float* mlp_w2 = (const float*)d_in[11];
    const float* mlp_b2 = (const float*)d_in[12];
    float* out = (float*)d_out;

    float *p_ada, *p_x1;
    __half *p_h, *p_qkv, *p_o, *p_h3;
    uint4 *p_wp;
    cudaGetSymbolAddress((void**)&p_ada, g_ada);
    cudaGetSymbolAddress((void**)&p_h,   g_h);
    cudaGetSymbolAddress((void**)&p_qkv, g_qkv);
    cudaGetSymbolAddress((void**)&p_o,   g_o);
    cudaGetSymbolAddress((void**)&p_x1,  g_x1);
    cudaGetSymbolAddress((void**)&p_h3,  g_h3);
    cudaGetSymbolAddress((void**)&p_wp,  g_wp);

    // 0. weight packs (one launch for all four)
    wpack_f16<<<dim3(32, 48), 256>>>(qkv_w, proj_w, mlp_w1, mlp_w2);
    // 1. adaLN vector
    ada_kernel<<<BB*12, 256>>>(cond, ada_w, ada_b);
    // 2. compact unmasked keys (exact: -10000 underflows to 0 in softmax)
    compact_kernel<<<BB, 1024>>>(mask);
    // 3. LN + modulate (MSA): sh_msa @0, sc_msa @512
    ln_mod_kernel<<<MM, 128>>>(x, 0, CC, p_h);
    // 4. qkv GEMM [8192,1536] -> fp16, q pre-scaled
    gemm_f16<0><<<dim3(12, 64), 256>>>(p_h, p_wp + WP4_QKV, qkv_b, nullptr, nullptr, p_qkv, 3*CC);
    // 5. pack compacted K/V
    kv_pack_kernel<<<dim3(NT64, HH, BB), 256>>>();
    // 6. attention
    attn_f16<<<dim3(NN/128, HH, BB), 256>>>();
    // 7. proj GEMM + gated residual (g_msa @1024) -> fp32 x1
    gemm_f16<2><<<dim3(4, 64), 256>>>(p_o, p_wp + WP4_PROJ, proj_b, x, p_ada + 2*CC, p_x1, CC);
    // 8. LN + modulate (MLP): sh_mlp @1536, sc_mlp @2048
    ln_mod_kernel<<<MM, 128>>>(p_x1, 3*CC, 4*CC, p_h);
    // 9. mlp1 + exact GELU -> fp16
    gemm_f16<1><<<dim3(4, 64), 256>>>(p_h, p_wp + WP4_MLP1, mlp_b1, nullptr, nullptr, p_h3, CC);
    // 10. mlp2 + gated residual (g_mlp @2560) -> d_out (fp32)
    gemm_f16<2><<<dim3(4, 64), 256>>>(p_h3, p_wp + WP4_MLP2, mlp_b2, p_x1, p_ada + 5*CC, out, CC);
}

// round 13
// speedup vs baseline: 5.8732x; 1.0878x over previous
#include <cuda_runtime.h>
#include <cuda_bf16.h>
#include <cuda_fp16.h>
#include <math.h>
#include <stdint.h>

// Problem constants
#define BB 2
#define NN 4096
#define CC 512
#define HH 8
#define DD 64
#define MM (BB*NN)      // 8192
#define ADA6 (6*CC)     // 3072
#define NT64 (NN/64)    // 64 kv tiles max

// ---------------- scratch ----------------------------------------------------
__device__ float  g_ada[BB*ADA6];
__device__ __half g_h [MM*CC];          // LN+mod outputs (fp16)
__device__ __half g_qkv[MM*3*CC];       // qkv (fp16, q pre-scaled)
__device__ __half g_o [MM*CC];          // attention out (fp16)
__device__ float  g_x1[MM*CC];          // residual stream (fp32)
__device__ __half g_h3[MM*CC];          // gelu out (fp16)
__device__ int    g_kvidx[BB*NN];
__device__ int    g_kvcnt[BB];
// packed K/V fragment PAIRS: [b][h][tile][ks(4)][njp(4)][lane(32)] uint4
__device__ uint4  g_kp[BB*HH*NT64*4*4*32];
__device__ uint4  g_vp[BB*HH*NT64*4*4*32];
// packed weights (fp16 fragment pairs): [(k16*(N/16)+nfp)*32+lane] uint4
#define WP4_QKV  0
#define WP4_PROJ 98304
#define WP4_MLP1 131072
#define WP4_MLP2 163840
__device__ uint4  g_wp[196608];

// attention dynamic smem: KV double buffer (32KB) + Ps (18KB)
#define ATTN_SMEM (2*1024*16 + 8*16*36*4)   // 51200

// ---------------- helpers ----------------------------------------------------
__device__ __forceinline__ uint32_t h2u(float a, float b) {
    __half2 h = __floats2half2_rn(a, b);
    return *(uint32_t*)&h;
}
__device__ __forceinline__ void mma_f16(float4& d, const uint32_t a[4],
                                        uint32_t b0, uint32_t b1) {
    asm volatile(
        "mma.sync.aligned.m16n8k16.row.col.f32.f16.f16.f32 "
        "{%0,%1,%2,%3}, {%4,%5,%6,%7}, {%8,%9}, {%0,%1,%2,%3};\n"
        : "+f"(d.x), "+f"(d.y), "+f"(d.z), "+f"(d.w)
        : "r"(a[0]), "r"(a[1]), "r"(a[2]), "r"(a[3]), "r"(b0), "r"(b1));
}
__device__ __forceinline__ uint32_t s2u(const void* p) {
    uint32_t a;
    asm("{ .reg .u64 t; cvta.to.shared.u64 t, %1; cvt.u32.u64 %0, t; }" : "=r"(a) : "l"(p));
    return a;
}
__device__ __forceinline__ void cp_async16(uint32_t dst, const void* src) {
    asm volatile("cp.async.cg.shared.global [%0], [%1], 16;" :: "r"(dst), "l"(src));
}
__device__ __forceinline__ void cp_commit() { asm volatile("cp.async.commit_group;" ::: "memory"); }
template<int NG> __device__ __forceinline__ void cp_wait() {
    asm volatile("cp.async.wait_group %0;" :: "n"(NG) : "memory");
}

// ---------------- ada = silu(cond) @ ada_w + ada_b ---------------------------
__global__ void ada_kernel(const float* __restrict__ cond,
                           const float* __restrict__ ada_w,
                           const float* __restrict__ ada_b) {
    int b = blockIdx.x / 12;
    int j = (blockIdx.x % 12) * 256 + threadIdx.x;
    __shared__ float sc[CC];
    for (int t = threadIdx.x; t < CC; t += 256) {
        float x = cond[b*CC + t];
        sc[t] = x / (1.0f + expf(-x));
    }
    __syncthreads();
    float acc = ada_b[j];
    #pragma unroll 8
    for (int c = 0; c < CC; c++) acc += sc[c] * ada_w[c*ADA6 + j];
    g_ada[b*ADA6 + j] = acc;
}

// ---------------- mask compaction (shfl-scan, 2 barriers) ---------------------
__global__ void compact_kernel(const int* __restrict__ mask) {
    int b = blockIdx.x;
    int tid = threadIdx.x;          // 1024
    int warp = tid >> 5, lane = tid & 31;
    int base = b*NN;
    int loc[4]; int cnt = 0;
    #pragma unroll
    for (int q = 0; q < 4; q++) {
        int n = tid*4 + q;
        if (mask[base + n] == 1) loc[cnt++] = n;
    }
    // warp inclusive scan
    int inc = cnt;
    #pragma unroll
    for (int off = 1; off < 32; off <<= 1) {
        int v = __shfl_up_sync(0xffffffffu, inc, off);
        if (lane >= off) inc += v;
    }
    __shared__ int wsum[32];
    if (lane == 31) wsum[warp] = inc;
    __syncthreads();
    if (warp == 0) {
        int v = wsum[lane];
        int s = v;
        #pragma unroll
        for (int off = 1; off < 32; off <<= 1) {
            int u = __shfl_up_sync(0xffffffffu, s, off);
            if (lane >= off) s += u;
        }
        wsum[lane] = s - v;              // exclusive prefix of warp sums
        if (lane == 31) g_kvcnt[b] = s;  // total
    }
    __syncthreads();
    int start = wsum[warp] + inc - cnt;
    for (int i = 0; i < cnt; i++) g_kvidx[base + start + i] = loc[i];
}

// ---------------- fused LayerNorm + adaLN modulate -> fp16 --------------------
__global__ void ln_mod_kernel(const float* __restrict__ X,
                              int shOff, int scOff,
                              __half* __restrict__ Hout) {
    int row = blockIdx.x;
    int b = row >> 12;
    int tid = threadIdx.x;
    const float* xr = X + (size_t)row * CC;
    float4 v = *(const float4*)(xr + tid*4);
    float s  = v.x + v.y + v.z + v.w;
    float sq = v.x*v.x + v.y*v.y + v.z*v.z + v.w*v.w;
    #pragma unroll
    for (int off = 16; off > 0; off >>= 1) {
        s  += __shfl_down_sync(0xffffffffu, s,  off);
        sq += __shfl_down_sync(0xffffffffu, sq, off);
    }
    __shared__ float ws[4], wq[4];
    if ((tid & 31) == 0) { ws[tid>>5] = s; wq[tid>>5] = sq; }
    __syncthreads();
    s  = ws[0] + ws[1] + ws[2] + ws[3];
    sq = wq[0] + wq[1] + wq[2] + wq[3];
    float mean = s * (1.0f/CC);
    float var  = sq * (1.0f/CC) - mean*mean;
    float rstd = rsqrtf(var + 1e-6f);
    int c = tid*4;
    const float* adab = g_ada + b*ADA6;
    float4 sc = *(const float4*)(adab + scOff + c);
    float4 sh = *(const float4*)(adab + shOff + c);
    float ox = (v.x - mean)*rstd*(1.0f + sc.x) + sh.x;
    float oy = (v.y - mean)*rstd*(1.0f + sc.y) + sh.y;
    float oz = (v.z - mean)*rstd*(1.0f + sc.z) + sh.z;
    float ow = (v.w - mean)*rstd*(1.0f + sc.w) + sh.w;
    uint2 u = make_uint2(h2u(ox, oy), h2u(oz, ow));
    *(uint2*)&Hout[(size_t)row*CC + c] = u;
}

// ---------------- weight pack (all 4 weights, one launch) ---------------------
__global__ void wpack_f16(const float* __restrict__ W0, const float* __restrict__ W1,
                          const float* __restrict__ W2, const float* __restrict__ W3) {
    __shared__ float ws[16][65];
    int k16 = blockIdx.x, nb = blockIdx.y;
    const float* W; int N; size_t off; int nbl;
    if (nb < 24)      { W = W0; N = 3*CC; off = WP4_QKV;  nbl = nb; }
    else if (nb < 32) { W = W1; N = CC;   off = WP4_PROJ; nbl = nb - 24; }
    else if (nb < 40) { W = W2; N = CC;   off = WP4_MLP1; nbl = nb - 32; }
    else              { W = W3; N = CC;   off = WP4_MLP2; nbl = nb - 40; }
    int tid = threadIdx.x;
    for (int i = tid; i < 16*64; i += 256) {
        int k = i >> 6, n = i & 63;
        ws[k][n] = W[(size_t)(k16*16 + k)*N + nbl*64 + n];
    }
    __syncthreads();
    if (tid < 128) {
        int nfp = tid >> 5, lane = tid & 31;
        int lr = lane >> 2, k0 = 2*(lane & 3);
        int n0 = nfp*16 + lr, n1 = n0 + 8;
        uint4 u;
        u.x = h2u(ws[k0][n0],   ws[k0+1][n0]);
        u.y = h2u(ws[k0+8][n0], ws[k0+9][n0]);
        u.z = h2u(ws[k0][n1],   ws[k0+1][n1]);
        u.w = h2u(ws[k0+8][n1], ws[k0+9][n1]);
        g_wp[off + ((size_t)k16*(N>>4) + nbl*4 + nfp)*32 + lane] = u;
    }
}

// ---------------- FP16 tensor-core GEMM (unchanged from R11) ------------------
template<int EPI>
__global__ __launch_bounds__(256, 2)
void gemm_f16(const __half* __restrict__ A, const uint4* __restrict__ Wp,
              const float* __restrict__ bias,
              const float* __restrict__ resid,
              const float* __restrict__ gate,
              void* __restrict__ CoutV, int N) {
    __shared__ uint4 Asp[2][512];
    int tid  = threadIdx.x;
    int warp = tid >> 5, lane = tid & 31;
    int wg = warp >> 2, wn4 = warp & 3;
    int m0 = blockIdx.y*128, n0 = blockIdx.x*128;

    int s0 = tid, s1 = tid + 256;
    auto loadA = [&](int kt, uint4& o0, uint4& o1) {
        #pragma unroll
        for (int j = 0; j < 2; j++) {
            int s = j ? s1 : s0;
            int rg = s >> 5, ln = s & 31;
            int mg = rg >> 1, ksl = rg & 1;
            int llr = ln >> 2, llc = ln & 3;
            int r0 = m0 + mg*16 + llr, r1 = r0 + 8;
            int ck = kt*32 + ksl*16 + 2*llc;
            uint4 v;
            v.x = *(const uint32_t*)&A[(size_t)r0*CC + ck];
            v.y = *(const uint32_t*)&A[(size_t)r1*CC + ck];
            v.z = *(const uint32_t*)&A[(size_t)r0*CC + ck + 8];
            v.w = *(const uint32_t*)&A[(size_t)r1*CC + ck + 8];
            if (j) o1 = v; else o0 = v;
        }
    };

    const uint4* wp0 = Wp + ((size_t)(n0 >> 4) + wn4*2)*32 + lane;
    size_t wstride = (size_t)(N >> 4) * 32;

    float4 acc[4][4];
    #pragma unroll
    for (int i = 0; i < 4; i++)
        #pragma unroll
        for (int j = 0; j < 4; j++) acc[i][j] = make_float4(0.f,0.f,0.f,0.f);

    uint4 pa0, pa1;
    loadA(0, pa0, pa1);
    Asp[0][s0] = pa0; Asp[0][s1] = pa1;
    uint4 bf[2][2][2];
    #pragma unroll
    for (int ks = 0; ks < 2; ks++)
        #pragma unroll
        for (int p = 0; p < 2; p++)
            bf[0][ks][p] = __ldg(wp0 + (size_t)ks*wstride + (size_t)p*32);
    __syncthreads();

    for (int kt = 0; kt < 16; kt++) {
        int cur = kt & 1;
        if (kt < 15) {
            loadA(kt + 1, pa0, pa1);
            #pragma unroll
            for (int ks = 0; ks < 2; ks++)
                #pragma unroll
                for (int p = 0; p < 2; p++)
                    bf[cur^1][ks][p] =
                        __ldg(wp0 + ((size_t)(kt+1)*2 + ks)*wstride + (size_t)p*32);
        }
        #pragma unroll
        for (int ks = 0; ks < 2; ks++) {
            #pragma unroll
            for (int mi = 0; mi < 4; mi++) {
                uint4 af4 = Asp[cur][(((wg*4 + mi)*2 + ks) << 5) + lane];
                uint32_t afr[4] = { af4.x, af4.y, af4.z, af4.w };
                #pragma unroll
                for (int p = 0; p < 2; p++) {
                    mma_f16(acc[mi][2*p],   afr, bf[cur][ks][p].x, bf[cur][ks][p].y);
                    mma_f16(acc[mi][2*p+1], afr, bf[cur][ks][p].z, bf[cur][ks][p].w);
                }
            }
        }
        if (kt < 15) {
            Asp[cur^1][s0] = pa0;
            Asp[cur^1][s1] = pa1;
        }
        __syncthreads();
    }

    int wm = wg*64, wn = wn4*32;
    int lr = lane >> 2, lc = lane & 3;
    #pragma unroll
    for (int mi = 0; mi < 4; mi++) {
        int r0 = m0 + wm + mi*16 + lr;
        int r1 = r0 + 8;
        int b0i = r0 >> 12, b1i = r1 >> 12;
        #pragma unroll
        for (int nj = 0; nj < 4; nj++) {
            int c = n0 + wn + nj*8 + 2*lc;
            float4 d = acc[mi][nj];
            float bx = bias[c], by = bias[c+1];
            float vx = d.x + bx, vy = d.y + by;
            float wx = d.z + bx, wy = d.w + by;
            if (EPI == 0) {
                float qs = (c < CC) ? 0.125f : 1.0f;
                vx *= qs; vy *= qs; wx *= qs; wy *= qs;
                __half* Ch = (__half*)CoutV;
                *(uint32_t*)&Ch[(size_t)r0*N + c] = h2u(vx, vy);
                *(uint32_t*)&Ch[(size_t)r1*N + c] = h2u(wx, wy);
            } else if (EPI == 1) {
                vx = 0.5f*vx*(1.0f + erff(vx*0.70710678118654752f));
                vy = 0.5f*vy*(1.0f + erff(vy*0.70710678118654752f));
                wx = 0.5f*wx*(1.0f + erff(wx*0.70710678118654752f));
                wy = 0.5f*wy*(1.0f + erff(wy*0.70710678118654752f));
                __half* Ch = (__half*)CoutV;
                *(uint32_t*)&Ch[(size_t)r0*N + c] = h2u(vx, vy);
                *(uint32_t*)&Ch[(size_t)r1*N + c] = h2u(wx, wy);
            } else {
                float gx0 = gate[(size_t)b0i*ADA6 + c], gy0 = gate[(size_t)b0i*ADA6 + c + 1];
                float gx1 = gate[(size_t)b1i*ADA6 + c], gy1 = gate[(size_t)b1i*ADA6 + c + 1];
                float* Cf = (float*)CoutV;
                *(float2*)&Cf[(size_t)r0*N + c] =
                    make_float2(resid[(size_t)r0*CC + c]     + gx0*vx,
                                resid[(size_t)r0*CC + c + 1] + gy0*vy);
                *(float2*)&Cf[(size_t)r1*N + c] =
                    make_float2(resid[(size_t)r1*CC + c]     + gx1*wx,
                                resid[(size_t)r1*CC + c + 1] + gy1*wy);
            }
        }
    }
}

// ---------------- KV pack: gather fp16 + fragment-pair permute ----------------
__global__ __launch_bounds__(256)
void kv_pack_kernel() {
    __shared__ __half Ks[64][72];
    __shared__ __half Vs[64][72];
    int t = blockIdx.x, h = blockIdx.y, b = blockIdx.z;
    int nk = g_kvcnt[b];
    int ntiles = (nk + 63) >> 6;
    if (t >= ntiles) return;
    int tid = threadIdx.x;

    {
        int row = tid >> 2, q4 = tid & 3;
        int slot = t*64 + row;
        if (slot < nk) {
            int n = g_kvidx[b*NN + slot];
            const __half* base = g_qkv + (size_t)(b*NN + n)*(3*CC) + h*DD + q4*16;
            *(uint4*)&Ks[row][q4*16]     = *(const uint4*)(base + CC);
            *(uint4*)&Ks[row][q4*16 + 8] = *(const uint4*)(base + CC + 8);
            *(uint4*)&Vs[row][q4*16]     = *(const uint4*)(base + 2*CC);
            *(uint4*)&Vs[row][q4*16 + 8] = *(const uint4*)(base + 2*CC + 8);
        } else {
            uint4 z = make_uint4(0,0,0,0);
            *(uint4*)&Ks[row][q4*16] = z; *(uint4*)&Ks[row][q4*16 + 8] = z;
            *(uint4*)&Vs[row][q4*16] = z; *(uint4*)&Vs[row][q4*16 + 8] = z;
        }
    }
    __syncthreads();

    int g = tid >> 5, lane = tid & 31;
    int lr = lane >> 2, lc = lane & 3;
    size_t tb = ((size_t)(b*HH + h)*NT64 + t) * 512;
    if (g < 4) {
        int n0 = g*16 + lr, n1 = n0 + 8;
        #pragma unroll
        for (int ks = 0; ks < 4; ks++) {
            int k0 = ks*16 + 2*lc;
            uint4 u;
            u.x = *(const uint32_t*)&Ks[n0][k0];
            u.y = *(const uint32_t*)&Ks[n0][k0 + 8];
            u.z = *(const uint32_t*)&Ks[n1][k0];
            u.w = *(const uint32_t*)&Ks[n1][k0 + 8];
            g_kp[tb + (ks*4 + g)*32 + lane] = u;
        }
    } else {
        int gg = g - 4;
        int nd0 = gg*16 + lr, nd1 = nd0 + 8;
        #pragma unroll
        for (int ks = 0; ks < 4; ks++) {
            int k0 = ks*16 + 2*lc;
            uint4 u;
            u.x = h2u(__half2float(Vs[k0][nd0]),   __half2float(Vs[k0+1][nd0]));
            u.y = h2u(__half2float(Vs[k0+8][nd0]), __half2float(Vs[k0+9][nd0]));
            u.z = h2u(__half2float(Vs[k0][nd1]),   __half2float(Vs[k0+1][nd1]));
            u.w = h2u(__half2float(Vs[k0+8][nd1]), __half2float(Vs[k0+9][nd1]));
            g_vp[tb + (ks*4 + gg)*32 + lane] = u;
        }
    }
}

// ---------------- FP16 flash attention (cp.async, dynamic smem) ---------------
__global__ __launch_bounds__(256, 2)
void attn_f16() {
    extern __shared__ __align__(16) char smraw[];
    uint4* KV = (uint4*)smraw;                          // [2][1024]
    uint32_t* Ps = (uint32_t*)(smraw + 32768);          // [8][16][36]
    #define PS(w, r, c) Ps[((w)*16 + (r))*36 + (c)]

    int qb = blockIdx.x, h = blockIdx.y, b = blockIdx.z;
    int tid = threadIdx.x;
    int warp = tid >> 5, lane = tid & 31;
    int lr = lane >> 2, lc = lane & 3;
    uint32_t kvsm = s2u(KV);

    // ---- persistent Q fragments (q pre-scaled in qkv epilogue) ----
    uint32_t qf[4][4];
    {
        const __half* q0 = g_qkv + (size_t)(b*NN + qb*128 + warp*16 + lr)*(3*CC) + h*DD;
        const __half* q1 = q0 + (size_t)8*(3*CC);
        #pragma unroll
        for (int ks = 0; ks < 4; ks++) {
            int k0 = ks*16 + 2*lc;
            qf[ks][0] = *(const uint32_t*)&q0[k0];
            qf[ks][1] = *(const uint32_t*)&q1[k0];
            qf[ks][2] = *(const uint32_t*)&q0[k0 + 8];
            qf[ks][3] = *(const uint32_t*)&q1[k0 + 8];
        }
    }

    float4 o[8];
    #pragma unroll
    for (int dn = 0; dn < 8; dn++) o[dn] = make_float4(0.f,0.f,0.f,0.f);
    float m0 = -INFINITY, m1 = -INFINITY, l0 = 0.f, l1 = 0.f;

    int nk = g_kvcnt[b];
    int ntiles = (nk + 63) >> 6;
    const uint4* kpb = g_kp + ((size_t)(b*HH + h))*NT64*512;
    const uint4* vpb = g_vp + ((size_t)(b*HH + h))*NT64*512;

    auto issue = [&](int t, int buf) {
        const uint4* kp = kpb + (size_t)t*512;
        const uint4* vp = vpb + (size_t)t*512;
        uint32_t dst = kvsm + (uint32_t)buf*16384;
        #pragma unroll
        for (int j = 0; j < 2; j++) {
            int idx = tid + j*256;
            cp_async16(dst + idx*16,          kp + idx);
            cp_async16(dst + (idx + 512)*16,  vp + idx);
        }
        cp_commit();
    };

    issue(0, 0);
    if (ntiles > 1) issue(1, 1);

    for (int t = 0; t < ntiles; t++) {
        if (t + 1 < ntiles) cp_wait<1>(); else cp_wait<0>();
        __syncthreads();
        int buf = t & 1;
        const uint4* kb = &KV[buf*1024];
        const uint4* vb = &KV[buf*1024 + 512];

        // ---- S = Q K^T : LDS.128 -> two mmas ----
        float4 s[8];
        #pragma unroll
        for (int nj = 0; nj < 8; nj++) s[nj] = make_float4(0.f,0.f,0.f,0.f);
        #pragma unroll
        for (int ks = 0; ks < 4; ks++) {
            #pragma unroll
            for (int p = 0; p < 4; p++) {
                uint4 kk = kb[(ks*4 + p)*32 + lane];
                mma_f16(s[2*p],   qf[ks], kk.x, kk.y);
                mma_f16(s[2*p+1], qf[ks], kk.z, kk.w);
            }
        }

        // mask only the ragged final tile
        int valid = nk - t*64;
        if (valid < 64) {
            #pragma unroll
            for (int nj = 0; nj < 8; nj++) {
                int c0 = nj*8 + 2*lc;
                if (c0     >= valid) { s[nj].x = -1e30f; s[nj].z = -1e30f; }
                if (c0 + 1 >= valid) { s[nj].y = -1e30f; s[nj].w = -1e30f; }
            }
        }

        // ---- online softmax ----
        float mx0 = -1e30f, mx1 = -1e30f;
        #pragma unroll
        for (int nj = 0; nj < 8; nj++) {
            mx0 = fmaxf(mx0, fmaxf(s[nj].x, s[nj].y));
            mx1 = fmaxf(mx1, fmaxf(s[nj].z, s[nj].w));
        }
        mx0 = fmaxf(mx0, __shfl_xor_sync(0xffffffffu, mx0, 1));
        mx0 = fmaxf(mx0, __shfl_xor_sync(0xffffffffu, mx0, 2));
        mx1 = fmaxf(mx1, __shfl_xor_sync(0xffffffffu, mx1, 1));
        mx1 = fmaxf(mx1, __shfl_xor_sync(0xffffffffu, mx1, 2));
        float mn0 = fmaxf(m0, mx0), mn1 = fmaxf(m1, mx1);
        float cr0 = __expf(m0 - mn0), cr1 = __expf(m1 - mn1);
        m0 = mn0; m1 = mn1;
        float sum0 = 0.f, sum1 = 0.f;
        #pragma unroll
        for (int nj = 0; nj < 8; nj++) {
            s[nj].x = __expf(s[nj].x - mn0); sum0 += s[nj].x;
            s[nj].y = __expf(s[nj].y - mn0); sum0 += s[nj].y;
            s[nj].z = __expf(s[nj].z - mn1); sum1 += s[nj].z;
            s[nj].w = __expf(s[nj].w - mn1); sum1 += s[nj].w;
        }
        sum0 += __shfl_xor_sync(0xffffffffu, sum0, 1);
        sum0 += __shfl_xor_sync(0xffffffffu, sum0, 2);
        sum1 += __shfl_xor_sync(0xffffffffu, sum1, 1);
        sum1 += __shfl_xor_sync(0xffffffffu, sum1, 2);
        l0 = l0*cr0 + sum0;
        l1 = l1*cr1 + sum1;
        #pragma unroll
        for (int dn = 0; dn < 8; dn++) {
            o[dn].x *= cr0; o[dn].y *= cr0;
            o[dn].z *= cr1; o[dn].w *= cr1;
        }

        // ---- P -> warp-private smem (half2) ----
        #pragma unroll
        for (int nj = 0; nj < 8; nj++) {
            PS(warp, lr,     nj*4 + lc) = h2u(s[nj].x, s[nj].y);
            PS(warp, lr + 8, nj*4 + lc) = h2u(s[nj].z, s[nj].w);
        }
        __syncwarp();

        // ---- O += P @ V : LDS.128 -> two mmas ----
        #pragma unroll
        for (int ks = 0; ks < 4; ks++) {
            uint32_t pf[4];
            pf[0] = PS(warp, lr,     ks*8 + lc);
            pf[1] = PS(warp, lr + 8, ks*8 + lc);
            pf[2] = PS(warp, lr,     ks*8 + lc + 4);
            pf[3] = PS(warp, lr + 8, ks*8 + lc + 4);
            #pragma unroll
            for (int p = 0; p < 4; p++) {
                uint4 vv = vb[(ks*4 + p)*32 + lane];
                mma_f16(o[2*p],   pf, vv.x, vv.y);
                mma_f16(o[2*p+1], pf, vv.z, vv.w);
            }
        }

        __syncthreads();                       // all reads of buf done
        if (t + 2 < ntiles) issue(t + 2, buf); // refill this buffer
    }

    // ---- epilogue: normalize, store fp16 ----
    float invl0 = 1.0f / l0, invl1 = 1.0f / l1;
    int r0 = qb*128 + warp*16 + lr;
    __half* orow0 = g_o + (size_t)(b*NN + r0)*CC + h*DD;
    __half* orow1 = orow0 + (size_t)8*CC;
    #pragma unroll
    for (int dn = 0; dn < 8; dn++) {
        int c = dn*8 + 2*lc;
        *(uint32_t*)&orow0[c] = h2u(o[dn].x*invl0, o[dn].y*invl0);
        *(uint32_t*)&orow1[c] = h2u(o[dn].z*invl1, o[dn].w*invl1);
    }
    #undef PS
}

// ---------------------------------------------------------------------------
extern "C" void kernel_launch(void* const* d_in, const int* in_sizes, int n_in,
                              void* d_out, int out_size) {
    const float* x      = (const float*)d_in[0];
    const float* cond   = (const float*)d_in[1];
    const int*   mask   = (const int*)  d_in[2];
    const float* qkv_w  = (const float*)d_in[3];
    const float* qkv_b  = (const float*)d_in[4];
    const float* proj_w = (const float*)d_in[5];
    const float* proj_b = (const float*)d_in[6];
    const float* ada_w  = (const float*)d_in[7];
    const float* ada_b  = (const float*)d_in[8];
    const float* mlp_w1 = (const float*)d_in[9];
    const float* mlp_b1 = (const float*)d_in[10];
    const float* mlp_w2 = (const float*)d_in[11];
    const float* mlp_b2 = (const float*)d_in[12];
    float* out = (float*)d_out;

    float *p_ada, *p_x1;
    __half *p_h, *p_qkv, *p_o, *p_h3;
    uint4 *p_wp;
    cudaGetSymbolAddress((void**)&p_ada, g_ada);
    cudaGetSymbolAddress((void**)&p_h,   g_h);
    cudaGetSymbolAddress((void**)&p_qkv, g_qkv);
    cudaGetSymbolAddress((void**)&p_o,   g_o);
    cudaGetSymbolAddress((void**)&p_x1,  g_x1);
    cudaGetSymbolAddress((void**)&p_h3,  g_h3);
    cudaGetSymbolAddress((void**)&p_wp,  g_wp);

    cudaFuncSetAttribute(attn_f16, cudaFuncAttributeMaxDynamicSharedMemorySize, ATTN_SMEM);

    // 0. weight packs (one launch for all four)
    wpack_f16<<<dim3(32, 48), 256>>>(qkv_w, proj_w, mlp_w1, mlp_w2);
    // 1. adaLN vector
    ada_kernel<<<BB*12, 256>>>(cond, ada_w, ada_b);
    // 2. compact unmasked keys (exact: -10000 underflows to 0 in softmax)
    compact_kernel<<<BB, 1024>>>(mask);
    // 3. LN + modulate (MSA): sh_msa @0, sc_msa @512
    ln_mod_kernel<<<MM, 128>>>(x, 0, CC, p_h);
    // 4. qkv GEMM [8192,1536] -> fp16, q pre-scaled
    gemm_f16<0><<<dim3(12, 64), 256>>>(p_h, p_wp + WP4_QKV, qkv_b, nullptr, nullptr, p_qkv, 3*CC);
    // 5. pack compacted K/V
    kv_pack_kernel<<<dim3(NT64, HH, BB), 256>>>();
    // 6. attention (cp.async pipelined, dynamic smem)
    attn_f16<<<dim3(NN/128, HH, BB), 256, ATTN_SMEM>>>();
    // 7. proj GEMM + gated residual (g_msa @1024) -> fp32 x1
    gemm_f16<2><<<dim3(4, 64), 256>>>(p_o, p_wp + WP4_PROJ, proj_b, x, p_ada + 2*CC, p_x1, CC);
    // 8. LN + modulate (MLP): sh_mlp @1536, sc_mlp @2048
    ln_mod_kernel<<<MM, 128>>>(p_x1, 3*CC, 4*CC, p_h);
    // 9. mlp1 + exact GELU -> fp16
    gemm_f16<1><<<dim3(4, 64), 256>>>(p_h, p_wp + WP4_MLP1, mlp_b1, nullptr, nullptr, p_h3, CC);
    // 10. mlp2 + gated residual (g_mlp @2560) -> d_out (fp32)
    gemm_f16<2><<<dim3(4, 64), 256>>>(p_h3, p_wp + WP4_MLP2, mlp_b2, p_x1, p_ada + 5*CC, out, CC);
}

// round 15
// speedup vs baseline: 6.0858x; 1.0362x over previous
#include <cuda_runtime.h>
#include <cuda_bf16.h>
#include <cuda_fp16.h>
#include <math.h>
#include <stdint.h>

// Problem constants
#define BB 2
#define NN 4096
#define CC 512
#define HH 8
#define DD 64
#define MM (BB*NN)      // 8192
#define ADA6 (6*CC)     // 3072
#define NT64 (NN/64)    // 64 kv tiles max

// ---------------- scratch ----------------------------------------------------
__device__ float  g_ada[BB*ADA6];
__device__ __half g_h [MM*CC];          // LN+mod outputs (fp16)
__device__ __half g_qkv[MM*3*CC];       // qkv (fp16, q pre-scaled by 0.125*log2e)
__device__ __half g_o [MM*CC];          // attention out (fp16)
__device__ float  g_x1[MM*CC];          // residual stream (fp32)
__device__ __half g_h3[MM*CC];          // gelu out (fp16)
__device__ int    g_kvidx[BB*NN];
__device__ int    g_kvcnt[BB];
// packed K/V fragment PAIRS: [b][h][tile][ks(4)][njp(4)][lane(32)] uint4
__device__ uint4  g_kp[BB*HH*NT64*4*4*32];
__device__ uint4  g_vp[BB*HH*NT64*4*4*32];
// packed weights (fp16 fragment pairs): [(k16*(N/16)+nfp)*32+lane] uint4
#define WP4_QKV  0
#define WP4_PROJ 98304
#define WP4_MLP1 131072
#define WP4_MLP2 163840
__device__ uint4  g_wp[196608];

// attention dynamic smem: KV double buffer only (P stays in registers now)
#define ATTN_SMEM (2*1024*16)   // 32768

// ---------------- helpers ----------------------------------------------------
__device__ __forceinline__ uint32_t h2u(float a, float b) {
    __half2 h = __floats2half2_rn(a, b);
    return *(uint32_t*)&h;
}
__device__ __forceinline__ void mma_f16(float4& d, const uint32_t a[4],
                                        uint32_t b0, uint32_t b1) {
    asm volatile(
        "mma.sync.aligned.m16n8k16.row.col.f32.f16.f16.f32 "
        "{%0,%1,%2,%3}, {%4,%5,%6,%7}, {%8,%9}, {%0,%1,%2,%3};\n"
        : "+f"(d.x), "+f"(d.y), "+f"(d.z), "+f"(d.w)
        : "r"(a[0]), "r"(a[1]), "r"(a[2]), "r"(a[3]), "r"(b0), "r"(b1));
}
__device__ __forceinline__ uint32_t s2u(const void* p) {
    uint32_t a;
    asm("{ .reg .u64 t; cvta.to.shared.u64 t, %1; cvt.u32.u64 %0, t; }" : "=r"(a) : "l"(p));
    return a;
}
__device__ __forceinline__ void cp_async16(uint32_t dst, const void* src) {
    asm volatile("cp.async.cg.shared.global [%0], [%1], 16;" :: "r"(dst), "l"(src));
}
__device__ __forceinline__ void cp_commit() { asm volatile("cp.async.commit_group;" ::: "memory"); }
template<int NG> __device__ __forceinline__ void cp_wait() {
    asm volatile("cp.async.wait_group %0;" :: "n"(NG) : "memory");
}

// ---------------- ada = silu(cond) @ ada_w + ada_b ---------------------------
__global__ void ada_kernel(const float* __restrict__ cond,
                           const float* __restrict__ ada_w,
                           const float* __restrict__ ada_b) {
    int b = blockIdx.x / 12;
    int j = (blockIdx.x % 12) * 256 + threadIdx.x;
    __shared__ float sc[CC];
    for (int t = threadIdx.x; t < CC; t += 256) {
        float x = cond[b*CC + t];
        sc[t] = x / (1.0f + expf(-x));
    }
    __syncthreads();
    float acc = ada_b[j];
    #pragma unroll 8
    for (int c = 0; c < CC; c++) acc += sc[c] * ada_w[c*ADA6 + j];
    g_ada[b*ADA6 + j] = acc;
}

// ---------------- mask compaction (shfl-scan, 2 barriers) ---------------------
__global__ void compact_kernel(const int* __restrict__ mask) {
    int b = blockIdx.x;
    int tid = threadIdx.x;          // 1024
    int warp = tid >> 5, lane = tid & 31;
    int base = b*NN;
    int loc[4]; int cnt = 0;
    #pragma unroll
    for (int q = 0; q < 4; q++) {
        int n = tid*4 + q;
        if (mask[base + n] == 1) loc[cnt++] = n;
    }
    int inc = cnt;
    #pragma unroll
    for (int off = 1; off < 32; off <<= 1) {
        int v = __shfl_up_sync(0xffffffffu, inc, off);
        if (lane >= off) inc += v;
    }
    __shared__ int wsum[32];
    if (lane == 31) wsum[warp] = inc;
    __syncthreads();
    if (warp == 0) {
        int v = wsum[lane];
        int s = v;
        #pragma unroll
        for (int off = 1; off < 32; off <<= 1) {
            int u = __shfl_up_sync(0xffffffffu, s, off);
            if (lane >= off) s += u;
        }
        wsum[lane] = s - v;
        if (lane == 31) g_kvcnt[b] = s;
    }
    __syncthreads();
    int start = wsum[warp] + inc - cnt;
    for (int i = 0; i < cnt; i++) g_kvidx[base + start + i] = loc[i];
}

// ---------------- fused LayerNorm + adaLN modulate -> fp16 --------------------
__global__ void ln_mod_kernel(const float* __restrict__ X,
                              int shOff, int scOff,
                              __half* __restrict__ Hout) {
    int row = blockIdx.x;
    int b = row >> 12;
    int tid = threadIdx.x;
    const float* xr = X + (size_t)row * CC;
    float4 v = *(const float4*)(xr + tid*4);
    float s  = v.x + v.y + v.z + v.w;
    float sq = v.x*v.x + v.y*v.y + v.z*v.z + v.w*v.w;
    #pragma unroll
    for (int off = 16; off > 0; off >>= 1) {
        s  += __shfl_down_sync(0xffffffffu, s,  off);
        sq += __shfl_down_sync(0xffffffffu, sq, off);
    }
    __shared__ float ws[4], wq[4];
    if ((tid & 31) == 0) { ws[tid>>5] = s; wq[tid>>5] = sq; }
    __syncthreads();
    s  = ws[0] + ws[1] + ws[2] + ws[3];
    sq = wq[0] + wq[1] + wq[2] + wq[3];
    float mean = s * (1.0f/CC);
    float var  = sq * (1.0f/CC) - mean*mean;
    float rstd = rsqrtf(var + 1e-6f);
    int c = tid*4;
    const float* adab = g_ada + b*ADA6;
    float4 sc = *(const float4*)(adab + scOff + c);
    float4 sh = *(const float4*)(adab + shOff + c);
    float ox = (v.x - mean)*rstd*(1.0f + sc.x) + sh.x;
    float oy = (v.y - mean)*rstd*(1.0f + sc.y) + sh.y;
    float oz = (v.z - mean)*rstd*(1.0f + sc.z) + sh.z;
    float ow = (v.w - mean)*rstd*(1.0f + sc.w) + sh.w;
    uint2 u = make_uint2(h2u(ox, oy), h2u(oz, ow));
    *(uint2*)&Hout[(size_t)row*CC + c] = u;
}

// ---------------- weight pack (all 4 weights, one launch) ---------------------
__global__ void wpack_f16(const float* __restrict__ W0, const float* __restrict__ W1,
                          const float* __restrict__ W2, const float* __restrict__ W3) {
    __shared__ float ws[16][65];
    int k16 = blockIdx.x, nb = blockIdx.y;
    const float* W; int N; size_t off; int nbl;
    if (nb < 24)      { W = W0; N = 3*CC; off = WP4_QKV;  nbl = nb; }
    else if (nb < 32) { W = W1; N = CC;   off = WP4_PROJ; nbl = nb - 24; }
    else if (nb < 40) { W = W2; N = CC;   off = WP4_MLP1; nbl = nb - 32; }
    else              { W = W3; N = CC;   off = WP4_MLP2; nbl = nb - 40; }
    int tid = threadIdx.x;
    for (int i = tid; i < 16*64; i += 256) {
        int k = i >> 6, n = i & 63;
        ws[k][n] = W[(size_t)(k16*16 + k)*N + nbl*64 + n];
    }
    __syncthreads();
    if (tid < 128) {
        int nfp = tid >> 5, lane = tid & 31;
        int lr = lane >> 2, k0 = 2*(lane & 3);
        int n0 = nfp*16 + lr, n1 = n0 + 8;
        uint4 u;
        u.x = h2u(ws[k0][n0],   ws[k0+1][n0]);
        u.y = h2u(ws[k0+8][n0], ws[k0+9][n0]);
        u.z = h2u(ws[k0][n1],   ws[k0+1][n1]);
        u.w = h2u(ws[k0+8][n1], ws[k0+9][n1]);
        g_wp[off + ((size_t)k16*(N>>4) + nbl*4 + nfp)*32 + lane] = u;
    }
}

// ---------------- FP16 tensor-core GEMM (unchanged from R13) ------------------
template<int EPI>
__global__ __launch_bounds__(256, 2)
void gemm_f16(const __half* __restrict__ A, const uint4* __restrict__ Wp,
              const float* __restrict__ bias,
              const float* __restrict__ resid,
              const float* __restrict__ gate,
              void* __restrict__ CoutV, int N) {
    __shared__ uint4 Asp[2][512];
    int tid  = threadIdx.x;
    int warp = tid >> 5, lane = tid & 31;
    int wg = warp >> 2, wn4 = warp & 3;
    int m0 = blockIdx.y*128, n0 = blockIdx.x*128;

    int s0 = tid, s1 = tid + 256;
    auto loadA = [&](int kt, uint4& o0, uint4& o1) {
        #pragma unroll
        for (int j = 0; j < 2; j++) {
            int s = j ? s1 : s0;
            int rg = s >> 5, ln = s & 31;
            int mg = rg >> 1, ksl = rg & 1;
            int llr = ln >> 2, llc = ln & 3;
            int r0 = m0 + mg*16 + llr, r1 = r0 + 8;
            int ck = kt*32 + ksl*16 + 2*llc;
            uint4 v;
            v.x = *(const uint32_t*)&A[(size_t)r0*CC + ck];
            v.y = *(const uint32_t*)&A[(size_t)r1*CC + ck];
            v.z = *(const uint32_t*)&A[(size_t)r0*CC + ck + 8];
            v.w = *(const uint32_t*)&A[(size_t)r1*CC + ck + 8];
            if (j) o1 = v; else o0 = v;
        }
    };

    const uint4* wp0 = Wp + ((size_t)(n0 >> 4) + wn4*2)*32 + lane;
    size_t wstride = (size_t)(N >> 4) * 32;

    float4 acc[4][4];
    #pragma unroll
    for (int i = 0; i < 4; i++)
        #pragma unroll
        for (int j = 0; j < 4; j++) acc[i][j] = make_float4(0.f,0.f,0.f,0.f);

    uint4 pa0, pa1;
    loadA(0, pa0, pa1);
    Asp[0][s0] = pa0; Asp[0][s1] = pa1;
    uint4 bf[2][2][2];
    #pragma unroll
    for (int ks = 0; ks < 2; ks++)
        #pragma unroll
        for (int p = 0; p < 2; p++)
            bf[0][ks][p] = __ldg(wp0 + (size_t)ks*wstride + (size_t)p*32);
    __syncthreads();

    for (int kt = 0; kt < 16; kt++) {
        int cur = kt & 1;
        if (kt < 15) {
            loadA(kt + 1, pa0, pa1);
            #pragma unroll
            for (int ks = 0; ks < 2; ks++)
                #pragma unroll
                for (int p = 0; p < 2; p++)
                    bf[cur^1][ks][p] =
                        __ldg(wp0 + ((size_t)(kt+1)*2 + ks)*wstride + (size_t)p*32);
        }
        #pragma unroll
        for (int ks = 0; ks < 2; ks++) {
            #pragma unroll
            for (int mi = 0; mi < 4; mi++) {
                uint4 af4 = Asp[cur][(((wg*4 + mi)*2 + ks) << 5) + lane];
                uint32_t afr[4] = { af4.x, af4.y, af4.z, af4.w };
                #pragma unroll
                for (int p = 0; p < 2; p++) {
                    mma_f16(acc[mi][2*p],   afr, bf[cur][ks][p].x, bf[cur][ks][p].y);
                    mma_f16(acc[mi][2*p+1], afr, bf[cur][ks][p].z, bf[cur][ks][p].w);
                }
            }
        }
        if (kt < 15) {
            Asp[cur^1][s0] = pa0;
            Asp[cur^1][s1] = pa1;
        }
        __syncthreads();
    }

    int wm = wg*64, wn = wn4*32;
    int lr = lane >> 2, lc = lane & 3;
    #pragma unroll
    for (int mi = 0; mi < 4; mi++) {
        int r0 = m0 + wm + mi*16 + lr;
        int r1 = r0 + 8;
        int b0i = r0 >> 12, b1i = r1 >> 12;
        #pragma unroll
        for (int nj = 0; nj < 4; nj++) {
            int c = n0 + wn + nj*8 + 2*lc;
            float4 d = acc[mi][nj];
            float bx = bias[c], by = bias[c+1];
            float vx = d.x + bx, vy = d.y + by;
            float wx = d.z + bx, wy = d.w + by;
            if (EPI == 0) {
                // fold D^-0.5 * log2(e) into q (softmax runs in exp2 domain)
                float qs = (c < CC) ? 0.125f * 1.4426950408889634f : 1.0f;
                vx *= qs; vy *= qs; wx *= qs; wy *= qs;
                __half* Ch = (__half*)CoutV;
                *(uint32_t*)&Ch[(size_t)r0*N + c] = h2u(vx, vy);
                *(uint32_t*)&Ch[(size_t)r1*N + c] = h2u(wx, wy);
            } else if (EPI == 1) {
                vx = 0.5f*vx*(1.0f + erff(vx*0.70710678118654752f));
                vy = 0.5f*vy*(1.0f + erff(vy*0.70710678118654752f));
                wx = 0.5f*wx*(1.0f + erff(wx*0.70710678118654752f));
                wy = 0.5f*wy*(1.0f + erff(wy*0.70710678118654752f));
                __half* Ch = (__half*)CoutV;
                *(uint32_t*)&Ch[(size_t)r0*N + c] = h2u(vx, vy);
                *(uint32_t*)&Ch[(size_t)r1*N + c] = h2u(wx, wy);
            } else {
                float gx0 = gate[(size_t)b0i*ADA6 + c], gy0 = gate[(size_t)b0i*ADA6 + c + 1];
                float gx1 = gate[(size_t)b1i*ADA6 + c], gy1 = gate[(size_t)b1i*ADA6 + c + 1];
                float* Cf = (float*)CoutV;
                *(float2*)&Cf[(size_t)r0*N + c] =
                    make_float2(resid[(size_t)r0*CC + c]     + gx0*vx,
                                resid[(size_t)r0*CC + c + 1] + gy0*vy);
                *(float2*)&Cf[(size_t)r1*N + c] =
                    make_float2(resid[(size_t)r1*CC + c]     + gx1*wx,
                                resid[(size_t)r1*CC + c + 1] + gy1*wy);
            }
        }
    }
}

// ---------------- KV pack: gather fp16 + fragment-pair permute ----------------
__global__ __launch_bounds__(256)
void kv_pack_kernel() {
    __shared__ __half Ks[64][72];
    __shared__ __half Vs[64][72];
    int t = blockIdx.x, h = blockIdx.y, b = blockIdx.z;
    int nk = g_kvcnt[b];
    int ntiles = (nk + 63) >> 6;
    if (t >= ntiles) return;
    int tid = threadIdx.x;

    {
        int row = tid >> 2, q4 = tid & 3;
        int slot = t*64 + row;
        if (slot < nk) {
            int n = g_kvidx[b*NN + slot];
            const __half* base = g_qkv + (size_t)(b*NN + n)*(3*CC) + h*DD + q4*16;
            *(uint4*)&Ks[row][q4*16]     = *(const uint4*)(base + CC);
            *(uint4*)&Ks[row][q4*16 + 8] = *(const uint4*)(base + CC + 8);
            *(uint4*)&Vs[row][q4*16]     = *(const uint4*)(base + 2*CC);
            *(uint4*)&Vs[row][q4*16 + 8] = *(const uint4*)(base + 2*CC + 8);
        } else {
            uint4 z = make_uint4(0,0,0,0);
            *(uint4*)&Ks[row][q4*16] = z; *(uint4*)&Ks[row][q4*16 + 8] = z;
            *(uint4*)&Vs[row][q4*16] = z; *(uint4*)&Vs[row][q4*16 + 8] = z;
        }
    }
    __syncthreads();

    int g = tid >> 5, lane = tid & 31;
    int lr = lane >> 2, lc = lane & 3;
    size_t tb = ((size_t)(b*HH + h)*NT64 + t) * 512;
    if (g < 4) {
        int n0 = g*16 + lr, n1 = n0 + 8;
        #pragma unroll
        for (int ks = 0; ks < 4; ks++) {
            int k0 = ks*16 + 2*lc;
            uint4 u;
            u.x = *(const uint32_t*)&Ks[n0][k0];
            u.y = *(const uint32_t*)&Ks[n0][k0 + 8];
            u.z = *(const uint32_t*)&Ks[n1][k0];
            u.w = *(const uint32_t*)&Ks[n1][k0 + 8];
            g_kp[tb + (ks*4 + g)*32 + lane] = u;
        }
    } else {
        int gg = g - 4;
        int nd0 = gg*16 + lr, nd1 = nd0 + 8;
        #pragma unroll
        for (int ks = 0; ks < 4; ks++) {
            int k0 = ks*16 + 2*lc;
            uint4 u;
            u.x = h2u(__half2float(Vs[k0][nd0]),   __half2float(Vs[k0+1][nd0]));
            u.y = h2u(__half2float(Vs[k0+8][nd0]), __half2float(Vs[k0+9][nd0]));
            u.z = h2u(__half2float(Vs[k0][nd1]),   __half2float(Vs[k0+1][nd1]));
            u.w = h2u(__half2float(Vs[k0+8][nd1]), __half2float(Vs[k0+9][nd1]));
            g_vp[tb + (ks*4 + gg)*32 + lane] = u;
        }
    }
}

// ---------------- FP16 flash attention (cp.async, P in registers) -------------
__global__ __launch_bounds__(256, 2)
void attn_f16() {
    extern __shared__ __align__(16) char smraw[];
    uint4* KV = (uint4*)smraw;                          // [2][1024]

    int qb = blockIdx.x, h = blockIdx.y, b = blockIdx.z;
    int tid = threadIdx.x;
    int warp = tid >> 5, lane = tid & 31;
    int lr = lane >> 2, lc = lane & 3;
    uint32_t kvsm = s2u(KV);

    // ---- persistent Q fragments (q pre-scaled by 0.125*log2e) ----
    uint32_t qf[4][4];
    {
        const __half* q0 = g_qkv + (size_t)(b*NN + qb*128 + warp*16 + lr)*(3*CC) + h*DD;
        const __half* q1 = q0 + (size_t)8*(3*CC);
        #pragma unroll
        for (int ks = 0; ks < 4; ks++) {
            int k0 = ks*16 + 2*lc;
            qf[ks][0] = *(const uint32_t*)&q0[k0];
            qf[ks][1] = *(const uint32_t*)&q1[k0];
            qf[ks][2] = *(const uint32_t*)&q0[k0 + 8];
            qf[ks][3] = *(const uint32_t*)&q1[k0 + 8];
        }
    }

    float4 o[8];
    #pragma unroll
    for (int dn = 0; dn < 8; dn++) o[dn] = make_float4(0.f,0.f,0.f,0.f);
    float m0 = -INFINITY, m1 = -INFINITY, l0 = 0.f, l1 = 0.f;

    int nk = g_kvcnt[b];
    int ntiles = (nk + 63) >> 6;
    const uint4* kpb = g_kp + ((size_t)(b*HH + h))*NT64*512;
    const uint4* vpb = g_vp + ((size_t)(b*HH + h))*NT64*512;

    auto issue = [&](int t, int buf) {
        const uint4* kp = kpb + (size_t)t*512;
        const uint4* vp = vpb + (size_t)t*512;
        uint32_t dst = kvsm + (uint32_t)buf*16384;
        #pragma unroll
        for (int j = 0; j < 2; j++) {
            int idx = tid + j*256;
            cp_async16(dst + idx*16,          kp + idx);
            cp_async16(dst + (idx + 512)*16,  vp + idx);
        }
        cp_commit();
    };

    issue(0, 0);
    if (ntiles > 1) issue(1, 1);

    for (int t = 0; t < ntiles; t++) {
        if (t + 1 < ntiles) cp_wait<1>(); else cp_wait<0>();
        __syncthreads();
        int buf = t & 1;
        const uint4* kb = &KV[buf*1024];
        const uint4* vb = &KV[buf*1024 + 512];

        // ---- S = Q K^T : LDS.128 -> two mmas ----
        float4 s[8];
        #pragma unroll
        for (int nj = 0; nj < 8; nj++) s[nj] = make_float4(0.f,0.f,0.f,0.f);
        #pragma unroll
        for (int ks = 0; ks < 4; ks++) {
            #pragma unroll
            for (int p = 0; p < 4; p++) {
                uint4 kk = kb[(ks*4 + p)*32 + lane];
                mma_f16(s[2*p],   qf[ks], kk.x, kk.y);
                mma_f16(s[2*p+1], qf[ks], kk.z, kk.w);
            }
        }

        // mask only the ragged final tile
        int valid = nk - t*64;
        if (valid < 64) {
            #pragma unroll
            for (int nj = 0; nj < 8; nj++) {
                int c0 = nj*8 + 2*lc;
                if (c0     >= valid) { s[nj].x = -1e30f; s[nj].z = -1e30f; }
                if (c0 + 1 >= valid) { s[nj].y = -1e30f; s[nj].w = -1e30f; }
            }
        }

        // ---- online softmax (exp2 domain; log2e folded into q) ----
        float mx0 = -1e30f, mx1 = -1e30f;
        #pragma unroll
        for (int nj = 0; nj < 8; nj++) {
            mx0 = fmaxf(mx0, fmaxf(s[nj].x, s[nj].y));
            mx1 = fmaxf(mx1, fmaxf(s[nj].z, s[nj].w));
        }
        mx0 = fmaxf(mx0, __shfl_xor_sync(0xffffffffu, mx0, 1));
        mx0 = fmaxf(mx0, __shfl_xor_sync(0xffffffffu, mx0, 2));
        mx1 = fmaxf(mx1, __shfl_xor_sync(0xffffffffu, mx1, 1));
        mx1 = fmaxf(mx1, __shfl_xor_sync(0xffffffffu, mx1, 2));
        float mn0 = fmaxf(m0, mx0), mn1 = fmaxf(m1, mx1);
        float cr0 = exp2f(m0 - mn0), cr1 = exp2f(m1 - mn1);
        m0 = mn0; m1 = mn1;
        float sum0 = 0.f, sum1 = 0.f;
        #pragma unroll
        for (int nj = 0; nj < 8; nj++) {
            s[nj].x = exp2f(s[nj].x - mn0); sum0 += s[nj].x;
            s[nj].y = exp2f(s[nj].y - mn0); sum0 += s[nj].y;
            s[nj].z = exp2f(s[nj].z - mn1); sum1 += s[nj].z;
            s[nj].w = exp2f(s[nj].w - mn1); sum1 += s[nj].w;
        }
        sum0 += __shfl_xor_sync(0xffffffffu, sum0, 1);
        sum0 += __shfl_xor_sync(0xffffffffu, sum0, 2);
        sum1 += __shfl_xor_sync(0xffffffffu, sum1, 1);
        sum1 += __shfl_xor_sync(0xffffffffu, sum1, 2);
        l0 = l0*cr0 + sum0;
        l1 = l1*cr1 + sum1;
        #pragma unroll
        for (int dn = 0; dn < 8; dn++) {
            o[dn].x *= cr0; o[dn].y *= cr0;
            o[dn].z *= cr1; o[dn].w *= cr1;
        }

        // ---- O += P @ V : P A-frags built directly from S C-frags ----
        // (C-layout of s[2ks],s[2ks+1] IS the A-layout for PV chunk ks)
        #pragma unroll
        for (int ks = 0; ks < 4; ks++) {
            uint32_t pf[4];
            pf[0] = h2u(s[2*ks].x,   s[2*ks].y);
            pf[1] = h2u(s[2*ks].z,   s[2*ks].w);
            pf[2] = h2u(s[2*ks+1].x, s[2*ks+1].y);
            pf[3] = h2u(s[2*ks+1].z, s[2*ks+1].w);
            #pragma unroll
            for (int p = 0; p < 4; p++) {
                uint4 vv = vb[(ks*4 + p)*32 + lane];
                mma_f16(o[2*p],   pf, vv.x, vv.y);
                mma_f16(o[2*p+1], pf, vv.z, vv.w);
            }
        }

        __syncthreads();                       // all reads of buf done
        if (t + 2 < ntiles) issue(t + 2, buf); // refill this buffer
    }

    // ---- epilogue: normalize, store fp16 ----
    float invl0 = 1.0f / l0, invl1 = 1.0f / l1;
    int r0 = qb*128 + warp*16 + lr;
    __half* orow0 = g_o + (size_t)(b*NN + r0)*CC + h*DD;
    __half* orow1 = orow0 + (size_t)8*CC;
    #pragma unroll
    for (int dn = 0; dn < 8; dn++) {
        int c = dn*8 + 2*lc;
        *(uint32_t*)&orow0[c] = h2u(o[dn].x*invl0, o[dn].y*invl0);
        *(uint32_t*)&orow1[c] = h2u(o[dn].z*invl1, o[dn].w*invl1);
    }
}

// ---------------------------------------------------------------------------
extern "C" void kernel_launch(void* const* d_in, const int* in_sizes, int n_in,
                              void* d_out, int out_size) {
    const float* x      = (const float*)d_in[0];
    const float* cond   = (const float*)d_in[1];
    const int*   mask   = (const int*)  d_in[2];
    const float* qkv_w  = (const float*)d_in[3];
    const float* qkv_b  = (const float*)d_in[4];
    const float* proj_w = (const float*)d_in[5];
    const float* proj_b = (const float*)d_in[6];
    const float* ada_w  = (const float*)d_in[7];
    const float* ada_b  = (const float*)d_in[8];
    const float* mlp_w1 = (const float*)d_in[9];
    const float* mlp_b1 = (const float*)d_in[10];
    const float* mlp_w2 = (const float*)d_in[11];
    const float* mlp_b2 = (const float*)d_in[12];
    float* out = (float*)d_out;

    float *p_ada, *p_x1;
    __half *p_h, *p_qkv, *p_o, *p_h3;
    uint4 *p_wp;
    cudaGetSymbolAddress((void**)&p_ada, g_ada);
    cudaGetSymbolAddress((void**)&p_h,   g_h);
    cudaGetSymbolAddress((void**)&p_qkv, g_qkv);
    cudaGetSymbolAddress((void**)&p_o,   g_o);
    cudaGetSymbolAddress((void**)&p_x1,  g_x1);
    cudaGetSymbolAddress((void**)&p_h3,  g_h3);
    cudaGetSymbolAddress((void**)&p_wp,  g_wp);

    cudaFuncSetAttribute(attn_f16, cudaFuncAttributeMaxDynamicSharedMemorySize, ATTN_SMEM);

    // 0. weight packs (one launch for all four)
    wpack_f16<<<dim3(32, 48), 256>>>(qkv_w, proj_w, mlp_w1, mlp_w2);
    // 1. adaLN vector
    ada_kernel<<<BB*12, 256>>>(cond, ada_w, ada_b);
    // 2. compact unmasked keys (exact: -10000 underflows to 0 in softmax)
    compact_kernel<<<BB, 1024>>>(mask);
    // 3. LN + modulate (MSA): sh_msa @0, sc_msa @512
    ln_mod_kernel<<<MM, 128>>>(x, 0, CC, p_h);
    // 4. qkv GEMM [8192,1536] -> fp16, q pre-scaled (incl. log2e)
    gemm_f16<0><<<dim3(12, 64), 256>>>(p_h, p_wp + WP4_QKV, qkv_b, nullptr, nullptr, p_qkv, 3*CC);
    // 5. pack compacted K/V
    kv_pack_kernel<<<dim3(NT64, HH, BB), 256>>>();
    // 6. attention (cp.async pipelined, register P)
    attn_f16<<<dim3(NN/128, HH, BB), 256, ATTN_SMEM>>>();
    // 7. proj GEMM + gated residual (g_msa @1024) -> fp32 x1
    gemm_f16<2><<<dim3(4, 64), 256>>>(p_o, p_wp + WP4_PROJ, proj_b, x, p_ada + 2*CC, p_x1, CC);
    // 8. LN + modulate (MLP): sh_mlp @1536, sc_mlp @2048
    ln_mod_kernel<<<MM, 128>>>(p_x1, 3*CC, 4*CC, p_h);
    // 9. mlp1 + exact GELU -> fp16
    gemm_f16<1><<<dim3(4, 64), 256>>>(p_h, p_wp + WP4_MLP1, mlp_b1, nullptr, nullptr, p_h3, CC);
    // 10. mlp2 + gated residual (g_mlp @2560) -> d_out (fp32)
    gemm_f16<2><<<dim3(4, 64), 256>>>(p_h3, p_wp + WP4_MLP2, mlp_b2, p_x1, p_ada + 5*CC, out, CC);
}